// round 10
// baseline (speedup 1.0000x reference)
#include <cuda_runtime.h>
#include <cuda_bf16.h>
#include <math.h>
#include <stdint.h>

#define B_   2
#define C_   128
#define N_   4096
#define K_   16
#define DIM_ 256
#define PH_  64
#define AH_  1024
#define M_   (N_ * K_)          // 65536 columns per batch in (n,k) space

// ---------------- scratch ---------------------------------------------------
__device__ float g_x    [(size_t)B_ * 2 * C_ * N_];
__device__ float g_t    [(size_t)B_ * C_ * N_];
__device__ float g_value[(size_t)B_ * C_ * N_];
__device__ float g_vf   [(size_t)B_ * DIM_ * N_];
__device__ float g_u    [(size_t)B_ * AH_ * N_];
__device__ float g_v    [(size_t)B_ * AH_ * N_];
__device__ float g_vt   [(size_t)B_ * N_ * AH_];       // v transposed: [B][N][AH]
__device__ int   g_idx  [(size_t)B_ * N_ * K_];
__device__ float g_t1   [(size_t)B_ * PH_ * M_];
__device__ float g_pe   [(size_t)B_ * DIM_ * M_];
__device__ float g_h    [(size_t)B_ * AH_ * M_];       // h: [B][AH][M]  (c-major)
__device__ float g_agg  [(size_t)B_ * DIM_ * N_];
__device__ float g_part [(size_t)B_ * 512 * AH_ * 2];
__device__ float g_partp[(size_t)PH_ * 512 * 2];
__device__ float g_Wuq  [AH_ * C_];
__device__ float g_Wvk  [AH_ * C_];
__device__ float g_bias1[AH_];
__device__ float g_scp  [PH_];
__device__ float g_shp  [PH_];
__device__ float g_sca  [AH_];
__device__ float g_sha  [AH_];
__device__ unsigned int g_w2img[16 * 65536 / 4];
__device__ unsigned int g_wmidimg[10 * 32768 / 4];
__device__ unsigned int g_wuqimg[8 * 65536 / 4];   // 8 c-chunks x 64KB
__device__ unsigned int g_wvkimg[8 * 65536 / 4];

// ---------------- helpers ---------------------------------------------------
__device__ __forceinline__ uint32_t smem_u32(const void* p) {
    uint32_t a;
    asm("{ .reg .u64 t; cvta.to.shared.u64 t, %1; cvt.u32.u64 %0, t; }" : "=r"(a) : "l"(p));
    return a;
}
#define SWZ128(b) ((b) ^ (((b) >> 3) & 0x70))
__device__ __forceinline__ uint32_t pack_bf16(float a, float b) {
    __nv_bfloat16 ha = __float2bfloat16(a), hb = __float2bfloat16(b);
    return (uint32_t)__bfloat16_as_ushort(ha) |
           ((uint32_t)__bfloat16_as_ushort(hb) << 16);
}
__device__ __forceinline__ void ldm_x4(uint32_t* r, uint32_t addr) {
    asm volatile("ldmatrix.sync.aligned.m8n8.x4.shared.b16 {%0,%1,%2,%3}, [%4];"
        : "=r"(r[0]), "=r"(r[1]), "=r"(r[2]), "=r"(r[3]) : "r"(addr));
}
__device__ __forceinline__ void mma16816(float* d, const uint32_t* a, const uint32_t* b) {
    asm volatile(
        "mma.sync.aligned.m16n8k16.row.col.f32.bf16.bf16.f32 "
        "{%0,%1,%2,%3}, {%4,%5,%6,%7}, {%8,%9}, {%0,%1,%2,%3};"
        : "+f"(d[0]), "+f"(d[1]), "+f"(d[2]), "+f"(d[3])
        : "r"(a[0]), "r"(a[1]), "r"(a[2]), "r"(a[3]), "r"(b[0]), "r"(b[1]));
}
__device__ __forceinline__ void cp_async16(uint32_t dst, const void* src) {
    asm volatile("cp.async.cg.shared.global [%0], [%1], 16;" :: "r"(dst), "l"(src));
}
#define CP_COMMIT() asm volatile("cp.async.commit_group;" ::: "memory")
#define CP_WAIT0()  asm volatile("cp.async.wait_group 0;" ::: "memory")

// ---------------- concat ----------------------------------------------------
__global__ void concat_kernel(const float* __restrict__ key,
                              const float* __restrict__ query,
                              float* __restrict__ x) {
    size_t i = (size_t)blockIdx.x * blockDim.x + threadIdx.x;
    if (i >= (size_t)B_ * 2 * C_ * N_) return;
    int n = (int)(i % N_);
    int c = (int)((i / N_) % (2 * C_));
    int b = (int)(i / ((size_t)N_ * 2 * C_));
    float v;
    if (c < C_) v = key  [((size_t)b * C_ + c) * N_ + n];
    else        v = query[((size_t)b * C_ + (c - C_)) * N_ + n];
    x[i] = v;
}

// ---------------- KNN -------------------------------------------------------
__global__ void knn_kernel(const float* __restrict__ pos, int* __restrict__ idx) {
    const int b = blockIdx.y;
    const int n = blockIdx.x * blockDim.x + threadIdx.x;
    const float* p = pos + (size_t)b * 3 * N_;
    const float qx = p[n], qy = p[N_ + n], qz = p[2 * N_ + n];
    const float qs = qx * qx + qy * qy + qz * qz;
    float bd[K_]; int bi[K_];
#pragma unroll
    for (int j = 0; j < K_; j++) { bd[j] = 3.4e38f; bi[j] = 0; }
    __shared__ float sx[512], sy[512], sz[512], ss[512];
    for (int t0 = 0; t0 < N_; t0 += 512) {
        __syncthreads();
        for (int i = threadIdx.x; i < 512; i += blockDim.x) {
            float x = p[t0 + i], y = p[N_ + t0 + i], z = p[2 * N_ + t0 + i];
            sx[i] = x; sy[i] = y; sz[i] = z; ss[i] = x * x + y * y + z * z;
        }
        __syncthreads();
        for (int i = 0; i < 512; i++) {
            float d = qs + ss[i] - 2.0f * (qx * sx[i] + qy * sy[i] + qz * sz[i]);
            if (d < bd[K_ - 1]) {
                int j = K_ - 1;
                while (j > 0 && d < bd[j - 1]) { bd[j] = bd[j - 1]; bi[j] = bi[j - 1]; j--; }
                bd[j] = d; bi[j] = t0 + i;
            }
        }
    }
    int* op = idx + ((size_t)b * N_ + n) * K_;
#pragma unroll
    for (int j = 0; j < K_; j++) op[j] = bi[j];
}

// ---------------- precompute small products ---------------------------------
__global__ void smallmm_kernel(const float* __restrict__ A, const float* __restrict__ Bm,
                               float* __restrict__ Cc, int O, int Id, int J, int tr) {
    int t = blockIdx.x * 256 + threadIdx.x;
    if (t >= O * J) return;
    int o = t / J, j = t % J;
    float s = 0.0f;
    for (int d = 0; d < Id; d++) s += A[o * Id + d] * Bm[d * J + j];
    if (tr) Cc[j * O + o] = s; else Cc[o * J + j] = s;
}
__global__ void bias1_kernel(const float* __restrict__ w1, const float* __restrict__ bq,
                             const float* __restrict__ bk, const float* __restrict__ pb2,
                             const float* __restrict__ ab1, float* __restrict__ out) {
    int o = blockIdx.x * 256 + threadIdx.x;
    if (o >= AH_) return;
    float s = ab1[o];
    for (int d = 0; d < DIM_; d++) s += w1[o * DIM_ + d] * (bq[d] - bk[d] + pb2[d]);
    out[o] = s;
}
// v [B][AH][N] -> v_t [B][N][AH]
__global__ void transpose_bt(const float* __restrict__ src, float* __restrict__ dst) {
    __shared__ float tile[32][33];
    int b = blockIdx.z;
    int c0 = blockIdx.y * 32, n0 = blockIdx.x * 32;
    int tx = threadIdx.x, ty = threadIdx.y;
    const float* s = src + ((size_t)b * AH_ + c0) * N_ + n0;
#pragma unroll
    for (int i = 0; i < 32; i += 8) tile[ty + i][tx] = s[(size_t)(ty + i) * N_ + tx];
    __syncthreads();
    float* d = dst + ((size_t)b * N_ + n0) * AH_ + c0;
#pragma unroll
    for (int i = 0; i < 32; i += 8) d[(size_t)(ty + i) * AH_ + tx] = tile[tx][ty + i];
}

// ---------------- att_w2 -> pre-swizzled bf16 hi/lo image --------------------
__global__ void prep_w2_kernel(const float* __restrict__ w2, unsigned int* __restrict__ img) {
    int t = blockIdx.x * 256 + threadIdx.x;
    if (t >= 256 * 256) return;
    int c = t >> 8, k4 = t & 255;
    int k = k4 * 4;
    int q = k >> 6, kl = k & 63;
    const float* src = w2 + (size_t)c * AH_ + k;
    float f0 = src[0], f1 = src[1], f2 = src[2], f3 = src[3];
    float h0 = __bfloat162float(__float2bfloat16(f0));
    float h1 = __bfloat162float(__float2bfloat16(f1));
    float h2 = __bfloat162float(__float2bfloat16(f2));
    float h3 = __bfloat162float(__float2bfloat16(f3));
    uint32_t off = SWZ128((uint32_t)((c >> 3) * 1024 + (c & 7) * 128 + kl * 2));
    char* base = (char*)img + (size_t)q * 65536;
    *(uint2*)(base + off) = make_uint2(pack_bf16(f0, f1), pack_bf16(f2, f3));
    *(uint2*)(base + 32768 + off) =
        make_uint2(pack_bf16(f0 - h0, f1 - h1), pack_bf16(f2 - h2, f3 - h3));
}

// ---------------- Wmid -> pre-swizzled bf16 hi/lo image ----------------------
__global__ void prep_wmid_kernel(const float* __restrict__ att_w1,
                                 const float* __restrict__ pos_w2,
                                 unsigned int* __restrict__ img) {
    int t = blockIdx.x * 256 + threadIdx.x;
    if (t >= 1280 * 16) return;
    int c = t >> 4, k4 = t & 15;
    float f[4];
    if (c < AH_) {
#pragma unroll 4
        for (int kk = 0; kk < 4; kk++) {
            float s = 0.0f;
            for (int d = 0; d < DIM_; d++)
                s += att_w1[(size_t)c * DIM_ + d] * pos_w2[d * PH_ + k4 * 4 + kk];
            f[kk] = s;
        }
    } else {
#pragma unroll
        for (int kk = 0; kk < 4; kk++) f[kk] = pos_w2[(c - AH_) * PH_ + k4 * 4 + kk];
    }
    float r[4];
#pragma unroll
    for (int kk = 0; kk < 4; kk++)
        r[kk] = f[kk] - __bfloat162float(__float2bfloat16(f[kk]));
    int ct = c >> 7, cl = c & 127;
    uint32_t off = (uint32_t)((cl >> 3) * 1024 + (cl & 7) * 128 +
                              ((k4 * 8) ^ ((cl & 7) << 4)));
    char* base = (char*)img + (size_t)ct * 32768;
    *(uint2*)(base + off) = make_uint2(pack_bf16(f[0], f[1]), pack_bf16(f[2], f[3]));
    *(uint2*)(base + 16384 + off) = make_uint2(pack_bf16(r[0], r[1]), pack_bf16(r[2], r[3]));
}

// ---------------- Wuq/Wvk [AH][C=128] -> image: 8 c-chunks x 64KB -------------
// chunk layout: [kc0 hi 16K][kc0 lo 16K][kc1 hi 16K][kc1 lo 16K]
__global__ void prep_wuv_kernel(const float* __restrict__ W, unsigned int* __restrict__ img) {
    int t = blockIdx.x * 256 + threadIdx.x;     // 1024 c * 32 k4
    if (t >= AH_ * 32) return;
    int c = t >> 5, k4 = t & 31;
    int k = k4 * 4;
    int kc = k >> 6, kl = k & 63;
    const float* src = W + (size_t)c * C_ + k;
    float f[4], r[4];
#pragma unroll
    for (int i = 0; i < 4; i++) {
        f[i] = src[i];
        r[i] = f[i] - __bfloat162float(__float2bfloat16(f[i]));
    }
    int ct = c >> 7, cl = c & 127;
    uint32_t off = (uint32_t)((cl >> 3) * 1024 + (cl & 7) * 128 +
                              ((kl * 2) ^ ((cl & 7) << 4)));
    char* base = (char*)img + (size_t)ct * 65536 + (size_t)kc * 32768;
    *(uint2*)(base + off) = make_uint2(pack_bf16(f[0], f[1]), pack_bf16(f[2], f[3]));
    *(uint2*)(base + 16384 + off) = make_uint2(pack_bf16(r[0], r[1]), pack_bf16(r[2], r[3]));
}

// ---------------- generic fp32 SGEMM (small GEMMs) --------------------------
template <int FLAGS>
__global__ void sgemm_kernel(const float* __restrict__ W, const float* __restrict__ Xg,
                             const float* __restrict__ bias, float* __restrict__ outg,
                             const float* __restrict__ resg, int O, int I, int M) {
    const int b = blockIdx.z;
    const float* X = Xg + (size_t)b * I * M;
    float* out = outg + (size_t)b * O * M;
    const float* res = (FLAGS & 4) ? (resg + (size_t)b * O * M) : nullptr;
    __shared__ float Ws[8][132];
    __shared__ float Xs[8][128];
    const int tid = threadIdx.x;
    const int tx = tid & 15, ty = tid >> 4;
    const int o0 = blockIdx.y * 128, m0 = blockIdx.x * 128;
    const int wr = tid >> 1, wc = (tid & 1) * 4;
    const int xr = tid >> 5, xc = (tid & 31) * 4;
    float acc[8][8];
#pragma unroll
    for (int i = 0; i < 8; i++)
#pragma unroll
        for (int j = 0; j < 8; j++) acc[i][j] = 0.0f;
    for (int kt = 0; kt < I; kt += 8) {
        float4 wv = *(const float4*)&W[(size_t)(o0 + wr) * I + kt + wc];
        float4 xv = *(const float4*)&X[(size_t)(kt + xr) * M + m0 + xc];
        __syncthreads();
        Ws[wc + 0][wr] = wv.x; Ws[wc + 1][wr] = wv.y;
        Ws[wc + 2][wr] = wv.z; Ws[wc + 3][wr] = wv.w;
        *(float4*)&Xs[xr][xc] = xv;
        __syncthreads();
#pragma unroll
        for (int k = 0; k < 8; k++) {
            float a[8], bb[8];
            *(float4*)&a[0]  = *(const float4*)&Ws[k][ty * 8];
            *(float4*)&a[4]  = *(const float4*)&Ws[k][ty * 8 + 4];
            *(float4*)&bb[0] = *(const float4*)&Xs[k][tx * 8];
            *(float4*)&bb[4] = *(const float4*)&Xs[k][tx * 8 + 4];
#pragma unroll
            for (int i = 0; i < 8; i++)
#pragma unroll
                for (int j = 0; j < 8; j++) acc[i][j] += a[i] * bb[j];
        }
    }
#pragma unroll
    for (int i = 0; i < 8; i++) {
        const int o = o0 + ty * 8 + i;
        const float bv = bias[o];
        float* orow = out + (size_t)o * M + m0 + tx * 8;
        const float* rrow = (FLAGS & 4) ? (res + (size_t)o * M + m0 + tx * 8) : nullptr;
#pragma unroll
        for (int jj = 0; jj < 8; jj += 4) {
            float4 v;
            v.x = acc[i][jj + 0] + bv; v.y = acc[i][jj + 1] + bv;
            v.z = acc[i][jj + 2] + bv; v.w = acc[i][jj + 3] + bv;
            if (FLAGS & 1) { v.x = fmaxf(v.x, 0.f); v.y = fmaxf(v.y, 0.f);
                             v.z = fmaxf(v.z, 0.f); v.w = fmaxf(v.w, 0.f); }
            if (FLAGS & 2) { float4 old = *(float4*)&orow[jj];
                             v.x += old.x; v.y += old.y; v.z += old.z; v.w += old.w; }
            if (FLAGS & 4) { float4 r = *(const float4*)&rrow[jj];
                             v.x += r.x; v.y += r.y; v.z += r.z; v.w += r.w; }
            *(float4*)&orow[jj] = v;
        }
    }
}

// ---------------- pos_rel conv1 + BN partial stats ---------------------------
__global__ void posrel_kernel(const float* __restrict__ pos, const int* __restrict__ idx,
                              const float* __restrict__ w, const float* __restrict__ bias,
                              float* __restrict__ t1, float* __restrict__ part) {
    size_t i = (size_t)blockIdx.x * 256 + threadIdx.x;
    int k = (int)(i & 15);
    int n = (int)((i >> 4) & (N_ - 1));
    int c = (int)((i >> 16) & (PH_ - 1));
    int b = (int)(i >> 22);
    int m = idx[(((size_t)b * N_ + n) << 4) + k];
    const float* p = pos + (size_t)b * 3 * N_;
    float rx = p[n] - p[m];
    float ry = p[N_ + n] - p[N_ + m];
    float rz = p[2 * N_ + n] - p[2 * N_ + m];
    float val = w[c * 3] * rx + w[c * 3 + 1] * ry + w[c * 3 + 2] * rz + bias[c];
    t1[i] = val;
    __shared__ float ssum[256], ssq[256];
    ssum[threadIdx.x] = val; ssq[threadIdx.x] = val * val;
    __syncthreads();
    for (int st = 128; st > 0; st >>= 1) {
        if ((int)threadIdx.x < st) {
            ssum[threadIdx.x] += ssum[threadIdx.x + st];
            ssq[threadIdx.x]  += ssq[threadIdx.x + st];
        }
        __syncthreads();
    }
    if (threadIdx.x == 0) {
        int cb = (blockIdx.x >> 8) & (PH_ - 1);
        int bb = blockIdx.x >> 14;
        int sblk = blockIdx.x & 255;
        size_t o = ((size_t)cb * 512 + bb * 256 + sblk) * 2;
        part[o] = ssum[0]; part[o + 1] = ssq[0];
    }
}

// ---------------- BN finalize ------------------------------------------------
__global__ void finalize_stats(const float* __restrict__ part, int P, int ps, int cs,
                               const float* __restrict__ g, const float* __restrict__ be,
                               float* __restrict__ sc, float* __restrict__ sh, float cnt) {
    int c = blockIdx.x;
    double s = 0.0, q = 0.0;
    for (int p = threadIdx.x; p < P; p += blockDim.x) {
        size_t o = ((size_t)p * ps + (size_t)c * cs) * 2;
        s += (double)part[o]; q += (double)part[o + 1];
    }
    __shared__ double S[256], Q[256];
    S[threadIdx.x] = s; Q[threadIdx.x] = q;
    __syncthreads();
    for (int st = 128; st > 0; st >>= 1) {
        if ((int)threadIdx.x < st) {
            S[threadIdx.x] += S[threadIdx.x + st];
            Q[threadIdx.x] += Q[threadIdx.x + st];
        }
        __syncthreads();
    }
    if (threadIdx.x == 0) {
        double mean = S[0] / (double)cnt;
        double var  = Q[0] / (double)cnt - mean * mean;
        float scv = g[c] * (float)(1.0 / sqrt(var + 1e-5));
        sc[c] = scv;
        sh[c] = be[c] - (float)mean * scv;
    }
}

// ---------------- u/v GEMM on HMMA ------------------------------------------
// out[c(1024)][n(128 per block)] = W[c][k] * X[k][n],  K = 128 (2 chunks)
#define UV_X     0
#define UV_W(s)  (65536 + (s) * 65536)
#define UV_SMEM  196608

__global__ __launch_bounds__(256, 1) void uv_hmma(
    const float* __restrict__ query, const float* __restrict__ key,
    const unsigned int* __restrict__ wuqimg, const unsigned int* __restrict__ wvkimg,
    float* __restrict__ ug, float* __restrict__ vg) {
    extern __shared__ char smc[];
    const uint32_t sb = smem_u32(smc);
    const int tid = threadIdx.x, lane = tid & 31, wid = tid >> 5;
    const int z = blockIdx.y;
    const int b = z & 1, which = z >> 1;
    const int n0 = blockIdx.x * 128;
    const float* X = (which == 0 ? query : key) + (size_t)b * C_ * N_;
    const unsigned int* wimg = (which == 0 ? wuqimg : wvkimg);
    float* out = (which == 0 ? ug : vg) + (size_t)b * AH_ * N_;
    const int warp_cg = wid >> 1;    // 4 x 32-c groups
    const int warp_mg = wid & 1;     // 2 x 64-n groups

    // prefetch W chunk 0 (64KB)
    {
        const uint4* src = (const uint4*)wimg;
        uint32_t dst = sb + UV_W(0);
#pragma unroll
        for (int it = 0; it < 16; it++)
            cp_async16(dst + (it * 256 + tid) * 16, src + it * 256 + tid);
        CP_COMMIT();
    }
    // convert X tile: 128 k x 128 n -> bf16 hi/lo atoms (2 k-chunks)
    {
        char* xbase = smc + UV_X;
        int m = tid & 127, khalf = tid >> 7;
#pragma unroll
        for (int k2 = 0; k2 < 32; k2++) {
            int k = khalf * 64 + k2 * 2;
            int kl = k & 63;
            float x0 = X[(size_t)k * N_ + n0 + m];
            float x1 = X[(size_t)(k + 1) * N_ + n0 + m];
            float l0 = x0 - __bfloat162float(__float2bfloat16(x0));
            float l1 = x1 - __bfloat162float(__float2bfloat16(x1));
            uint32_t off = (uint32_t)((m >> 3) * 1024 + (m & 7) * 128 +
                                      ((kl * 2) ^ ((m & 7) << 4)));
            char* dst = xbase + khalf * 32768;
            *(uint32_t*)(dst + off) = pack_bf16(x0, x1);
            *(uint32_t*)(dst + 16384 + off) = pack_bf16(l0, l1);
        }
    }
    CP_WAIT0();
    __syncthreads();

    const int g = lane >> 3, lr = lane & 7;
    const int wrow = warp_cg * 32 + (g & 1) * 8 + lr;
    const int xrow = warp_mg * 64 + (g >> 1) * 8 + lr;
    const int wkb0 = (g >> 1) * 16;
    const int xkb0 = (g & 1) * 16;
    const uint32_t sX = sb + UV_X;

    for (int ct = 0; ct < 8; ct++) {
        const int s = ct & 1;
        if (ct + 1 < 8) {
            const uint4* src = (const uint4*)wimg + (ct + 1) * 4096;
            uint32_t dst = sb + UV_W(s ^ 1);
#pragma unroll
            for (int it = 0; it < 16; it++)
                cp_async16(dst + (it * 256 + tid) * 16, src + it * 256 + tid);
            CP_COMMIT();
        }
        const uint32_t sW = sb + UV_W(s);
        float acc[2][8][4];
#pragma unroll
        for (int a = 0; a < 2; a++)
#pragma unroll
            for (int q = 0; q < 8; q++)
#pragma unroll
                for (int j = 0; j < 4; j++) acc[a][q][j] = 0.0f;
#pragma unroll
        for (int kc = 0; kc < 2; kc++) {
#pragma unroll
            for (int ks = 0; ks < 4; ks++) {
                uint32_t Whi[2][4], Wlo[2][4], Xhf[4][4], Xlf[4][4];
#pragma unroll
                for (int ct2 = 0; ct2 < 2; ct2++) {
                    int cr = wrow + ct2 * 16;
                    uint32_t ro = (uint32_t)((cr >> 3) * 1024 + (cr & 7) * 128);
                    uint32_t kb = (uint32_t)((ks * 32 + wkb0) ^ ((cr & 7) << 4));
                    ldm_x4(Whi[ct2], sW + kc * 32768 + ro + kb);
                    ldm_x4(Wlo[ct2], sW + kc * 32768 + 16384 + ro + kb);
                }
#pragma unroll
                for (int np = 0; np < 4; np++) {
                    int mr = xrow + np * 16;
                    uint32_t ro = (uint32_t)((mr >> 3) * 1024 + (mr & 7) * 128);
                    uint32_t kb = (uint32_t)((ks * 32 + xkb0) ^ ((mr & 7) << 4));
                    ldm_x4(Xhf[np], sX + kc * 32768 + ro + kb);
                    ldm_x4(Xlf[np], sX + kc * 32768 + 16384 + ro + kb);
                }
#pragma unroll
                for (int ct2 = 0; ct2 < 2; ct2++)
#pragma unroll
                    for (int np = 0; np < 4; np++) {
                        mma16816(acc[ct2][np * 2],     Whi[ct2], &Xhf[np][0]);
                        mma16816(acc[ct2][np * 2],     Wlo[ct2], &Xhf[np][0]);
                        mma16816(acc[ct2][np * 2],     Whi[ct2], &Xlf[np][0]);
                        mma16816(acc[ct2][np * 2 + 1], Whi[ct2], &Xhf[np][2]);
                        mma16816(acc[ct2][np * 2 + 1], Wlo[ct2], &Xhf[np][2]);
                        mma16816(acc[ct2][np * 2 + 1], Whi[ct2], &Xlf[np][2]);
                    }
            }
        }
#pragma unroll
        for (int ct2 = 0; ct2 < 2; ct2++) {
#pragma unroll
            for (int j = 0; j < 4; j++) {
                int c_g = ct * 128 + warp_cg * 32 + ct2 * 16 + (lane >> 2) + (j >> 1) * 8;
                float* orow = out + (size_t)c_g * N_ + n0;
#pragma unroll
                for (int q = 0; q < 8; q++) {
                    int m_loc = warp_mg * 64 + q * 8 + (lane & 3) * 2 + (j & 1);
                    orow[m_loc] = acc[ct2][q][j];
                }
            }
        }
        CP_WAIT0();
        __syncthreads();
    }
}

// ---------------- fused mid on HMMA, smem-staged gather ----------------------
#define FM_XHI   0
#define FM_XLO   16384
#define FM_W(s)  (32768 + (s) * 32768)
#define FM_VG    98304
#define FM_U     164352
#define FM_RED   168960
#define FM_SIDX  171008
#define FM_SMEM  171520

__global__ __launch_bounds__(256, 1) void fused_mid_hmma(
    const float* __restrict__ t1, const float* __restrict__ psc,
    const float* __restrict__ psh, const unsigned int* __restrict__ wimg,
    const float* __restrict__ bias1, const float* __restrict__ pos_b2,
    const float* __restrict__ u, const float* __restrict__ vt,
    const int* __restrict__ idx, float* __restrict__ h,
    float* __restrict__ pe, float* __restrict__ part) {
    extern __shared__ char smc[];
    const uint32_t sb = smem_u32(smc);
    const int tid = threadIdx.x, lane = tid & 31, wid = tid >> 5;
    const int b = blockIdx.y, m0 = blockIdx.x * 128;
    const int warp_cg = wid >> 1;
    const int warp_mg = wid & 1;

    int* sidx = (int*)(smc + FM_SIDX);
    float* vgs = (float*)(smc + FM_VG);
    float* us  = (float*)(smc + FM_U);
    float* redS = (float*)(smc + FM_RED);
    float* redQ = redS + 256;

    if (tid < 128) sidx[tid] = idx[((size_t)b * N_ + (m0 >> 4)) * K_ + tid];

    {
        const uint4* src = (const uint4*)wimg;
        uint32_t dst = sb + FM_W(0);
#pragma unroll
        for (int it = 0; it < 8; it++)
            cp_async16(dst + (it * 256 + tid) * 16, src + it * 256 + tid);
        CP_COMMIT();
    }
    {
        const float* tb = t1 + (size_t)b * PH_ * M_ + m0;
        char* xhi = smc + FM_XHI;
        char* xlo = smc + FM_XLO;
        int m = tid & 127, khalf = tid >> 7;
#pragma unroll
        for (int k2 = 0; k2 < 16; k2++) {
            int k = khalf * 32 + k2 * 2;
            float x0 = tb[(size_t)k * M_ + m];
            float x1 = tb[(size_t)(k + 1) * M_ + m];
            x0 = fmaxf(x0 * psc[k] + psh[k], 0.f);
            x1 = fmaxf(x1 * psc[k + 1] + psh[k + 1], 0.f);
            float l0 = x0 - __bfloat162float(__float2bfloat16(x0));
            float l1 = x1 - __bfloat162float(__float2bfloat16(x1));
            uint32_t off = (uint32_t)((m >> 3) * 1024 + (m & 7) * 128 +
                                      ((k * 2) ^ ((m & 7) << 4)));
            *(uint32_t*)(xhi + off) = pack_bf16(x0, x1);
            *(uint32_t*)(xlo + off) = pack_bf16(l0, l1);
        }
    }
    CP_WAIT0();
    __syncthreads();

    const int g = lane >> 3, lr = lane & 7;
    const int wrow = warp_cg * 32 + (g & 1) * 8 + lr;
    const int xrow = warp_mg * 64 + (g >> 1) * 8 + lr;
    const int wkb0 = (g >> 1) * 16;
    const int xkb0 = (g & 1) * 16;
    const uint32_t sX = sb + FM_XHI;
    const float* vtb = vt + (size_t)b * N_ * AH_;
    const int n0 = m0 >> 4;

    for (int ct = 0; ct < 10; ct++) {
        const int s = ct & 1;
        if (ct + 1 < 10) {
            const uint4* src = (const uint4*)wimg + (ct + 1) * 2048;
            uint32_t dst = sb + FM_W(s ^ 1);
#pragma unroll
            for (int it = 0; it < 8; it++)
                cp_async16(dst + (it * 256 + tid) * 16, src + it * 256 + tid);
            CP_COMMIT();
        }
        if (ct < 8) {
#pragma unroll
            for (int jj = 0; jj < 16; jj++) {
                int j = wid * 16 + jj;
                const float* row = vtb + (size_t)sidx[j] * AH_ + ct * 128;
#pragma unroll
                for (int cc = 0; cc < 4; cc++) {
                    int c = cc * 32 + lane;
                    vgs[c * 129 + j] = row[c];
                }
            }
#pragma unroll
            for (int it = 0; it < 4; it++) {
                int e = it * 256 + tid;
                int c = e >> 3, nn = e & 7;
                us[c * 9 + nn] = u[((size_t)b * AH_ + ct * 128 + c) * N_ + n0 + nn]
                               + bias1[ct * 128 + c];
            }
        }
        const uint32_t sW = sb + FM_W(s);
        float acc[2][8][4];
#pragma unroll
        for (int a = 0; a < 2; a++)
#pragma unroll
            for (int q = 0; q < 8; q++)
#pragma unroll
                for (int j = 0; j < 4; j++) acc[a][q][j] = 0.0f;
#pragma unroll
        for (int ks = 0; ks < 4; ks++) {
            uint32_t Whi[2][4], Wlo[2][4], Xhf[4][4], Xlf[4][4];
#pragma unroll
            for (int ct2 = 0; ct2 < 2; ct2++) {
                int cr = wrow + ct2 * 16;
                uint32_t ro = (uint32_t)((cr >> 3) * 1024 + (cr & 7) * 128);
                uint32_t kb = (uint32_t)((ks * 32 + wkb0) ^ ((cr & 7) << 4));
                ldm_x4(Whi[ct2], sW + ro + kb);
                ldm_x4(Wlo[ct2], sW + 16384 + ro + kb);
            }
#pragma unroll
            for (int np = 0; np < 4; np++) {
                int mr = xrow + np * 16;
                uint32_t ro = (uint32_t)((mr >> 3) * 1024 + (mr & 7) * 128);
                uint32_t kb = (uint32_t)((ks * 32 + xkb0) ^ ((mr & 7) << 4));
                ldm_x4(Xhf[np], sX + ro + kb);
                ldm_x4(Xlf[np], sX + 16384 + ro + kb);
            }
#pragma unroll
            for (int ct2 = 0; ct2 < 2; ct2++)
#pragma unroll
                for (int np = 0; np < 4; np++) {
                    mma16816(acc[ct2][np * 2],     Whi[ct2], &Xhf[np][0]);
                    mma16816(acc[ct2][np * 2],     Wlo[ct2], &Xhf[np][0]);
                    mma16816(acc[ct2][np * 2],     Whi[ct2], &Xlf[np][0]);
                    mma16816(acc[ct2][np * 2 + 1], Whi[ct2], &Xhf[np][2]);
                    mma16816(acc[ct2][np * 2 + 1], Wlo[ct2], &Xhf[np][2]);
                    mma16816(acc[ct2][np * 2 + 1], Whi[ct2], &Xlf[np][2]);
                }
        }
        if (ct < 8) {
            __syncthreads();
            float sS[2][2], sQ[2][2];
#pragma unroll
            for (int a = 0; a < 2; a++) { sS[a][0] = sS[a][1] = 0.f; sQ[a][0] = sQ[a][1] = 0.f; }
#pragma unroll
            for (int ct2 = 0; ct2 < 2; ct2++) {
#pragma unroll
                for (int j = 0; j < 4; j++) {
                    int rh = j >> 1;
                    int c_loc = warp_cg * 32 + ct2 * 16 + (lane >> 2) + rh * 8;
                    int c_g = ct * 128 + c_loc;
                    float* hrow = h + ((size_t)b * AH_ + c_g) * M_ + m0;
#pragma unroll
                    for (int q = 0; q < 8; q++) {
                        int m_loc = warp_mg * 64 + q * 8 + (lane & 3) * 2 + (j & 1);
                        float val = acc[ct2][q][j] + us[c_loc * 9 + (m_loc >> 4)]
                                  - vgs[c_loc * 129 + m_loc];
                        hrow[m_loc] = val;
                        sS[ct2][rh] += val; sQ[ct2][rh] += val * val;
                    }
                }
            }
#pragma unroll
            for (int ct2 = 0; ct2 < 2; ct2++)
#pragma unroll
                for (int rh = 0; rh < 2; rh++) {
                    float s1 = sS[ct2][rh], q1 = sQ[ct2][rh];
                    s1 += __shfl_xor_sync(0xffffffffu, s1, 1);
                    s1 += __shfl_xor_sync(0xffffffffu, s1, 2);
                    q1 += __shfl_xor_sync(0xffffffffu, q1, 1);
                    q1 += __shfl_xor_sync(0xffffffffu, q1, 2);
                    if ((lane & 3) == 0) {
                        int c_loc = warp_cg * 32 + ct2 * 16 + (lane >> 2) + rh * 8;
                        redS[c_loc * 2 + warp_mg] = s1;
                        redQ[c_loc * 2 + warp_mg] = q1;
                    }
                }
            __syncthreads();
            if (tid < 128) {
                float ss = redS[tid * 2] + redS[tid * 2 + 1];
                float qq = redQ[tid * 2] + redQ[tid * 2 + 1];
                size_t po = (((size_t)b * 512 + blockIdx.x) * AH_ + ct * 128 + tid) * 2;
                part[po] = ss; part[po + 1] = qq;
            }
        } else {
#pragma unroll
            for (int ct2 = 0; ct2 < 2; ct2++) {
#pragma unroll
                for (int j = 0; j < 4; j++) {
                    int c_pe = (ct - 8) * 128 + warp_cg * 32 + ct2 * 16 + (lane >> 2) + (j >> 1) * 8;
                    float bv = pos_b2[c_pe];
                    float* prow = pe + ((size_t)b * DIM_ + c_pe) * M_ + m0;
#pragma unroll
                    for (int q = 0; q < 8; q++) {
                        int m_loc = warp_mg * 64 + q * 8 + (lane & 3) * 2 + (j & 1);
                        prow[m_loc] = acc[ct2][q][j] + bv;
                    }
                }
            }
        }
        CP_WAIT0();
        __syncthreads();
    }
}

// ---------------- attn GEMM2 (HMMA, cp.async pipelined) ----------------------
#define A_OFF(s)  ((s) * 32768)
#define B_OFF(s)  (65536 + (s) * 65536)
#define STG_OFF   196608
#define SMEM_ATT2 229376

__device__ __forceinline__ void attn2_cpasync(uint32_t sb, int s, int cq,
                                              const float* hbase, const uint4* w2img,
                                              int tid) {
    const uint4* src = w2img + (size_t)cq * 4096;
    uint32_t bdst = sb + B_OFF(s);
#pragma unroll
    for (int it = 0; it < 16; it++) {
        int i = it * 256 + tid;
        cp_async16(bdst + i * 16, src + i);
    }
#pragma unroll
    for (int it = 0; it < 8; it++) {
        int ch = it * 256 + tid;
        int krow = ch >> 5;
        const float* srcr = hbase + (size_t)(cq * 64 + krow) * M_ + (ch & 31) * 4;
        cp_async16(sb + STG_OFF + krow * 512 + (ch & 31) * 16, srcr);
    }
}

__device__ __forceinline__ void attn2_convert(char* smc, int s, int cq,
                                              const float* __restrict__ scale,
                                              const float* __restrict__ shift,
                                              int wid, int lane) {
    const float* stg = (const float*)(smc + STG_OFF);
    char* dst = smc + A_OFF(s);
#pragma unroll
    for (int g2 = 0; g2 < 2; g2++) {
        int base_k = wid * 8 + g2 * 4;
        float4 v[4];
#pragma unroll
        for (int r = 0; r < 4; r++)
            v[r] = *(const float4*)&stg[(base_k + r) * 128 + lane * 4];
        float X[4][4], L[4][4];
#pragma unroll
        for (int r = 0; r < 4; r++) {
            float sc = scale[cq * 64 + base_k + r];
            float sh = shift[cq * 64 + base_k + r];
            float xv[4] = {v[r].x, v[r].y, v[r].z, v[r].w};
#pragma unroll
            for (int mm = 0; mm < 4; mm++) {
                float x = fmaxf(xv[mm] * sc + sh, 0.f);
                X[mm][r] = x;
                L[mm][r] = x - __bfloat162float(__float2bfloat16(x));
            }
        }
#pragma unroll
        for (int mm = 0; mm < 4; mm++) {
            int m = lane * 4 + mm;
            uint32_t off = (uint32_t)((m >> 3) * 1024 + (m & 7) * 128 +
                                      ((base_k * 2) ^ ((m & 7) << 4)));
            *(uint2*)(dst + off) = make_uint2(pack_bf16(X[mm][0], X[mm][1]),
                                              pack_bf16(X[mm][2], X[mm][3]));
            *(uint2*)(dst + 16384 + off) = make_uint2(pack_bf16(L[mm][0], L[mm][1]),
                                                      pack_bf16(L[mm][2], L[mm][3]));
        }
    }
}

__global__ __launch_bounds__(256, 1) void attn2_hmma_kernel(
    const uint4* __restrict__ w2img, const float* __restrict__ h,
    const float* __restrict__ scale, const float* __restrict__ shift,
    const float* __restrict__ pe, const float* __restrict__ vf,
    float* __restrict__ agg) {
    extern __shared__ char smc[];
    const uint32_t sb = smem_u32(smc);
    const int tid = threadIdx.x, lane = tid & 31, wid = tid >> 5;
    const int b = blockIdx.y, m0 = blockIdx.x * 128;
    const int warp_m = wid >> 2, warp_c = wid & 3;

    const float* hbase = h + (size_t)b * AH_ * M_ + m0;

    float acc[4][8][4];
#pragma unroll
    for (int mt = 0; mt < 4; mt++)
#pragma unroll
        for (int nt = 0; nt < 8; nt++)
#pragma unroll
            for (int j = 0; j < 4; j++) acc[mt][nt][j] = 0.0f;

    const int g = lane >> 3, lr = lane & 7;
    const int amr  = warp_m * 64 + (g & 1) * 8 + lr;
    const int bcr  = warp_c * 64 + (g >> 1) * 8 + lr;
    const int akb0 = (g >> 1) * 16;
    const int bkb0 = (g & 1) * 16;

    attn2_cpasync(sb, 0, 0, hbase, w2img, tid);
    CP_COMMIT();
    CP_WAIT0();
    __syncthreads();
    attn2_convert(smc, 0, 0, scale, shift, wid, lane);
    __syncthreads();

    for (int cq = 0; cq < 16; cq++) {
        const int s = cq & 1;
        if (cq + 1 < 16) {
            attn2_cpasync(sb, s ^ 1, cq + 1, hbase, w2img, tid);
            CP_COMMIT();
        }
        const uint32_t sA = sb + A_OFF(s);
        const uint32_t sB = sb + B_OFF(s);
#pragma unroll
        for (int ks = 0; ks < 4; ks++) {
            uint32_t Ahi[4][4], Alo[4][4], Bhi[4][4], Blo[4][4];
#pragma unroll
            for (int mt = 0; mt < 4; mt++) {
                int m = amr + mt * 16;
                uint32_t ro = (uint32_t)((m >> 3) * 1024 + (m & 7) * 128);
                uint32_t kb = (uint32_t)((ks * 32 + akb0) ^ ((m & 7) << 4));
                ldm_x4(Ahi[mt], sA + ro + kb);
                ldm_x4(Alo[mt], sA + 16384 + ro + kb);
            }
#pragma unroll
            for (int np = 0; np < 4; np++) {
                int c = bcr + np * 16;
                uint32_t ro = (uint32_t)((c >> 3) * 1024 + (c & 7) * 128);
                uint32_t kb = (uint32_t)((ks * 32 + bkb0) ^ ((c & 7) << 4));
                ldm_x4(Bhi[np], sB + ro + kb);
                ldm_x4(Blo[np], sB + 32768 + ro + kb);
            }
#pragma unroll
            for (int mt = 0; mt < 4; mt++)
#pragma unroll
                for (int np = 0; np < 4; np++) {
                    mma16816(acc[mt][np * 2],     Ahi[mt], &Bhi[np][0]);
                    mma16816(acc[mt][np * 2],     Alo[mt], &Bhi[np][0]);
                    mma16816(acc[mt][np * 2],     Ahi[mt], &Blo[np][0]);
                    mma16816(acc[mt][np * 2 + 1], Ahi[mt], &Bhi[np][2]);
                    mma16816(acc[mt][np * 2 + 1], Alo[mt], &Bhi[np][2]);
                    mma16816(acc[mt][np * 2 + 1], Ahi[mt], &Blo[np][2]);
                }
        }
        if (cq + 1 < 16) {
            CP_WAIT0();
            __syncthreads();
            attn2_convert(smc, s ^ 1, cq + 1, scale, shift, wid, lane);
            __syncthreads();
        }
    }
    __syncthreads();

    float* pes = (float*)smc;
    for (int i = tid; i < 256 * 32; i += 256) {
        int row = i >> 5, q = i & 31;
        float4 v = *(const float4*)(pe + ((size_t)(b * DIM_ + row)) * M_ + m0 + q * 4);
        *(float4*)&pes[row * 132 + q * 4] = v;
    }
    __syncthreads();

#pragma unroll
    for (int mt = 0; mt < 4; mt++) {
        const int mbase = warp_m * 64 + mt * 16;
        const int n = (m0 + mbase) >> 4;
        const int r = lane >> 2;
#pragma unroll
        for (int nt = 0; nt < 8; nt++) {
#pragma unroll
            for (int j = 0; j < 2; j++) {
                int c = warp_c * 64 + nt * 8 + (lane & 3) * 2 + j;
                float v0 = acc[mt][nt][j], v1 = acc[mt][nt][2 + j];
                float mx = fmaxf(v0, v1);
                mx = fmaxf(mx, __shfl_xor_sync(0xffffffffu, mx, 4));
                mx = fmaxf(mx, __shfl_xor_sync(0xffffffffu, mx, 8));
                mx = fmaxf(mx, __shfl_xor_sync(0xffffffffu, mx, 16));
                float e0 = __expf(v0 - mx), e1 = __expf(v1 - mx);
                float se = e0 + e1;
                se += __shfl_xor_sync(0xffffffffu, se, 4);
                se += __shfl_xor_sync(0xffffffffu, se, 8);
                se += __shfl_xor_sync(0xffffffffu, se, 16);
                float p0 = pes[c * 132 + mbase + r];
                float p1 = pes[c * 132 + mbase + r + 8];
                float t = e0 * p0 + e1 * p1;
                t += __shfl_xor_sync(0xffffffffu, t, 4);
                t += __shfl_xor_sync(0xffffffffu, t, 8);
                t += __shfl_xor_sync(0xffffffffu, t, 16);
                if (r == 0) {
                    size_t o = ((size_t)(b * DIM_ + c)) * N_ + n;
                    agg[o] = vf[o] + t / se;
                }
            }
        }
    }
}

// ---------------- launch ----------------------------------------------------
extern "C" void kernel_launch(void* const* d_in, const int* in_sizes, int n_in,
                              void* d_out, int out_size) {
    const float* pos     = (const float*)d_in[0];
    const float* key     = (const float*)d_in[1];
    const float* query   = (const float*)d_in[2];
    const float* mlpv_w1 = (const float*)d_in[3];
    const float* mlpv_b1 = (const float*)d_in[4];
    const float* mlpv_w2 = (const float*)d_in[5];
    const float* mlpv_b2 = (const float*)d_in[6];
    const float* mlpv_ws = (const float*)d_in[7];
    const float* mlpv_bs = (const float*)d_in[8];
    const float* wk      = (const float*)d_in[9];
    const float* bk      = (const float*)d_in[10];
    const float* wq      = (const float*)d_in[11];
    const float* bq      = (const float*)d_in[12];
    const float* wv      = (const float*)d_in[13];
    const float* bv      = (const float*)d_in[14];
    const float* pos_w1  = (const float*)d_in[15];
    const float* pos_b1  = (const float*)d_in[16];
    const float* pos_g1  = (const float*)d_in[17];
    const float* pos_be1 = (const float*)d_in[18];
    const float* pos_w2  = (const float*)d_in[19];
    const float* pos_b2  = (const float*)d_in[20];
    const float* att_w1  = (const float*)d_in[21];
    const float* att_b1  = (const float*)d_in[22];
    const float* att_g1  = (const float*)d_in[23];
    const float* att_be1 = (const float*)d_in[24];
    const float* att_w2  = (const float*)d_in[25];
    const float* we      = (const float*)d_in[27];
    const float* be      = (const float*)d_in[28];
    float* out = (float*)d_out;

    void* p;
#define GETP(sym, var) cudaGetSymbolAddress(&p, sym); float* var = (float*)p;
    GETP(g_x, x_)       GETP(g_t, t_)       GETP(g_value, val)
    GETP(g_vf, vf_)     GETP(g_u, u_)       GETP(g_v, v_)
    GETP(g_vt, vt_)
    GETP(g_t1, t1_)     GETP(g_pe, pe_)     GETP(g_h, h_)
    GETP(g_agg, agg)    GETP(g_part, part)  GETP(g_partp, partp)
    GETP(g_Wuq, Wuq)    GETP(g_Wvk, Wvk)    GETP(g_bias1, bias1)
    GETP(g_scp, scp)    GETP(g_shp, shp)    GETP(g_sca, sca)
    GETP(g_sha, sha)
#undef GETP
    cudaGetSymbolAddress(&p, g_idx);      int* idx = (int*)p;
    cudaGetSymbolAddress(&p, g_w2img);    unsigned int* w2img = (unsigned int*)p;
    cudaGetSymbolAddress(&p, g_wmidimg);  unsigned int* wmidimg = (unsigned int*)p;
    cudaGetSymbolAddress(&p, g_wuqimg);   unsigned int* wuqimg = (unsigned int*)p;
    cudaGetSymbolAddress(&p, g_wvkimg);   unsigned int* wvkimg = (unsigned int*)p;

    // --- precompute folded weights + weight images ---
    smallmm_kernel<<<(AH_ * C_ + 255) / 256, 256>>>(att_w1, wq, Wuq, AH_, DIM_, C_, 0);
    smallmm_kernel<<<(AH_ * C_ + 255) / 256, 256>>>(att_w1, wk, Wvk, AH_, DIM_, C_, 0);
    bias1_kernel<<<(AH_ + 255) / 256, 256>>>(att_w1, bq, bk, pos_b2, att_b1, bias1);
    prep_w2_kernel<<<(256 * 256) / 256, 256>>>(att_w2, w2img);
    prep_wmid_kernel<<<(1280 * 16 + 255) / 256, 256>>>(att_w1, pos_w2, wmidimg);
    prep_wuv_kernel<<<(AH_ * 32 + 255) / 256, 256>>>(Wuq, wuqimg);
    prep_wuv_kernel<<<(AH_ * 32 + 255) / 256, 256>>>(Wvk, wvkimg);

    // --- front end ---
    concat_kernel<<<(unsigned)(((size_t)B_ * 2 * C_ * N_ + 255) / 256), 256>>>(key, query, x_);
    knn_kernel<<<dim3(N_ / 256, B_), 256>>>(pos, idx);
    sgemm_kernel<1><<<dim3(N_ / 128, C_ / 128, B_), 256>>>(mlpv_w1, x_, mlpv_b1, t_, nullptr, C_, 2 * C_, N_);
    sgemm_kernel<0><<<dim3(N_ / 128, C_ / 128, B_), 256>>>(mlpv_w2, t_, mlpv_b2, val, nullptr, C_, C_, N_);
    sgemm_kernel<2><<<dim3(N_ / 128, C_ / 128, B_), 256>>>(mlpv_ws, x_, mlpv_bs, val, nullptr, C_, 2 * C_, N_);
    sgemm_kernel<0><<<dim3(N_ / 128, DIM_ / 128, B_), 256>>>(wv, val, bv, vf_, nullptr, DIM_, C_, N_);

    // --- u/v on HMMA ---
    cudaFuncSetAttribute(uv_hmma, cudaFuncAttributeMaxDynamicSharedMemorySize, UV_SMEM);
    uv_hmma<<<dim3(N_ / 128, 4), 256, UV_SMEM>>>(query, key, wuqimg, wvkimg, u_, v_);
    transpose_bt<<<dim3(N_ / 32, AH_ / 32, B_), dim3(32, 8)>>>(v_, vt_);

    // --- pos_rel conv1 + pos BN ---
    posrel_kernel<<<(unsigned)(((size_t)B_ * PH_ * M_) / 256), 256>>>(pos, idx, pos_w1, pos_b1, t1_, partp);
    finalize_stats<<<PH_, 256>>>(partp, 512, 1, 512, pos_g1, pos_be1, scp, shp, (float)((size_t)B_ * M_));

    // --- fused mid on HMMA with smem-staged gather ---
    cudaFuncSetAttribute(fused_mid_hmma, cudaFuncAttributeMaxDynamicSharedMemorySize, FM_SMEM);
    fused_mid_hmma<<<dim3(M_ / 128, B_), 256, FM_SMEM>>>(
        t1_, scp, shp, wmidimg, bias1, pos_b2, u_, vt_, idx, h_, pe_, part);
    finalize_stats<<<AH_, 256>>>(part, B_ * 512, AH_, 1, att_g1, att_be1, sca, sha, (float)((size_t)B_ * M_));

    // --- big GEMM2: cp.async-pipelined HMMA + softmax + aggregation ---
    cudaFuncSetAttribute(attn2_hmma_kernel, cudaFuncAttributeMaxDynamicSharedMemorySize, SMEM_ATT2);
    attn2_hmma_kernel<<<dim3(M_ / 128, B_), 256, SMEM_ATT2>>>(
        (const uint4*)w2img, h_, sca, sha, pe_, vf_, agg);

    // --- final projection + residual ---
    sgemm_kernel<4><<<dim3(N_ / 128, C_ / 128, B_), 256>>>(we, agg, be, out, val, C_, DIM_, N_);
}

// round 11
// speedup vs baseline: 1.1529x; 1.1529x over previous
#include <cuda_runtime.h>
#include <cuda_bf16.h>
#include <cuda_fp16.h>
#include <math.h>
#include <stdint.h>

#define B_   2
#define C_   128
#define N_   4096
#define K_   16
#define DIM_ 256
#define PH_  64
#define AH_  1024
#define M_   (N_ * K_)          // 65536 columns per batch in (n,k) space

// ---------------- scratch ---------------------------------------------------
__device__ float g_x    [(size_t)B_ * 2 * C_ * N_];
__device__ float g_t    [(size_t)B_ * C_ * N_];
__device__ float g_value[(size_t)B_ * C_ * N_];
__device__ float g_vf   [(size_t)B_ * DIM_ * N_];
__device__ float g_u    [(size_t)B_ * AH_ * N_];
__device__ float g_v    [(size_t)B_ * AH_ * N_];
__device__ float g_vt   [(size_t)B_ * N_ * AH_];       // v transposed: [B][N][AH]
__device__ int   g_idx  [(size_t)B_ * N_ * K_];
__device__ float g_t1   [(size_t)B_ * PH_ * M_];
__device__ float g_pe   [(size_t)B_ * DIM_ * M_];
__device__ float g_h    [(size_t)B_ * AH_ * M_];       // h: [B][AH][M]  (c-major)
__device__ float g_agg  [(size_t)B_ * DIM_ * N_];
__device__ float g_part [(size_t)B_ * 512 * AH_ * 2];
__device__ float g_partp[(size_t)PH_ * 512 * 2];
__device__ float g_Wuq  [AH_ * C_];
__device__ float g_Wvk  [AH_ * C_];
__device__ float g_bias1[AH_];
__device__ float g_scp  [PH_];
__device__ float g_shp  [PH_];
__device__ float g_sca  [AH_];
__device__ float g_sha  [AH_];
// fp16 image of att_w2: 16 K-chunks x 32KB = 512KB
__device__ unsigned int g_w2img[16 * 32768 / 4];
// bf16 hi/lo image of Wmid = concat(att_w1@pos_w2, pos_w2): 10 chunks x 32KB
__device__ unsigned int g_wmidimg[10 * 32768 / 4];
__device__ unsigned int g_wuqimg[8 * 65536 / 4];   // 8 c-chunks x 64KB (bf16 hi/lo)
__device__ unsigned int g_wvkimg[8 * 65536 / 4];

// ---------------- helpers ---------------------------------------------------
__device__ __forceinline__ uint32_t smem_u32(const void* p) {
    uint32_t a;
    asm("{ .reg .u64 t; cvta.to.shared.u64 t, %1; cvt.u32.u64 %0, t; }" : "=r"(a) : "l"(p));
    return a;
}
#define SWZ128(b) ((b) ^ (((b) >> 3) & 0x70))
__device__ __forceinline__ uint32_t pack_bf16(float a, float b) {
    __nv_bfloat16 ha = __float2bfloat16(a), hb = __float2bfloat16(b);
    return (uint32_t)__bfloat16_as_ushort(ha) |
           ((uint32_t)__bfloat16_as_ushort(hb) << 16);
}
__device__ __forceinline__ uint32_t pack_h2(float a, float b) {
    __half2 t = __floats2half2_rn(a, b);
    return *reinterpret_cast<uint32_t*>(&t);
}
__device__ __forceinline__ void ldm_x4(uint32_t* r, uint32_t addr) {
    asm volatile("ldmatrix.sync.aligned.m8n8.x4.shared.b16 {%0,%1,%2,%3}, [%4];"
        : "=r"(r[0]), "=r"(r[1]), "=r"(r[2]), "=r"(r[3]) : "r"(addr));
}
__device__ __forceinline__ void mma16816(float* d, const uint32_t* a, const uint32_t* b) {
    asm volatile(
        "mma.sync.aligned.m16n8k16.row.col.f32.bf16.bf16.f32 "
        "{%0,%1,%2,%3}, {%4,%5,%6,%7}, {%8,%9}, {%0,%1,%2,%3};"
        : "+f"(d[0]), "+f"(d[1]), "+f"(d[2]), "+f"(d[3])
        : "r"(a[0]), "r"(a[1]), "r"(a[2]), "r"(a[3]), "r"(b[0]), "r"(b[1]));
}
__device__ __forceinline__ void mma16816h(float* d, const uint32_t* a, const uint32_t* b) {
    asm volatile(
        "mma.sync.aligned.m16n8k16.row.col.f32.f16.f16.f32 "
        "{%0,%1,%2,%3}, {%4,%5,%6,%7}, {%8,%9}, {%0,%1,%2,%3};"
        : "+f"(d[0]), "+f"(d[1]), "+f"(d[2]), "+f"(d[3])
        : "r"(a[0]), "r"(a[1]), "r"(a[2]), "r"(a[3]), "r"(b[0]), "r"(b[1]));
}
__device__ __forceinline__ void cp_async16(uint32_t dst, const void* src) {
    asm volatile("cp.async.cg.shared.global [%0], [%1], 16;" :: "r"(dst), "l"(src));
}
#define CP_COMMIT() asm volatile("cp.async.commit_group;" ::: "memory")
#define CP_WAIT0()  asm volatile("cp.async.wait_group 0;" ::: "memory")

// ---------------- concat ----------------------------------------------------
__global__ void concat_kernel(const float* __restrict__ key,
                              const float* __restrict__ query,
                              float* __restrict__ x) {
    size_t i = (size_t)blockIdx.x * blockDim.x + threadIdx.x;
    if (i >= (size_t)B_ * 2 * C_ * N_) return;
    int n = (int)(i % N_);
    int c = (int)((i / N_) % (2 * C_));
    int b = (int)(i / ((size_t)N_ * 2 * C_));
    float v;
    if (c < C_) v = key  [((size_t)b * C_ + c) * N_ + n];
    else        v = query[((size_t)b * C_ + (c - C_)) * N_ + n];
    x[i] = v;
}

// ---------------- KNN -------------------------------------------------------
__global__ void knn_kernel(const float* __restrict__ pos, int* __restrict__ idx) {
    const int b = blockIdx.y;
    const int n = blockIdx.x * blockDim.x + threadIdx.x;
    const float* p = pos + (size_t)b * 3 * N_;
    const float qx = p[n], qy = p[N_ + n], qz = p[2 * N_ + n];
    const float qs = qx * qx + qy * qy + qz * qz;
    float bd[K_]; int bi[K_];
#pragma unroll
    for (int j = 0; j < K_; j++) { bd[j] = 3.4e38f; bi[j] = 0; }
    __shared__ float sx[512], sy[512], sz[512], ss[512];
    for (int t0 = 0; t0 < N_; t0 += 512) {
        __syncthreads();
        for (int i = threadIdx.x; i < 512; i += blockDim.x) {
            float x = p[t0 + i], y = p[N_ + t0 + i], z = p[2 * N_ + t0 + i];
            sx[i] = x; sy[i] = y; sz[i] = z; ss[i] = x * x + y * y + z * z;
        }
        __syncthreads();
        for (int i = 0; i < 512; i++) {
            float d = qs + ss[i] - 2.0f * (qx * sx[i] + qy * sy[i] + qz * sz[i]);
            if (d < bd[K_ - 1]) {
                int j = K_ - 1;
                while (j > 0 && d < bd[j - 1]) { bd[j] = bd[j - 1]; bi[j] = bi[j - 1]; j--; }
                bd[j] = d; bi[j] = t0 + i;
            }
        }
    }
    int* op = idx + ((size_t)b * N_ + n) * K_;
#pragma unroll
    for (int j = 0; j < K_; j++) op[j] = bi[j];
}

// ---------------- precompute small products ---------------------------------
__global__ void smallmm_kernel(const float* __restrict__ A, const float* __restrict__ Bm,
                               float* __restrict__ Cc, int O, int Id, int J, int tr) {
    int t = blockIdx.x * 256 + threadIdx.x;
    if (t >= O * J) return;
    int o = t / J, j = t % J;
    float s = 0.0f;
    for (int d = 0; d < Id; d++) s += A[o * Id + d] * Bm[d * J + j];
    if (tr) Cc[j * O + o] = s; else Cc[o * J + j] = s;
}
__global__ void bias1_kernel(const float* __restrict__ w1, const float* __restrict__ bq,
                             const float* __restrict__ bk, const float* __restrict__ pb2,
                             const float* __restrict__ ab1, float* __restrict__ out) {
    int o = blockIdx.x * 256 + threadIdx.x;
    if (o >= AH_) return;
    float s = ab1[o];
    for (int d = 0; d < DIM_; d++) s += w1[o * DIM_ + d] * (bq[d] - bk[d] + pb2[d]);
    out[o] = s;
}
// v [B][AH][N] -> v_t [B][N][AH]
__global__ void transpose_bt(const float* __restrict__ src, float* __restrict__ dst) {
    __shared__ float tile[32][33];
    int b = blockIdx.z;
    int c0 = blockIdx.y * 32, n0 = blockIdx.x * 32;
    int tx = threadIdx.x, ty = threadIdx.y;
    const float* s = src + ((size_t)b * AH_ + c0) * N_ + n0;
#pragma unroll
    for (int i = 0; i < 32; i += 8) tile[ty + i][tx] = s[(size_t)(ty + i) * N_ + tx];
    __syncthreads();
    float* d = dst + ((size_t)b * N_ + n0) * AH_ + c0;
#pragma unroll
    for (int i = 0; i < 32; i += 8) d[(size_t)(ty + i) * AH_ + tx] = tile[tx][ty + i];
}

// ---------------- att_w2 -> pre-swizzled fp16 image --------------------------
__global__ void prep_w2_kernel(const float* __restrict__ w2, unsigned int* __restrict__ img) {
    int t = blockIdx.x * 256 + threadIdx.x;   // 65536 = 256 c * 256 k4
    if (t >= 256 * 256) return;
    int c = t >> 8, k4 = t & 255;
    int k = k4 * 4;
    int q = k >> 6, kl = k & 63;
    const float* src = w2 + (size_t)c * AH_ + k;
    uint32_t off = SWZ128((uint32_t)((c >> 3) * 1024 + (c & 7) * 128 + kl * 2));
    char* base = (char*)img + (size_t)q * 32768;
    *(uint2*)(base + off) = make_uint2(pack_h2(src[0], src[1]), pack_h2(src[2], src[3]));
}

// ---------------- Wmid -> pre-swizzled bf16 hi/lo image ----------------------
__global__ void prep_wmid_kernel(const float* __restrict__ att_w1,
                                 const float* __restrict__ pos_w2,
                                 unsigned int* __restrict__ img) {
    int t = blockIdx.x * 256 + threadIdx.x;
    if (t >= 1280 * 16) return;
    int c = t >> 4, k4 = t & 15;
    float f[4];
    if (c < AH_) {
#pragma unroll 4
        for (int kk = 0; kk < 4; kk++) {
            float s = 0.0f;
            for (int d = 0; d < DIM_; d++)
                s += att_w1[(size_t)c * DIM_ + d] * pos_w2[d * PH_ + k4 * 4 + kk];
            f[kk] = s;
        }
    } else {
#pragma unroll
        for (int kk = 0; kk < 4; kk++) f[kk] = pos_w2[(c - AH_) * PH_ + k4 * 4 + kk];
    }
    float r[4];
#pragma unroll
    for (int kk = 0; kk < 4; kk++)
        r[kk] = f[kk] - __bfloat162float(__float2bfloat16(f[kk]));
    int ct = c >> 7, cl = c & 127;
    uint32_t off = (uint32_t)((cl >> 3) * 1024 + (cl & 7) * 128 +
                              ((k4 * 8) ^ ((cl & 7) << 4)));
    char* base = (char*)img + (size_t)ct * 32768;
    *(uint2*)(base + off) = make_uint2(pack_bf16(f[0], f[1]), pack_bf16(f[2], f[3]));
    *(uint2*)(base + 16384 + off) = make_uint2(pack_bf16(r[0], r[1]), pack_bf16(r[2], r[3]));
}

// ---------------- Wuq/Wvk [AH][C=128] -> image: 8 c-chunks x 64KB -------------
__global__ void prep_wuv_kernel(const float* __restrict__ W, unsigned int* __restrict__ img) {
    int t = blockIdx.x * 256 + threadIdx.x;     // 1024 c * 32 k4
    if (t >= AH_ * 32) return;
    int c = t >> 5, k4 = t & 31;
    int k = k4 * 4;
    int kc = k >> 6, kl = k & 63;
    const float* src = W + (size_t)c * C_ + k;
    float f[4], r[4];
#pragma unroll
    for (int i = 0; i < 4; i++) {
        f[i] = src[i];
        r[i] = f[i] - __bfloat162float(__float2bfloat16(f[i]));
    }
    int ct = c >> 7, cl = c & 127;
    uint32_t off = (uint32_t)((cl >> 3) * 1024 + (cl & 7) * 128 +
                              ((kl * 2) ^ ((cl & 7) << 4)));
    char* base = (char*)img + (size_t)ct * 65536 + (size_t)kc * 32768;
    *(uint2*)(base + off) = make_uint2(pack_bf16(f[0], f[1]), pack_bf16(f[2], f[3]));
    *(uint2*)(base + 16384 + off) = make_uint2(pack_bf16(r[0], r[1]), pack_bf16(r[2], r[3]));
}

// ---------------- generic fp32 SGEMM (small GEMMs) --------------------------
template <int FLAGS>
__global__ void sgemm_kernel(const float* __restrict__ W, const float* __restrict__ Xg,
                             const float* __restrict__ bias, float* __restrict__ outg,
                             const float* __restrict__ resg, int O, int I, int M) {
    const int b = blockIdx.z;
    const float* X = Xg + (size_t)b * I * M;
    float* out = outg + (size_t)b * O * M;
    const float* res = (FLAGS & 4) ? (resg + (size_t)b * O * M) : nullptr;
    __shared__ float Ws[8][132];
    __shared__ float Xs[8][128];
    const int tid = threadIdx.x;
    const int tx = tid & 15, ty = tid >> 4;
    const int o0 = blockIdx.y * 128, m0 = blockIdx.x * 128;
    const int wr = tid >> 1, wc = (tid & 1) * 4;
    const int xr = tid >> 5, xc = (tid & 31) * 4;
    float acc[8][8];
#pragma unroll
    for (int i = 0; i < 8; i++)
#pragma unroll
        for (int j = 0; j < 8; j++) acc[i][j] = 0.0f;
    for (int kt = 0; kt < I; kt += 8) {
        float4 wv = *(const float4*)&W[(size_t)(o0 + wr) * I + kt + wc];
        float4 xv = *(const float4*)&X[(size_t)(kt + xr) * M + m0 + xc];
        __syncthreads();
        Ws[wc + 0][wr] = wv.x; Ws[wc + 1][wr] = wv.y;
        Ws[wc + 2][wr] = wv.z; Ws[wc + 3][wr] = wv.w;
        *(float4*)&Xs[xr][xc] = xv;
        __syncthreads();
#pragma unroll
        for (int k = 0; k < 8; k++) {
            float a[8], bb[8];
            *(float4*)&a[0]  = *(const float4*)&Ws[k][ty * 8];
            *(float4*)&a[4]  = *(const float4*)&Ws[k][ty * 8 + 4];
            *(float4*)&bb[0] = *(const float4*)&Xs[k][tx * 8];
            *(float4*)&bb[4] = *(const float4*)&Xs[k][tx * 8 + 4];
#pragma unroll
            for (int i = 0; i < 8; i++)
#pragma unroll
                for (int j = 0; j < 8; j++) acc[i][j] += a[i] * bb[j];
        }
    }
#pragma unroll
    for (int i = 0; i < 8; i++) {
        const int o = o0 + ty * 8 + i;
        const float bv = bias[o];
        float* orow = out + (size_t)o * M + m0 + tx * 8;
        const float* rrow = (FLAGS & 4) ? (res + (size_t)o * M + m0 + tx * 8) : nullptr;
#pragma unroll
        for (int jj = 0; jj < 8; jj += 4) {
            float4 v;
            v.x = acc[i][jj + 0] + bv; v.y = acc[i][jj + 1] + bv;
            v.z = acc[i][jj + 2] + bv; v.w = acc[i][jj + 3] + bv;
            if (FLAGS & 1) { v.x = fmaxf(v.x, 0.f); v.y = fmaxf(v.y, 0.f);
                             v.z = fmaxf(v.z, 0.f); v.w = fmaxf(v.w, 0.f); }
            if (FLAGS & 2) { float4 old = *(float4*)&orow[jj];
                             v.x += old.x; v.y += old.y; v.z += old.z; v.w += old.w; }
            if (FLAGS & 4) { float4 r = *(const float4*)&rrow[jj];
                             v.x += r.x; v.y += r.y; v.z += r.z; v.w += r.w; }
            *(float4*)&orow[jj] = v;
        }
    }
}

// ---------------- pos_rel conv1 + BN partial stats ---------------------------
__global__ void posrel_kernel(const float* __restrict__ pos, const int* __restrict__ idx,
                              const float* __restrict__ w, const float* __restrict__ bias,
                              float* __restrict__ t1, float* __restrict__ part) {
    size_t i = (size_t)blockIdx.x * 256 + threadIdx.x;
    int k = (int)(i & 15);
    int n = (int)((i >> 4) & (N_ - 1));
    int c = (int)((i >> 16) & (PH_ - 1));
    int b = (int)(i >> 22);
    int m = idx[(((size_t)b * N_ + n) << 4) + k];
    const float* p = pos + (size_t)b * 3 * N_;
    float rx = p[n] - p[m];
    float ry = p[N_ + n] - p[N_ + m];
    float rz = p[2 * N_ + n] - p[2 * N_ + m];
    float val = w[c * 3] * rx + w[c * 3 + 1] * ry + w[c * 3 + 2] * rz + bias[c];
    t1[i] = val;
    __shared__ float ssum[256], ssq[256];
    ssum[threadIdx.x] = val; ssq[threadIdx.x] = val * val;
    __syncthreads();
    for (int st = 128; st > 0; st >>= 1) {
        if ((int)threadIdx.x < st) {
            ssum[threadIdx.x] += ssum[threadIdx.x + st];
            ssq[threadIdx.x]  += ssq[threadIdx.x + st];
        }
        __syncthreads();
    }
    if (threadIdx.x == 0) {
        int cb = (blockIdx.x >> 8) & (PH_ - 1);
        int bb = blockIdx.x >> 14;
        int sblk = blockIdx.x & 255;
        size_t o = ((size_t)cb * 512 + bb * 256 + sblk) * 2;
        part[o] = ssum[0]; part[o + 1] = ssq[0];
    }
}

// ---------------- BN finalize ------------------------------------------------
__global__ void finalize_stats(const float* __restrict__ part, int P, int ps, int cs,
                               const float* __restrict__ g, const float* __restrict__ be,
                               float* __restrict__ sc, float* __restrict__ sh, float cnt) {
    int c = blockIdx.x;
    double s = 0.0, q = 0.0;
    for (int p = threadIdx.x; p < P; p += blockDim.x) {
        size_t o = ((size_t)p * ps + (size_t)c * cs) * 2;
        s += (double)part[o]; q += (double)part[o + 1];
    }
    __shared__ double S[256], Q[256];
    S[threadIdx.x] = s; Q[threadIdx.x] = q;
    __syncthreads();
    for (int st = 128; st > 0; st >>= 1) {
        if ((int)threadIdx.x < st) {
            S[threadIdx.x] += S[threadIdx.x + st];
            Q[threadIdx.x] += Q[threadIdx.x + st];
        }
        __syncthreads();
    }
    if (threadIdx.x == 0) {
        double mean = S[0] / (double)cnt;
        double var  = Q[0] / (double)cnt - mean * mean;
        float scv = g[c] * (float)(1.0 / sqrt(var + 1e-5));
        sc[c] = scv;
        sh[c] = be[c] - (float)mean * scv;
    }
}

// ---------------- u/v GEMM on HMMA ------------------------------------------
#define UV_X     0
#define UV_W(s)  (65536 + (s) * 65536)
#define UV_SMEM  196608

__global__ __launch_bounds__(256, 1) void uv_hmma(
    const float* __restrict__ query, const float* __restrict__ key,
    const unsigned int* __restrict__ wuqimg, const unsigned int* __restrict__ wvkimg,
    float* __restrict__ ug, float* __restrict__ vg) {
    extern __shared__ char smc[];
    const uint32_t sb = smem_u32(smc);
    const int tid = threadIdx.x, lane = tid & 31, wid = tid >> 5;
    const int z = blockIdx.y;
    const int b = z & 1, which = z >> 1;
    const int n0 = blockIdx.x * 128;
    const float* X = (which == 0 ? query : key) + (size_t)b * C_ * N_;
    const unsigned int* wimg = (which == 0 ? wuqimg : wvkimg);
    float* out = (which == 0 ? ug : vg) + (size_t)b * AH_ * N_;
    const int warp_cg = wid >> 1;
    const int warp_mg = wid & 1;

    {
        const uint4* src = (const uint4*)wimg;
        uint32_t dst = sb + UV_W(0);
#pragma unroll
        for (int it = 0; it < 16; it++)
            cp_async16(dst + (it * 256 + tid) * 16, src + it * 256 + tid);
        CP_COMMIT();
    }
    {
        char* xbase = smc + UV_X;
        int m = tid & 127, khalf = tid >> 7;
#pragma unroll
        for (int k2 = 0; k2 < 32; k2++) {
            int k = khalf * 64 + k2 * 2;
            int kl = k & 63;
            float x0 = X[(size_t)k * N_ + n0 + m];
            float x1 = X[(size_t)(k + 1) * N_ + n0 + m];
            float l0 = x0 - __bfloat162float(__float2bfloat16(x0));
            float l1 = x1 - __bfloat162float(__float2bfloat16(x1));
            uint32_t off = (uint32_t)((m >> 3) * 1024 + (m & 7) * 128 +
                                      ((kl * 2) ^ ((m & 7) << 4)));
            char* dst = xbase + khalf * 32768;
            *(uint32_t*)(dst + off) = pack_bf16(x0, x1);
            *(uint32_t*)(dst + 16384 + off) = pack_bf16(l0, l1);
        }
    }
    CP_WAIT0();
    __syncthreads();

    const int g = lane >> 3, lr = lane & 7;
    const int wrow = warp_cg * 32 + (g & 1) * 8 + lr;
    const int xrow = warp_mg * 64 + (g >> 1) * 8 + lr;
    const int wkb0 = (g >> 1) * 16;
    const int xkb0 = (g & 1) * 16;
    const uint32_t sX = sb + UV_X;

    for (int ct = 0; ct < 8; ct++) {
        const int s = ct & 1;
        if (ct + 1 < 8) {
            const uint4* src = (const uint4*)wimg + (ct + 1) * 4096;
            uint32_t dst = sb + UV_W(s ^ 1);
#pragma unroll
            for (int it = 0; it < 16; it++)
                cp_async16(dst + (it * 256 + tid) * 16, src + it * 256 + tid);
            CP_COMMIT();
        }
        const uint32_t sW = sb + UV_W(s);
        float acc[2][8][4];
#pragma unroll
        for (int a = 0; a < 2; a++)
#pragma unroll
            for (int q = 0; q < 8; q++)
#pragma unroll
                for (int j = 0; j < 4; j++) acc[a][q][j] = 0.0f;
#pragma unroll
        for (int kc = 0; kc < 2; kc++) {
#pragma unroll
            for (int ks = 0; ks < 4; ks++) {
                uint32_t Whi[2][4], Wlo[2][4], Xhf[4][4], Xlf[4][4];
#pragma unroll
                for (int ct2 = 0; ct2 < 2; ct2++) {
                    int cr = wrow + ct2 * 16;
                    uint32_t ro = (uint32_t)((cr >> 3) * 1024 + (cr & 7) * 128);
                    uint32_t kb = (uint32_t)((ks * 32 + wkb0) ^ ((cr & 7) << 4));
                    ldm_x4(Whi[ct2], sW + kc * 32768 + ro + kb);
                    ldm_x4(Wlo[ct2], sW + kc * 32768 + 16384 + ro + kb);
                }
#pragma unroll
                for (int np = 0; np < 4; np++) {
                    int mr = xrow + np * 16;
                    uint32_t ro = (uint32_t)((mr >> 3) * 1024 + (mr & 7) * 128);
                    uint32_t kb = (uint32_t)((ks * 32 + xkb0) ^ ((mr & 7) << 4));
                    ldm_x4(Xhf[np], sX + kc * 32768 + ro + kb);
                    ldm_x4(Xlf[np], sX + kc * 32768 + 16384 + ro + kb);
                }
#pragma unroll
                for (int ct2 = 0; ct2 < 2; ct2++)
#pragma unroll
                    for (int np = 0; np < 4; np++) {
                        mma16816(acc[ct2][np * 2],     Whi[ct2], &Xhf[np][0]);
                        mma16816(acc[ct2][np * 2],     Wlo[ct2], &Xhf[np][0]);
                        mma16816(acc[ct2][np * 2],     Whi[ct2], &Xlf[np][0]);
                        mma16816(acc[ct2][np * 2 + 1], Whi[ct2], &Xhf[np][2]);
                        mma16816(acc[ct2][np * 2 + 1], Wlo[ct2], &Xhf[np][2]);
                        mma16816(acc[ct2][np * 2 + 1], Whi[ct2], &Xlf[np][2]);
                    }
            }
        }
#pragma unroll
        for (int ct2 = 0; ct2 < 2; ct2++) {
#pragma unroll
            for (int j = 0; j < 4; j++) {
                int c_g = ct * 128 + warp_cg * 32 + ct2 * 16 + (lane >> 2) + (j >> 1) * 8;
                float* orow = out + (size_t)c_g * N_ + n0;
#pragma unroll
                for (int q = 0; q < 8; q++) {
                    int m_loc = warp_mg * 64 + q * 8 + (lane & 3) * 2 + (j & 1);
                    orow[m_loc] = acc[ct2][q][j];
                }
            }
        }
        CP_WAIT0();
        __syncthreads();
    }
}

// ---------------- fused mid on HMMA, smem-staged gather ----------------------
#define FM_XHI   0
#define FM_XLO   16384
#define FM_W(s)  (32768 + (s) * 32768)
#define FM_VG    98304
#define FM_U     164352
#define FM_RED   168960
#define FM_SIDX  171008
#define FM_SMEM  171520

__global__ __launch_bounds__(256, 1) void fused_mid_hmma(
    const float* __restrict__ t1, const float* __restrict__ psc,
    const float* __restrict__ psh, const unsigned int* __restrict__ wimg,
    const float* __restrict__ bias1, const float* __restrict__ pos_b2,
    const float* __restrict__ u, const float* __restrict__ vt,
    const int* __restrict__ idx, float* __restrict__ h,
    float* __restrict__ pe, float* __restrict__ part) {
    extern __shared__ char smc[];
    const uint32_t sb = smem_u32(smc);
    const int tid = threadIdx.x, lane = tid & 31, wid = tid >> 5;
    const int b = blockIdx.y, m0 = blockIdx.x * 128;
    const int warp_cg = wid >> 1;
    const int warp_mg = wid & 1;

    int* sidx = (int*)(smc + FM_SIDX);
    float* vgs = (float*)(smc + FM_VG);
    float* us  = (float*)(smc + FM_U);
    float* redS = (float*)(smc + FM_RED);
    float* redQ = redS + 256;

    if (tid < 128) sidx[tid] = idx[((size_t)b * N_ + (m0 >> 4)) * K_ + tid];

    {
        const uint4* src = (const uint4*)wimg;
        uint32_t dst = sb + FM_W(0);
#pragma unroll
        for (int it = 0; it < 8; it++)
            cp_async16(dst + (it * 256 + tid) * 16, src + it * 256 + tid);
        CP_COMMIT();
    }
    {
        const float* tb = t1 + (size_t)b * PH_ * M_ + m0;
        char* xhi = smc + FM_XHI;
        char* xlo = smc + FM_XLO;
        int m = tid & 127, khalf = tid >> 7;
#pragma unroll
        for (int k2 = 0; k2 < 16; k2++) {
            int k = khalf * 32 + k2 * 2;
            float x0 = tb[(size_t)k * M_ + m];
            float x1 = tb[(size_t)(k + 1) * M_ + m];
            x0 = fmaxf(x0 * psc[k] + psh[k], 0.f);
            x1 = fmaxf(x1 * psc[k + 1] + psh[k + 1], 0.f);
            float l0 = x0 - __bfloat162float(__float2bfloat16(x0));
            float l1 = x1 - __bfloat162float(__float2bfloat16(x1));
            uint32_t off = (uint32_t)((m >> 3) * 1024 + (m & 7) * 128 +
                                      ((k * 2) ^ ((m & 7) << 4)));
            *(uint32_t*)(xhi + off) = pack_bf16(x0, x1);
            *(uint32_t*)(xlo + off) = pack_bf16(l0, l1);
        }
    }
    CP_WAIT0();
    __syncthreads();

    const int g = lane >> 3, lr = lane & 7;
    const int wrow = warp_cg * 32 + (g & 1) * 8 + lr;
    const int xrow = warp_mg * 64 + (g >> 1) * 8 + lr;
    const int wkb0 = (g >> 1) * 16;
    const int xkb0 = (g & 1) * 16;
    const uint32_t sX = sb + FM_XHI;
    const float* vtb = vt + (size_t)b * N_ * AH_;
    const int n0 = m0 >> 4;

    for (int ct = 0; ct < 10; ct++) {
        const int s = ct & 1;
        if (ct + 1 < 10) {
            const uint4* src = (const uint4*)wimg + (ct + 1) * 2048;
            uint32_t dst = sb + FM_W(s ^ 1);
#pragma unroll
            for (int it = 0; it < 8; it++)
                cp_async16(dst + (it * 256 + tid) * 16, src + it * 256 + tid);
            CP_COMMIT();
        }
        if (ct < 8) {
#pragma unroll
            for (int jj = 0; jj < 16; jj++) {
                int j = wid * 16 + jj;
                const float* row = vtb + (size_t)sidx[j] * AH_ + ct * 128;
#pragma unroll
                for (int cc = 0; cc < 4; cc++) {
                    int c = cc * 32 + lane;
                    vgs[c * 129 + j] = row[c];
                }
            }
#pragma unroll
            for (int it = 0; it < 4; it++) {
                int e = it * 256 + tid;
                int c = e >> 3, nn = e & 7;
                us[c * 9 + nn] = u[((size_t)b * AH_ + ct * 128 + c) * N_ + n0 + nn]
                               + bias1[ct * 128 + c];
            }
        }
        const uint32_t sW = sb + FM_W(s);
        float acc[2][8][4];
#pragma unroll
        for (int a = 0; a < 2; a++)
#pragma unroll
            for (int q = 0; q < 8; q++)
#pragma unroll
                for (int j = 0; j < 4; j++) acc[a][q][j] = 0.0f;
#pragma unroll
        for (int ks = 0; ks < 4; ks++) {
            uint32_t Whi[2][4], Wlo[2][4], Xhf[4][4], Xlf[4][4];
#pragma unroll
            for (int ct2 = 0; ct2 < 2; ct2++) {
                int cr = wrow + ct2 * 16;
                uint32_t ro = (uint32_t)((cr >> 3) * 1024 + (cr & 7) * 128);
                uint32_t kb = (uint32_t)((ks * 32 + wkb0) ^ ((cr & 7) << 4));
                ldm_x4(Whi[ct2], sW + ro + kb);
                ldm_x4(Wlo[ct2], sW + 16384 + ro + kb);
            }
#pragma unroll
            for (int np = 0; np < 4; np++) {
                int mr = xrow + np * 16;
                uint32_t ro = (uint32_t)((mr >> 3) * 1024 + (mr & 7) * 128);
                uint32_t kb = (uint32_t)((ks * 32 + xkb0) ^ ((mr & 7) << 4));
                ldm_x4(Xhf[np], sX + ro + kb);
                ldm_x4(Xlf[np], sX + 16384 + ro + kb);
            }
#pragma unroll
            for (int ct2 = 0; ct2 < 2; ct2++)
#pragma unroll
                for (int np = 0; np < 4; np++) {
                    mma16816(acc[ct2][np * 2],     Whi[ct2], &Xhf[np][0]);
                    mma16816(acc[ct2][np * 2],     Wlo[ct2], &Xhf[np][0]);
                    mma16816(acc[ct2][np * 2],     Whi[ct2], &Xlf[np][0]);
                    mma16816(acc[ct2][np * 2 + 1], Whi[ct2], &Xhf[np][2]);
                    mma16816(acc[ct2][np * 2 + 1], Wlo[ct2], &Xhf[np][2]);
                    mma16816(acc[ct2][np * 2 + 1], Whi[ct2], &Xlf[np][2]);
                }
        }
        if (ct < 8) {
            __syncthreads();
            float sS[2][2], sQ[2][2];
#pragma unroll
            for (int a = 0; a < 2; a++) { sS[a][0] = sS[a][1] = 0.f; sQ[a][0] = sQ[a][1] = 0.f; }
#pragma unroll
            for (int ct2 = 0; ct2 < 2; ct2++) {
#pragma unroll
                for (int j = 0; j < 4; j++) {
                    int rh = j >> 1;
                    int c_loc = warp_cg * 32 + ct2 * 16 + (lane >> 2) + rh * 8;
                    int c_g = ct * 128 + c_loc;
                    float* hrow = h + ((size_t)b * AH_ + c_g) * M_ + m0;
#pragma unroll
                    for (int q = 0; q < 8; q++) {
                        int m_loc = warp_mg * 64 + q * 8 + (lane & 3) * 2 + (j & 1);
                        float val = acc[ct2][q][j] + us[c_loc * 9 + (m_loc >> 4)]
                                  - vgs[c_loc * 129 + m_loc];
                        hrow[m_loc] = val;
                        sS[ct2][rh] += val; sQ[ct2][rh] += val * val;
                    }
                }
            }
#pragma unroll
            for (int ct2 = 0; ct2 < 2; ct2++)
#pragma unroll
                for (int rh = 0; rh < 2; rh++) {
                    float s1 = sS[ct2][rh], q1 = sQ[ct2][rh];
                    s1 += __shfl_xor_sync(0xffffffffu, s1, 1);
                    s1 += __shfl_xor_sync(0xffffffffu, s1, 2);
                    q1 += __shfl_xor_sync(0xffffffffu, q1, 1);
                    q1 += __shfl_xor_sync(0xffffffffu, q1, 2);
                    if ((lane & 3) == 0) {
                        int c_loc = warp_cg * 32 + ct2 * 16 + (lane >> 2) + rh * 8;
                        redS[c_loc * 2 + warp_mg] = s1;
                        redQ[c_loc * 2 + warp_mg] = q1;
                    }
                }
            __syncthreads();
            if (tid < 128) {
                float ss = redS[tid * 2] + redS[tid * 2 + 1];
                float qq = redQ[tid * 2] + redQ[tid * 2 + 1];
                size_t po = (((size_t)b * 512 + blockIdx.x) * AH_ + ct * 128 + tid) * 2;
                part[po] = ss; part[po + 1] = qq;
            }
        } else {
#pragma unroll
            for (int ct2 = 0; ct2 < 2; ct2++) {
#pragma unroll
                for (int j = 0; j < 4; j++) {
                    int c_pe = (ct - 8) * 128 + warp_cg * 32 + ct2 * 16 + (lane >> 2) + (j >> 1) * 8;
                    float bv = pos_b2[c_pe];
                    float* prow = pe + ((size_t)b * DIM_ + c_pe) * M_ + m0;
#pragma unroll
                    for (int q = 0; q < 8; q++) {
                        int m_loc = warp_mg * 64 + q * 8 + (lane & 3) * 2 + (j & 1);
                        prow[m_loc] = acc[ct2][q][j] + bv;
                    }
                }
            }
        }
        CP_WAIT0();
        __syncthreads();
    }
}

// ---------------- attn GEMM2 (fp16 HMMA, cp.async pipelined) -----------------
// A fp16 2x16K (0,16K) | B fp16 2x32K (32K,64K) | staging 32K (96K) = 128K
#define A_OFF(s)  ((s) * 16384)
#define B_OFF(s)  (32768 + (s) * 32768)
#define STG_OFF   98304
#define SMEM_ATT2 135168   // epilogue pes region needs 135168

__device__ __forceinline__ void attn2_cpasync(uint32_t sb, int s, int cq,
                                              const float* hbase, const uint4* w2img,
                                              int tid) {
    const uint4* src = w2img + (size_t)cq * 2048;
    uint32_t bdst = sb + B_OFF(s);
#pragma unroll
    for (int it = 0; it < 8; it++) {
        int i = it * 256 + tid;
        cp_async16(bdst + i * 16, src + i);
    }
#pragma unroll
    for (int it = 0; it < 8; it++) {
        int ch = it * 256 + tid;
        int krow = ch >> 5;
        const float* srcr = hbase + (size_t)(cq * 64 + krow) * M_ + (ch & 31) * 4;
        cp_async16(sb + STG_OFF + krow * 512 + (ch & 31) * 16, srcr);
    }
}

__device__ __forceinline__ void attn2_convert(char* smc, int s, int cq,
                                              const float* __restrict__ scale,
                                              const float* __restrict__ shift,
                                              int wid, int lane) {
    const float* stg = (const float*)(smc + STG_OFF);
    char* dst = smc + A_OFF(s);
#pragma unroll
    for (int g2 = 0; g2 < 2; g2++) {
        int base_k = wid * 8 + g2 * 4;
        float4 v[4];
#pragma unroll
        for (int r = 0; r < 4; r++)
            v[r] = *(const float4*)&stg[(base_k + r) * 128 + lane * 4];
        float X[4][4];
#pragma unroll
        for (int r = 0; r < 4; r++) {
            float sc = scale[cq * 64 + base_k + r];
            float sh = shift[cq * 64 + base_k + r];
            float xv[4] = {v[r].x, v[r].y, v[r].z, v[r].w};
#pragma unroll
            for (int mm = 0; mm < 4; mm++)
                X[mm][r] = fmaxf(xv[mm] * sc + sh, 0.f);
        }
#pragma unroll
        for (int mm = 0; mm < 4; mm++) {
            int m = lane * 4 + mm;
            uint32_t off = (uint32_t)((m >> 3) * 1024 + (m & 7) * 128 +
                                      ((base_k * 2) ^ ((m & 7) << 4)));
            *(uint2*)(dst + off) = make_uint2(pack_h2(X[mm][0], X[mm][1]),
                                              pack_h2(X[mm][2], X[mm][3]));
        }
    }
}

__global__ __launch_bounds__(256, 1) void attn2_hmma_kernel(
    const uint4* __restrict__ w2img, const float* __restrict__ h,
    const float* __restrict__ scale, const float* __restrict__ shift,
    const float* __restrict__ pe, const float* __restrict__ vf,
    float* __restrict__ agg) {
    extern __shared__ char smc[];
    const uint32_t sb = smem_u32(smc);
    const int tid = threadIdx.x, lane = tid & 31, wid = tid >> 5;
    const int b = blockIdx.y, m0 = blockIdx.x * 128;
    const int warp_m = wid >> 2, warp_c = wid & 3;

    const float* hbase = h + (size_t)b * AH_ * M_ + m0;

    float acc[4][8][4];
#pragma unroll
    for (int mt = 0; mt < 4; mt++)
#pragma unroll
        for (int nt = 0; nt < 8; nt++)
#pragma unroll
            for (int j = 0; j < 4; j++) acc[mt][nt][j] = 0.0f;

    const int g = lane >> 3, lr = lane & 7;
    const int amr  = warp_m * 64 + (g & 1) * 8 + lr;
    const int bcr  = warp_c * 64 + (g >> 1) * 8 + lr;
    const int akb0 = (g >> 1) * 16;
    const int bkb0 = (g & 1) * 16;

    attn2_cpasync(sb, 0, 0, hbase, w2img, tid);
    CP_COMMIT();
    CP_WAIT0();
    __syncthreads();
    attn2_convert(smc, 0, 0, scale, shift, wid, lane);
    __syncthreads();

    for (int cq = 0; cq < 16; cq++) {
        const int s = cq & 1;
        if (cq + 1 < 16) {
            attn2_cpasync(sb, s ^ 1, cq + 1, hbase, w2img, tid);
            CP_COMMIT();
        }
        const uint32_t sA = sb + A_OFF(s);
        const uint32_t sB = sb + B_OFF(s);
#pragma unroll
        for (int ks = 0; ks < 4; ks++) {
            uint32_t Af[4][4], Bf[4][4];
#pragma unroll
            for (int mt = 0; mt < 4; mt++) {
                int m = amr + mt * 16;
                uint32_t ro = (uint32_t)((m >> 3) * 1024 + (m & 7) * 128);
                uint32_t kb = (uint32_t)((ks * 32 + akb0) ^ ((m & 7) << 4));
                ldm_x4(Af[mt], sA + ro + kb);
            }
#pragma unroll
            for (int np = 0; np < 4; np++) {
                int c = bcr + np * 16;
                uint32_t ro = (uint32_t)((c >> 3) * 1024 + (c & 7) * 128);
                uint32_t kb = (uint32_t)((ks * 32 + bkb0) ^ ((c & 7) << 4));
                ldm_x4(Bf[np], sB + ro + kb);
            }
#pragma unroll
            for (int mt = 0; mt < 4; mt++)
#pragma unroll
                for (int np = 0; np < 4; np++) {
                    mma16816h(acc[mt][np * 2],     Af[mt], &Bf[np][0]);
                    mma16816h(acc[mt][np * 2 + 1], Af[mt], &Bf[np][2]);
                }
        }
        if (cq + 1 < 16) {
            CP_WAIT0();
            __syncthreads();
            attn2_convert(smc, s ^ 1, cq + 1, scale, shift, wid, lane);
            __syncthreads();
        }
    }
    __syncthreads();

    // epilogue: stage pe tile (c=256 rows x m=128 cols, stride 132)
    float* pes = (float*)smc;
    for (int i = tid; i < 256 * 32; i += 256) {
        int row = i >> 5, q = i & 31;
        float4 v = *(const float4*)(pe + ((size_t)(b * DIM_ + row)) * M_ + m0 + q * 4);
        *(float4*)&pes[row * 132 + q * 4] = v;
    }
    __syncthreads();

#pragma unroll
    for (int mt = 0; mt < 4; mt++) {
        const int mbase = warp_m * 64 + mt * 16;
        const int n = (m0 + mbase) >> 4;
        const int r = lane >> 2;
#pragma unroll
        for (int nt = 0; nt < 8; nt++) {
#pragma unroll
            for (int j = 0; j < 2; j++) {
                int c = warp_c * 64 + nt * 8 + (lane & 3) * 2 + j;
                float v0 = acc[mt][nt][j], v1 = acc[mt][nt][2 + j];
                float mx = fmaxf(v0, v1);
                mx = fmaxf(mx, __shfl_xor_sync(0xffffffffu, mx, 4));
                mx = fmaxf(mx, __shfl_xor_sync(0xffffffffu, mx, 8));
                mx = fmaxf(mx, __shfl_xor_sync(0xffffffffu, mx, 16));
                float e0 = __expf(v0 - mx), e1 = __expf(v1 - mx);
                float se = e0 + e1;
                se += __shfl_xor_sync(0xffffffffu, se, 4);
                se += __shfl_xor_sync(0xffffffffu, se, 8);
                se += __shfl_xor_sync(0xffffffffu, se, 16);
                float p0 = pes[c * 132 + mbase + r];
                float p1 = pes[c * 132 + mbase + r + 8];
                float t = e0 * p0 + e1 * p1;
                t += __shfl_xor_sync(0xffffffffu, t, 4);
                t += __shfl_xor_sync(0xffffffffu, t, 8);
                t += __shfl_xor_sync(0xffffffffu, t, 16);
                if (r == 0) {
                    size_t o = ((size_t)(b * DIM_ + c)) * N_ + n;
                    agg[o] = vf[o] + t / se;
                }
            }
        }
    }
}

// ---------------- launch ----------------------------------------------------
extern "C" void kernel_launch(void* const* d_in, const int* in_sizes, int n_in,
                              void* d_out, int out_size) {
    const float* pos     = (const float*)d_in[0];
    const float* key     = (const float*)d_in[1];
    const float* query   = (const float*)d_in[2];
    const float* mlpv_w1 = (const float*)d_in[3];
    const float* mlpv_b1 = (const float*)d_in[4];
    const float* mlpv_w2 = (const float*)d_in[5];
    const float* mlpv_b2 = (const float*)d_in[6];
    const float* mlpv_ws = (const float*)d_in[7];
    const float* mlpv_bs = (const float*)d_in[8];
    const float* wk      = (const float*)d_in[9];
    const float* bk      = (const float*)d_in[10];
    const float* wq      = (const float*)d_in[11];
    const float* bq      = (const float*)d_in[12];
    const float* wv      = (const float*)d_in[13];
    const float* bv      = (const float*)d_in[14];
    const float* pos_w1  = (const float*)d_in[15];
    const float* pos_b1  = (const float*)d_in[16];
    const float* pos_g1  = (const float*)d_in[17];
    const float* pos_be1 = (const float*)d_in[18];
    const float* pos_w2  = (const float*)d_in[19];
    const float* pos_b2  = (const float*)d_in[20];
    const float* att_w1  = (const float*)d_in[21];
    const float* att_b1  = (const float*)d_in[22];
    const float* att_g1  = (const float*)d_in[23];
    const float* att_be1 = (const float*)d_in[24];
    const float* att_w2  = (const float*)d_in[25];
    const float* we      = (const float*)d_in[27];
    const float* be      = (const float*)d_in[28];
    float* out = (float*)d_out;

    void* p;
#define GETP(sym, var) cudaGetSymbolAddress(&p, sym); float* var = (float*)p;
    GETP(g_x, x_)       GETP(g_t, t_)       GETP(g_value, val)
    GETP(g_vf, vf_)     GETP(g_u, u_)       GETP(g_v, v_)
    GETP(g_vt, vt_)
    GETP(g_t1, t1_)     GETP(g_pe, pe_)     GETP(g_h, h_)
    GETP(g_agg, agg)    GETP(g_part, part)  GETP(g_partp, partp)
    GETP(g_Wuq, Wuq)    GETP(g_Wvk, Wvk)    GETP(g_bias1, bias1)
    GETP(g_scp, scp)    GETP(g_shp, shp)    GETP(g_sca, sca)
    GETP(g_sha, sha)
#undef GETP
    cudaGetSymbolAddress(&p, g_idx);      int* idx = (int*)p;
    cudaGetSymbolAddress(&p, g_w2img);    unsigned int* w2img = (unsigned int*)p;
    cudaGetSymbolAddress(&p, g_wmidimg);  unsigned int* wmidimg = (unsigned int*)p;
    cudaGetSymbolAddress(&p, g_wuqimg);   unsigned int* wuqimg = (unsigned int*)p;
    cudaGetSymbolAddress(&p, g_wvkimg);   unsigned int* wvkimg = (unsigned int*)p;

    // --- precompute folded weights + weight images ---
    smallmm_kernel<<<(AH_ * C_ + 255) / 256, 256>>>(att_w1, wq, Wuq, AH_, DIM_, C_, 0);
    smallmm_kernel<<<(AH_ * C_ + 255) / 256, 256>>>(att_w1, wk, Wvk, AH_, DIM_, C_, 0);
    bias1_kernel<<<(AH_ + 255) / 256, 256>>>(att_w1, bq, bk, pos_b2, att_b1, bias1);
    prep_w2_kernel<<<(256 * 256) / 256, 256>>>(att_w2, w2img);
    prep_wmid_kernel<<<(1280 * 16 + 255) / 256, 256>>>(att_w1, pos_w2, wmidimg);
    prep_wuv_kernel<<<(AH_ * 32 + 255) / 256, 256>>>(Wuq, wuqimg);
    prep_wuv_kernel<<<(AH_ * 32 + 255) / 256, 256>>>(Wvk, wvkimg);

    // --- front end ---
    concat_kernel<<<(unsigned)(((size_t)B_ * 2 * C_ * N_ + 255) / 256), 256>>>(key, query, x_);
    knn_kernel<<<dim3(N_ / 256, B_), 256>>>(pos, idx);
    sgemm_kernel<1><<<dim3(N_ / 128, C_ / 128, B_), 256>>>(mlpv_w1, x_, mlpv_b1, t_, nullptr, C_, 2 * C_, N_);
    sgemm_kernel<0><<<dim3(N_ / 128, C_ / 128, B_), 256>>>(mlpv_w2, t_, mlpv_b2, val, nullptr, C_, C_, N_);
    sgemm_kernel<2><<<dim3(N_ / 128, C_ / 128, B_), 256>>>(mlpv_ws, x_, mlpv_bs, val, nullptr, C_, 2 * C_, N_);
    sgemm_kernel<0><<<dim3(N_ / 128, DIM_ / 128, B_), 256>>>(wv, val, bv, vf_, nullptr, DIM_, C_, N_);

    // --- u/v on HMMA ---
    cudaFuncSetAttribute(uv_hmma, cudaFuncAttributeMaxDynamicSharedMemorySize, UV_SMEM);
    uv_hmma<<<dim3(N_ / 128, 4), 256, UV_SMEM>>>(query, key, wuqimg, wvkimg, u_, v_);
    transpose_bt<<<dim3(N_ / 32, AH_ / 32, B_), dim3(32, 8)>>>(v_, vt_);

    // --- pos_rel conv1 + pos BN ---
    posrel_kernel<<<(unsigned)(((size_t)B_ * PH_ * M_) / 256), 256>>>(pos, idx, pos_w1, pos_b1, t1_, partp);
    finalize_stats<<<PH_, 256>>>(partp, 512, 1, 512, pos_g1, pos_be1, scp, shp, (float)((size_t)B_ * M_));

    // --- fused mid on HMMA with smem-staged gather ---
    cudaFuncSetAttribute(fused_mid_hmma, cudaFuncAttributeMaxDynamicSharedMemorySize, FM_SMEM);
    fused_mid_hmma<<<dim3(M_ / 128, B_), 256, FM_SMEM>>>(
        t1_, scp, shp, wmidimg, bias1, pos_b2, u_, vt_, idx, h_, pe_, part);
    finalize_stats<<<AH_, 256>>>(part, B_ * 512, AH_, 1, att_g1, att_be1, sca, sha, (float)((size_t)B_ * M_));

    // --- big GEMM2: fp16 HMMA + softmax + aggregation ---
    cudaFuncSetAttribute(attn2_hmma_kernel, cudaFuncAttributeMaxDynamicSharedMemorySize, SMEM_ATT2);
    attn2_hmma_kernel<<<dim3(M_ / 128, B_), 256, SMEM_ATT2>>>(
        (const uint4*)w2img, h_, sca, sha, pe_, vf_, agg);

    // --- final projection + residual ---
    sgemm_kernel<4><<<dim3(N_ / 128, C_ / 128, B_), 256>>>(we, agg, be, out, val, C_, DIM_, N_);
}

// round 12
// speedup vs baseline: 1.2014x; 1.0421x over previous
#include <cuda_runtime.h>
#include <cuda_bf16.h>
#include <cuda_fp16.h>
#include <math.h>
#include <stdint.h>

#define B_   2
#define C_   128
#define N_   4096
#define K_   16
#define DIM_ 256
#define PH_  64
#define AH_  1024
#define M_   (N_ * K_)          // 65536 columns per batch in (n,k) space

// ---------------- scratch ---------------------------------------------------
__device__ float g_x    [(size_t)B_ * 2 * C_ * N_];
__device__ float g_t    [(size_t)B_ * C_ * N_];
__device__ float g_value[(size_t)B_ * C_ * N_];
__device__ float g_vf   [(size_t)B_ * DIM_ * N_];
__device__ float g_u    [(size_t)B_ * AH_ * N_];
__device__ float g_v    [(size_t)B_ * AH_ * N_];
__device__ float g_vt   [(size_t)B_ * N_ * AH_];       // v transposed: [B][N][AH]
__device__ int   g_idx  [(size_t)B_ * N_ * K_];
__device__ float g_t1   [(size_t)B_ * PH_ * M_];
__device__ float g_pe   [(size_t)B_ * DIM_ * M_];
__device__ float g_h    [(size_t)B_ * AH_ * M_];       // h: [B][AH][M]  (c-major)
__device__ float g_agg  [(size_t)B_ * DIM_ * N_];
__device__ float g_part [(size_t)B_ * 512 * AH_ * 2];
__device__ float g_partp[(size_t)PH_ * 512 * 2];
__device__ float g_Wuq  [AH_ * C_];
__device__ float g_Wvk  [AH_ * C_];
__device__ float g_bias1[AH_];
__device__ float g_scp  [PH_];
__device__ float g_shp  [PH_];
__device__ float g_sca  [AH_];
__device__ float g_sha  [AH_];
// fp16 image of att_w2: 16 K-chunks x 32KB = 512KB
__device__ unsigned int g_w2img[16 * 32768 / 4];
// fp16 image of Wmid = concat(att_w1@pos_w2, pos_w2): 10 chunks x 16KB
__device__ unsigned int g_wmidimg[10 * 16384 / 4];
// fp16 images of Wuq/Wvk: 8 c-chunks x 32KB (2 kc x 16KB)
__device__ unsigned int g_wuqimg[8 * 32768 / 4];
__device__ unsigned int g_wvkimg[8 * 32768 / 4];

// ---------------- helpers ---------------------------------------------------
__device__ __forceinline__ uint32_t smem_u32(const void* p) {
    uint32_t a;
    asm("{ .reg .u64 t; cvta.to.shared.u64 t, %1; cvt.u32.u64 %0, t; }" : "=r"(a) : "l"(p));
    return a;
}
#define SWZ128(b) ((b) ^ (((b) >> 3) & 0x70))
__device__ __forceinline__ uint32_t pack_h2(float a, float b) {
    __half2 t = __floats2half2_rn(a, b);
    return *reinterpret_cast<uint32_t*>(&t);
}
__device__ __forceinline__ void ldm_x4(uint32_t* r, uint32_t addr) {
    asm volatile("ldmatrix.sync.aligned.m8n8.x4.shared.b16 {%0,%1,%2,%3}, [%4];"
        : "=r"(r[0]), "=r"(r[1]), "=r"(r[2]), "=r"(r[3]) : "r"(addr));
}
__device__ __forceinline__ void mma16816h(float* d, const uint32_t* a, const uint32_t* b) {
    asm volatile(
        "mma.sync.aligned.m16n8k16.row.col.f32.f16.f16.f32 "
        "{%0,%1,%2,%3}, {%4,%5,%6,%7}, {%8,%9}, {%0,%1,%2,%3};"
        : "+f"(d[0]), "+f"(d[1]), "+f"(d[2]), "+f"(d[3])
        : "r"(a[0]), "r"(a[1]), "r"(a[2]), "r"(a[3]), "r"(b[0]), "r"(b[1]));
}
__device__ __forceinline__ void cp_async16(uint32_t dst, const void* src) {
    asm volatile("cp.async.cg.shared.global [%0], [%1], 16;" :: "r"(dst), "l"(src));
}
#define CP_COMMIT() asm volatile("cp.async.commit_group;" ::: "memory")
#define CP_WAIT0()  asm volatile("cp.async.wait_group 0;" ::: "memory")

// ---------------- concat ----------------------------------------------------
__global__ void concat_kernel(const float* __restrict__ key,
                              const float* __restrict__ query,
                              float* __restrict__ x) {
    size_t i = (size_t)blockIdx.x * blockDim.x + threadIdx.x;
    if (i >= (size_t)B_ * 2 * C_ * N_) return;
    int n = (int)(i % N_);
    int c = (int)((i / N_) % (2 * C_));
    int b = (int)(i / ((size_t)N_ * 2 * C_));
    float v;
    if (c < C_) v = key  [((size_t)b * C_ + c) * N_ + n];
    else        v = query[((size_t)b * C_ + (c - C_)) * N_ + n];
    x[i] = v;
}

// ---------------- KNN -------------------------------------------------------
__global__ void knn_kernel(const float* __restrict__ pos, int* __restrict__ idx) {
    const int b = blockIdx.y;
    const int n = blockIdx.x * blockDim.x + threadIdx.x;
    const float* p = pos + (size_t)b * 3 * N_;
    const float qx = p[n], qy = p[N_ + n], qz = p[2 * N_ + n];
    const float qs = qx * qx + qy * qy + qz * qz;
    float bd[K_]; int bi[K_];
#pragma unroll
    for (int j = 0; j < K_; j++) { bd[j] = 3.4e38f; bi[j] = 0; }
    __shared__ float sx[512], sy[512], sz[512], ss[512];
    for (int t0 = 0; t0 < N_; t0 += 512) {
        __syncthreads();
        for (int i = threadIdx.x; i < 512; i += blockDim.x) {
            float x = p[t0 + i], y = p[N_ + t0 + i], z = p[2 * N_ + t0 + i];
            sx[i] = x; sy[i] = y; sz[i] = z; ss[i] = x * x + y * y + z * z;
        }
        __syncthreads();
        for (int i = 0; i < 512; i++) {
            float d = qs + ss[i] - 2.0f * (qx * sx[i] + qy * sy[i] + qz * sz[i]);
            if (d < bd[K_ - 1]) {
                int j = K_ - 1;
                while (j > 0 && d < bd[j - 1]) { bd[j] = bd[j - 1]; bi[j] = bi[j - 1]; j--; }
                bd[j] = d; bi[j] = t0 + i;
            }
        }
    }
    int* op = idx + ((size_t)b * N_ + n) * K_;
#pragma unroll
    for (int j = 0; j < K_; j++) op[j] = bi[j];
}

// ---------------- precompute small products ---------------------------------
__global__ void smallmm_kernel(const float* __restrict__ A, const float* __restrict__ Bm,
                               float* __restrict__ Cc, int O, int Id, int J, int tr) {
    int t = blockIdx.x * 256 + threadIdx.x;
    if (t >= O * J) return;
    int o = t / J, j = t % J;
    float s = 0.0f;
    for (int d = 0; d < Id; d++) s += A[o * Id + d] * Bm[d * J + j];
    if (tr) Cc[j * O + o] = s; else Cc[o * J + j] = s;
}
__global__ void bias1_kernel(const float* __restrict__ w1, const float* __restrict__ bq,
                             const float* __restrict__ bk, const float* __restrict__ pb2,
                             const float* __restrict__ ab1, float* __restrict__ out) {
    int o = blockIdx.x * 256 + threadIdx.x;
    if (o >= AH_) return;
    float s = ab1[o];
    for (int d = 0; d < DIM_; d++) s += w1[o * DIM_ + d] * (bq[d] - bk[d] + pb2[d]);
    out[o] = s;
}
// v [B][AH][N] -> v_t [B][N][AH]
__global__ void transpose_bt(const float* __restrict__ src, float* __restrict__ dst) {
    __shared__ float tile[32][33];
    int b = blockIdx.z;
    int c0 = blockIdx.y * 32, n0 = blockIdx.x * 32;
    int tx = threadIdx.x, ty = threadIdx.y;
    const float* s = src + ((size_t)b * AH_ + c0) * N_ + n0;
#pragma unroll
    for (int i = 0; i < 32; i += 8) tile[ty + i][tx] = s[(size_t)(ty + i) * N_ + tx];
    __syncthreads();
    float* d = dst + ((size_t)b * N_ + n0) * AH_ + c0;
#pragma unroll
    for (int i = 0; i < 32; i += 8) d[(size_t)(ty + i) * AH_ + tx] = tile[tx][ty + i];
}

// ---------------- att_w2 -> pre-swizzled fp16 image --------------------------
__global__ void prep_w2_kernel(const float* __restrict__ w2, unsigned int* __restrict__ img) {
    int t = blockIdx.x * 256 + threadIdx.x;   // 65536 = 256 c * 256 k4
    if (t >= 256 * 256) return;
    int c = t >> 8, k4 = t & 255;
    int k = k4 * 4;
    int q = k >> 6, kl = k & 63;
    const float* src = w2 + (size_t)c * AH_ + k;
    uint32_t off = SWZ128((uint32_t)((c >> 3) * 1024 + (c & 7) * 128 + kl * 2));
    char* base = (char*)img + (size_t)q * 32768;
    *(uint2*)(base + off) = make_uint2(pack_h2(src[0], src[1]), pack_h2(src[2], src[3]));
}

// ---------------- Wmid -> pre-swizzled fp16 image ----------------------------
// Wmid[c][k]: c<1024: (att_w1@pos_w2)[c][k]; c>=1024: pos_w2[c-1024][k]. k=0..63.
__global__ void prep_wmid_kernel(const float* __restrict__ att_w1,
                                 const float* __restrict__ pos_w2,
                                 unsigned int* __restrict__ img) {
    int t = blockIdx.x * 256 + threadIdx.x;
    if (t >= 1280 * 16) return;
    int c = t >> 4, k4 = t & 15;
    float f[4];
    if (c < AH_) {
#pragma unroll 4
        for (int kk = 0; kk < 4; kk++) {
            float s = 0.0f;
            for (int d = 0; d < DIM_; d++)
                s += att_w1[(size_t)c * DIM_ + d] * pos_w2[d * PH_ + k4 * 4 + kk];
            f[kk] = s;
        }
    } else {
#pragma unroll
        for (int kk = 0; kk < 4; kk++) f[kk] = pos_w2[(c - AH_) * PH_ + k4 * 4 + kk];
    }
    int ct = c >> 7, cl = c & 127;
    uint32_t off = (uint32_t)((cl >> 3) * 1024 + (cl & 7) * 128 +
                              ((k4 * 8) ^ ((cl & 7) << 4)));
    char* base = (char*)img + (size_t)ct * 16384;
    *(uint2*)(base + off) = make_uint2(pack_h2(f[0], f[1]), pack_h2(f[2], f[3]));
}

// ---------------- Wuq/Wvk [AH][C=128] -> fp16 image: 8 c-chunks x 32KB --------
__global__ void prep_wuv_kernel(const float* __restrict__ W, unsigned int* __restrict__ img) {
    int t = blockIdx.x * 256 + threadIdx.x;     // 1024 c * 32 k4
    if (t >= AH_ * 32) return;
    int c = t >> 5, k4 = t & 31;
    int k = k4 * 4;
    int kc = k >> 6, kl = k & 63;
    const float* src = W + (size_t)c * C_ + k;
    int ct = c >> 7, cl = c & 127;
    uint32_t off = (uint32_t)((cl >> 3) * 1024 + (cl & 7) * 128 +
                              ((kl * 2) ^ ((cl & 7) << 4)));
    char* base = (char*)img + (size_t)ct * 32768 + (size_t)kc * 16384;
    *(uint2*)(base + off) = make_uint2(pack_h2(src[0], src[1]), pack_h2(src[2], src[3]));
}

// ---------------- generic fp32 SGEMM (small GEMMs) --------------------------
template <int FLAGS>
__global__ void sgemm_kernel(const float* __restrict__ W, const float* __restrict__ Xg,
                             const float* __restrict__ bias, float* __restrict__ outg,
                             const float* __restrict__ resg, int O, int I, int M) {
    const int b = blockIdx.z;
    const float* X = Xg + (size_t)b * I * M;
    float* out = outg + (size_t)b * O * M;
    const float* res = (FLAGS & 4) ? (resg + (size_t)b * O * M) : nullptr;
    __shared__ float Ws[8][132];
    __shared__ float Xs[8][128];
    const int tid = threadIdx.x;
    const int tx = tid & 15, ty = tid >> 4;
    const int o0 = blockIdx.y * 128, m0 = blockIdx.x * 128;
    const int wr = tid >> 1, wc = (tid & 1) * 4;
    const int xr = tid >> 5, xc = (tid & 31) * 4;
    float acc[8][8];
#pragma unroll
    for (int i = 0; i < 8; i++)
#pragma unroll
        for (int j = 0; j < 8; j++) acc[i][j] = 0.0f;
    for (int kt = 0; kt < I; kt += 8) {
        float4 wv = *(const float4*)&W[(size_t)(o0 + wr) * I + kt + wc];
        float4 xv = *(const float4*)&X[(size_t)(kt + xr) * M + m0 + xc];
        __syncthreads();
        Ws[wc + 0][wr] = wv.x; Ws[wc + 1][wr] = wv.y;
        Ws[wc + 2][wr] = wv.z; Ws[wc + 3][wr] = wv.w;
        *(float4*)&Xs[xr][xc] = xv;
        __syncthreads();
#pragma unroll
        for (int k = 0; k < 8; k++) {
            float a[8], bb[8];
            *(float4*)&a[0]  = *(const float4*)&Ws[k][ty * 8];
            *(float4*)&a[4]  = *(const float4*)&Ws[k][ty * 8 + 4];
            *(float4*)&bb[0] = *(const float4*)&Xs[k][tx * 8];
            *(float4*)&bb[4] = *(const float4*)&Xs[k][tx * 8 + 4];
#pragma unroll
            for (int i = 0; i < 8; i++)
#pragma unroll
                for (int j = 0; j < 8; j++) acc[i][j] += a[i] * bb[j];
        }
    }
#pragma unroll
    for (int i = 0; i < 8; i++) {
        const int o = o0 + ty * 8 + i;
        const float bv = bias[o];
        float* orow = out + (size_t)o * M + m0 + tx * 8;
        const float* rrow = (FLAGS & 4) ? (res + (size_t)o * M + m0 + tx * 8) : nullptr;
#pragma unroll
        for (int jj = 0; jj < 8; jj += 4) {
            float4 v;
            v.x = acc[i][jj + 0] + bv; v.y = acc[i][jj + 1] + bv;
            v.z = acc[i][jj + 2] + bv; v.w = acc[i][jj + 3] + bv;
            if (FLAGS & 1) { v.x = fmaxf(v.x, 0.f); v.y = fmaxf(v.y, 0.f);
                             v.z = fmaxf(v.z, 0.f); v.w = fmaxf(v.w, 0.f); }
            if (FLAGS & 2) { float4 old = *(float4*)&orow[jj];
                             v.x += old.x; v.y += old.y; v.z += old.z; v.w += old.w; }
            if (FLAGS & 4) { float4 r = *(const float4*)&rrow[jj];
                             v.x += r.x; v.y += r.y; v.z += r.z; v.w += r.w; }
            *(float4*)&orow[jj] = v;
        }
    }
}

// ---------------- pos_rel conv1 + BN partial stats ---------------------------
__global__ void posrel_kernel(const float* __restrict__ pos, const int* __restrict__ idx,
                              const float* __restrict__ w, const float* __restrict__ bias,
                              float* __restrict__ t1, float* __restrict__ part) {
    size_t i = (size_t)blockIdx.x * 256 + threadIdx.x;
    int k = (int)(i & 15);
    int n = (int)((i >> 4) & (N_ - 1));
    int c = (int)((i >> 16) & (PH_ - 1));
    int b = (int)(i >> 22);
    int m = idx[(((size_t)b * N_ + n) << 4) + k];
    const float* p = pos + (size_t)b * 3 * N_;
    float rx = p[n] - p[m];
    float ry = p[N_ + n] - p[N_ + m];
    float rz = p[2 * N_ + n] - p[2 * N_ + m];
    float val = w[c * 3] * rx + w[c * 3 + 1] * ry + w[c * 3 + 2] * rz + bias[c];
    t1[i] = val;
    __shared__ float ssum[256], ssq[256];
    ssum[threadIdx.x] = val; ssq[threadIdx.x] = val * val;
    __syncthreads();
    for (int st = 128; st > 0; st >>= 1) {
        if ((int)threadIdx.x < st) {
            ssum[threadIdx.x] += ssum[threadIdx.x + st];
            ssq[threadIdx.x]  += ssq[threadIdx.x + st];
        }
        __syncthreads();
    }
    if (threadIdx.x == 0) {
        int cb = (blockIdx.x >> 8) & (PH_ - 1);
        int bb = blockIdx.x >> 14;
        int sblk = blockIdx.x & 255;
        size_t o = ((size_t)cb * 512 + bb * 256 + sblk) * 2;
        part[o] = ssum[0]; part[o + 1] = ssq[0];
    }
}

// ---------------- BN finalize ------------------------------------------------
__global__ void finalize_stats(const float* __restrict__ part, int P, int ps, int cs,
                               const float* __restrict__ g, const float* __restrict__ be,
                               float* __restrict__ sc, float* __restrict__ sh, float cnt) {
    int c = blockIdx.x;
    double s = 0.0, q = 0.0;
    for (int p = threadIdx.x; p < P; p += blockDim.x) {
        size_t o = ((size_t)p * ps + (size_t)c * cs) * 2;
        s += (double)part[o]; q += (double)part[o + 1];
    }
    __shared__ double S[256], Q[256];
    S[threadIdx.x] = s; Q[threadIdx.x] = q;
    __syncthreads();
    for (int st = 128; st > 0; st >>= 1) {
        if ((int)threadIdx.x < st) {
            S[threadIdx.x] += S[threadIdx.x + st];
            Q[threadIdx.x] += Q[threadIdx.x + st];
        }
        __syncthreads();
    }
    if (threadIdx.x == 0) {
        double mean = S[0] / (double)cnt;
        double var  = Q[0] / (double)cnt - mean * mean;
        float scv = g[c] * (float)(1.0 / sqrt(var + 1e-5));
        sc[c] = scv;
        sh[c] = be[c] - (float)mean * scv;
    }
}

// ---------------- u/v GEMM on fp16 HMMA --------------------------------------
// out[c(1024)][n(128 per block)] = W[c][k] * X[k][n],  K = 128 (2 chunks)
// smem: X 32KB (2 kc x 16KB) | W 2 x 32KB = 96KB
#define UV_X     0
#define UV_W(s)  (32768 + (s) * 32768)
#define UV_SMEM  98304

__global__ __launch_bounds__(256, 1) void uv_hmma(
    const float* __restrict__ query, const float* __restrict__ key,
    const unsigned int* __restrict__ wuqimg, const unsigned int* __restrict__ wvkimg,
    float* __restrict__ ug, float* __restrict__ vg) {
    extern __shared__ char smc[];
    const uint32_t sb = smem_u32(smc);
    const int tid = threadIdx.x, lane = tid & 31, wid = tid >> 5;
    const int z = blockIdx.y;
    const int b = z & 1, which = z >> 1;
    const int n0 = blockIdx.x * 128;
    const float* X = (which == 0 ? query : key) + (size_t)b * C_ * N_;
    const unsigned int* wimg = (which == 0 ? wuqimg : wvkimg);
    float* out = (which == 0 ? ug : vg) + (size_t)b * AH_ * N_;
    const int warp_cg = wid >> 1;
    const int warp_mg = wid & 1;

    {
        const uint4* src = (const uint4*)wimg;
        uint32_t dst = sb + UV_W(0);
#pragma unroll
        for (int it = 0; it < 8; it++)
            cp_async16(dst + (it * 256 + tid) * 16, src + it * 256 + tid);
        CP_COMMIT();
    }
    {
        char* xbase = smc + UV_X;
        int m = tid & 127, khalf = tid >> 7;
#pragma unroll
        for (int k2 = 0; k2 < 32; k2++) {
            int k = khalf * 64 + k2 * 2;
            int kl = k & 63;
            float x0 = X[(size_t)k * N_ + n0 + m];
            float x1 = X[(size_t)(k + 1) * N_ + n0 + m];
            uint32_t off = (uint32_t)((m >> 3) * 1024 + (m & 7) * 128 +
                                      ((kl * 2) ^ ((m & 7) << 4)));
            char* dst = xbase + khalf * 16384;
            *(uint32_t*)(dst + off) = pack_h2(x0, x1);
        }
    }
    CP_WAIT0();
    __syncthreads();

    const int g = lane >> 3, lr = lane & 7;
    const int wrow = warp_cg * 32 + (g & 1) * 8 + lr;
    const int xrow = warp_mg * 64 + (g >> 1) * 8 + lr;
    const int wkb0 = (g >> 1) * 16;
    const int xkb0 = (g & 1) * 16;
    const uint32_t sX = sb + UV_X;

    for (int ct = 0; ct < 8; ct++) {
        const int s = ct & 1;
        if (ct + 1 < 8) {
            const uint4* src = (const uint4*)wimg + (ct + 1) * 2048;
            uint32_t dst = sb + UV_W(s ^ 1);
#pragma unroll
            for (int it = 0; it < 8; it++)
                cp_async16(dst + (it * 256 + tid) * 16, src + it * 256 + tid);
            CP_COMMIT();
        }
        const uint32_t sW = sb + UV_W(s);
        float acc[2][8][4];
#pragma unroll
        for (int a = 0; a < 2; a++)
#pragma unroll
            for (int q = 0; q < 8; q++)
#pragma unroll
                for (int j = 0; j < 4; j++) acc[a][q][j] = 0.0f;
#pragma unroll
        for (int kc = 0; kc < 2; kc++) {
#pragma unroll
            for (int ks = 0; ks < 4; ks++) {
                uint32_t Wf[2][4], Xf[4][4];
#pragma unroll
                for (int ct2 = 0; ct2 < 2; ct2++) {
                    int cr = wrow + ct2 * 16;
                    uint32_t ro = (uint32_t)((cr >> 3) * 1024 + (cr & 7) * 128);
                    uint32_t kb = (uint32_t)((ks * 32 + wkb0) ^ ((cr & 7) << 4));
                    ldm_x4(Wf[ct2], sW + kc * 16384 + ro + kb);
                }
#pragma unroll
                for (int np = 0; np < 4; np++) {
                    int mr = xrow + np * 16;
                    uint32_t ro = (uint32_t)((mr >> 3) * 1024 + (mr & 7) * 128);
                    uint32_t kb = (uint32_t)((ks * 32 + xkb0) ^ ((mr & 7) << 4));
                    ldm_x4(Xf[np], sX + kc * 16384 + ro + kb);
                }
#pragma unroll
                for (int ct2 = 0; ct2 < 2; ct2++)
#pragma unroll
                    for (int np = 0; np < 4; np++) {
                        mma16816h(acc[ct2][np * 2],     Wf[ct2], &Xf[np][0]);
                        mma16816h(acc[ct2][np * 2 + 1], Wf[ct2], &Xf[np][2]);
                    }
            }
        }
#pragma unroll
        for (int ct2 = 0; ct2 < 2; ct2++) {
#pragma unroll
            for (int j = 0; j < 4; j++) {
                int c_g = ct * 128 + warp_cg * 32 + ct2 * 16 + (lane >> 2) + (j >> 1) * 8;
                float* orow = out + (size_t)c_g * N_ + n0;
#pragma unroll
                for (int q = 0; q < 8; q++) {
                    int m_loc = warp_mg * 64 + q * 8 + (lane & 3) * 2 + (j & 1);
                    orow[m_loc] = acc[ct2][q][j];
                }
            }
        }
        CP_WAIT0();
        __syncthreads();
    }
}

// ---------------- fused mid on fp16 HMMA, smem-staged gather -----------------
// smem: X 16K | W 2x16K | VG 66048 | US 4608 | RED 2048 | SIDX 512
#define FM_X     0
#define FM_W(s)  (16384 + (s) * 16384)
#define FM_VG    49152
#define FM_U     115200
#define FM_RED   119808
#define FM_SIDX  121856
#define FM_SMEM  122368

__global__ __launch_bounds__(256, 1) void fused_mid_hmma(
    const float* __restrict__ t1, const float* __restrict__ psc,
    const float* __restrict__ psh, const unsigned int* __restrict__ wimg,
    const float* __restrict__ bias1, const float* __restrict__ pos_b2,
    const float* __restrict__ u, const float* __restrict__ vt,
    const int* __restrict__ idx, float* __restrict__ h,
    float* __restrict__ pe, float* __restrict__ part) {
    extern __shared__ char smc[];
    const uint32_t sb = smem_u32(smc);
    const int tid = threadIdx.x, lane = tid & 31, wid = tid >> 5;
    const int b = blockIdx.y, m0 = blockIdx.x * 128;
    const int warp_cg = wid >> 1;
    const int warp_mg = wid & 1;

    int* sidx = (int*)(smc + FM_SIDX);
    float* vgs = (float*)(smc + FM_VG);
    float* us  = (float*)(smc + FM_U);
    float* redS = (float*)(smc + FM_RED);
    float* redQ = redS + 256;

    if (tid < 128) sidx[tid] = idx[((size_t)b * N_ + (m0 >> 4)) * K_ + tid];

    {
        const uint4* src = (const uint4*)wimg;
        uint32_t dst = sb + FM_W(0);
#pragma unroll
        for (int it = 0; it < 4; it++)
            cp_async16(dst + (it * 256 + tid) * 16, src + it * 256 + tid);
        CP_COMMIT();
    }
    {
        const float* tb = t1 + (size_t)b * PH_ * M_ + m0;
        char* xd = smc + FM_X;
        int m = tid & 127, khalf = tid >> 7;
#pragma unroll
        for (int k2 = 0; k2 < 16; k2++) {
            int k = khalf * 32 + k2 * 2;
            float x0 = tb[(size_t)k * M_ + m];
            float x1 = tb[(size_t)(k + 1) * M_ + m];
            x0 = fmaxf(x0 * psc[k] + psh[k], 0.f);
            x1 = fmaxf(x1 * psc[k + 1] + psh[k + 1], 0.f);
            uint32_t off = (uint32_t)((m >> 3) * 1024 + (m & 7) * 128 +
                                      ((k * 2) ^ ((m & 7) << 4)));
            *(uint32_t*)(xd + off) = pack_h2(x0, x1);
        }
    }
    CP_WAIT0();
    __syncthreads();

    const int g = lane >> 3, lr = lane & 7;
    const int wrow = warp_cg * 32 + (g & 1) * 8 + lr;
    const int xrow = warp_mg * 64 + (g >> 1) * 8 + lr;
    const int wkb0 = (g >> 1) * 16;
    const int xkb0 = (g & 1) * 16;
    const uint32_t sX = sb + FM_X;
    const float* vtb = vt + (size_t)b * N_ * AH_;
    const int n0 = m0 >> 4;

    for (int ct = 0; ct < 10; ct++) {
        const int s = ct & 1;
        if (ct + 1 < 10) {
            const uint4* src = (const uint4*)wimg + (ct + 1) * 1024;
            uint32_t dst = sb + FM_W(s ^ 1);
#pragma unroll
            for (int it = 0; it < 4; it++)
                cp_async16(dst + (it * 256 + tid) * 16, src + it * 256 + tid);
            CP_COMMIT();
        }
        if (ct < 8) {
#pragma unroll
            for (int jj = 0; jj < 16; jj++) {
                int j = wid * 16 + jj;
                const float* row = vtb + (size_t)sidx[j] * AH_ + ct * 128;
#pragma unroll
                for (int cc = 0; cc < 4; cc++) {
                    int c = cc * 32 + lane;
                    vgs[c * 129 + j] = row[c];
                }
            }
#pragma unroll
            for (int it = 0; it < 4; it++) {
                int e = it * 256 + tid;
                int c = e >> 3, nn = e & 7;
                us[c * 9 + nn] = u[((size_t)b * AH_ + ct * 128 + c) * N_ + n0 + nn]
                               + bias1[ct * 128 + c];
            }
        }
        const uint32_t sW = sb + FM_W(s);
        float acc[2][8][4];
#pragma unroll
        for (int a = 0; a < 2; a++)
#pragma unroll
            for (int q = 0; q < 8; q++)
#pragma unroll
                for (int j = 0; j < 4; j++) acc[a][q][j] = 0.0f;
#pragma unroll
        for (int ks = 0; ks < 4; ks++) {
            uint32_t Wf[2][4], Xf[4][4];
#pragma unroll
            for (int ct2 = 0; ct2 < 2; ct2++) {
                int cr = wrow + ct2 * 16;
                uint32_t ro = (uint32_t)((cr >> 3) * 1024 + (cr & 7) * 128);
                uint32_t kb = (uint32_t)((ks * 32 + wkb0) ^ ((cr & 7) << 4));
                ldm_x4(Wf[ct2], sW + ro + kb);
            }
#pragma unroll
            for (int np = 0; np < 4; np++) {
                int mr = xrow + np * 16;
                uint32_t ro = (uint32_t)((mr >> 3) * 1024 + (mr & 7) * 128);
                uint32_t kb = (uint32_t)((ks * 32 + xkb0) ^ ((mr & 7) << 4));
                ldm_x4(Xf[np], sX + ro + kb);
            }
#pragma unroll
            for (int ct2 = 0; ct2 < 2; ct2++)
#pragma unroll
                for (int np = 0; np < 4; np++) {
                    mma16816h(acc[ct2][np * 2],     Wf[ct2], &Xf[np][0]);
                    mma16816h(acc[ct2][np * 2 + 1], Wf[ct2], &Xf[np][2]);
                }
        }
        if (ct < 8) {
            __syncthreads();
            float sS[2][2], sQ[2][2];
#pragma unroll
            for (int a = 0; a < 2; a++) { sS[a][0] = sS[a][1] = 0.f; sQ[a][0] = sQ[a][1] = 0.f; }
#pragma unroll
            for (int ct2 = 0; ct2 < 2; ct2++) {
#pragma unroll
                for (int j = 0; j < 4; j++) {
                    int rh = j >> 1;
                    int c_loc = warp_cg * 32 + ct2 * 16 + (lane >> 2) + rh * 8;
                    int c_g = ct * 128 + c_loc;
                    float* hrow = h + ((size_t)b * AH_ + c_g) * M_ + m0;
#pragma unroll
                    for (int q = 0; q < 8; q++) {
                        int m_loc = warp_mg * 64 + q * 8 + (lane & 3) * 2 + (j & 1);
                        float val = acc[ct2][q][j] + us[c_loc * 9 + (m_loc >> 4)]
                                  - vgs[c_loc * 129 + m_loc];
                        hrow[m_loc] = val;
                        sS[ct2][rh] += val; sQ[ct2][rh] += val * val;
                    }
                }
            }
#pragma unroll
            for (int ct2 = 0; ct2 < 2; ct2++)
#pragma unroll
                for (int rh = 0; rh < 2; rh++) {
                    float s1 = sS[ct2][rh], q1 = sQ[ct2][rh];
                    s1 += __shfl_xor_sync(0xffffffffu, s1, 1);
                    s1 += __shfl_xor_sync(0xffffffffu, s1, 2);
                    q1 += __shfl_xor_sync(0xffffffffu, q1, 1);
                    q1 += __shfl_xor_sync(0xffffffffu, q1, 2);
                    if ((lane & 3) == 0) {
                        int c_loc = warp_cg * 32 + ct2 * 16 + (lane >> 2) + rh * 8;
                        redS[c_loc * 2 + warp_mg] = s1;
                        redQ[c_loc * 2 + warp_mg] = q1;
                    }
                }
            __syncthreads();
            if (tid < 128) {
                float ss = redS[tid * 2] + redS[tid * 2 + 1];
                float qq = redQ[tid * 2] + redQ[tid * 2 + 1];
                size_t po = (((size_t)b * 512 + blockIdx.x) * AH_ + ct * 128 + tid) * 2;
                part[po] = ss; part[po + 1] = qq;
            }
        } else {
#pragma unroll
            for (int ct2 = 0; ct2 < 2; ct2++) {
#pragma unroll
                for (int j = 0; j < 4; j++) {
                    int c_pe = (ct - 8) * 128 + warp_cg * 32 + ct2 * 16 + (lane >> 2) + (j >> 1) * 8;
                    float bv = pos_b2[c_pe];
                    float* prow = pe + ((size_t)b * DIM_ + c_pe) * M_ + m0;
#pragma unroll
                    for (int q = 0; q < 8; q++) {
                        int m_loc = warp_mg * 64 + q * 8 + (lane & 3) * 2 + (j & 1);
                        prow[m_loc] = acc[ct2][q][j] + bv;
                    }
                }
            }
        }
        CP_WAIT0();
        __syncthreads();
    }
}

// ---------------- attn GEMM2 (fp16 HMMA, cp.async pipelined) -----------------
#define A_OFF(s)  ((s) * 16384)
#define B_OFF(s)  (32768 + (s) * 32768)
#define STG_OFF   98304
#define SMEM_ATT2 135168

__device__ __forceinline__ void attn2_cpasync(uint32_t sb, int s, int cq,
                                              const float* hbase, const uint4* w2img,
                                              int tid) {
    const uint4* src = w2img + (size_t)cq * 2048;
    uint32_t bdst = sb + B_OFF(s);
#pragma unroll
    for (int it = 0; it < 8; it++) {
        int i = it * 256 + tid;
        cp_async16(bdst + i * 16, src + i);
    }
#pragma unroll
    for (int it = 0; it < 8; it++) {
        int ch = it * 256 + tid;
        int krow = ch >> 5;
        const float* srcr = hbase + (size_t)(cq * 64 + krow) * M_ + (ch & 31) * 4;
        cp_async16(sb + STG_OFF + krow * 512 + (ch & 31) * 16, srcr);
    }
}

__device__ __forceinline__ void attn2_convert(char* smc, int s, int cq,
                                              const float* __restrict__ scale,
                                              const float* __restrict__ shift,
                                              int wid, int lane) {
    const float* stg = (const float*)(smc + STG_OFF);
    char* dst = smc + A_OFF(s);
#pragma unroll
    for (int g2 = 0; g2 < 2; g2++) {
        int base_k = wid * 8 + g2 * 4;
        float4 v[4];
#pragma unroll
        for (int r = 0; r < 4; r++)
            v[r] = *(const float4*)&stg[(base_k + r) * 128 + lane * 4];
        float X[4][4];
#pragma unroll
        for (int r = 0; r < 4; r++) {
            float sc = scale[cq * 64 + base_k + r];
            float sh = shift[cq * 64 + base_k + r];
            float xv[4] = {v[r].x, v[r].y, v[r].z, v[r].w};
#pragma unroll
            for (int mm = 0; mm < 4; mm++)
                X[mm][r] = fmaxf(xv[mm] * sc + sh, 0.f);
        }
#pragma unroll
        for (int mm = 0; mm < 4; mm++) {
            int m = lane * 4 + mm;
            uint32_t off = (uint32_t)((m >> 3) * 1024 + (m & 7) * 128 +
                                      ((base_k * 2) ^ ((m & 7) << 4)));
            *(uint2*)(dst + off) = make_uint2(pack_h2(X[mm][0], X[mm][1]),
                                              pack_h2(X[mm][2], X[mm][3]));
        }
    }
}

__global__ __launch_bounds__(256, 1) void attn2_hmma_kernel(
    const uint4* __restrict__ w2img, const float* __restrict__ h,
    const float* __restrict__ scale, const float* __restrict__ shift,
    const float* __restrict__ pe, const float* __restrict__ vf,
    float* __restrict__ agg) {
    extern __shared__ char smc[];
    const uint32_t sb = smem_u32(smc);
    const int tid = threadIdx.x, lane = tid & 31, wid = tid >> 5;
    const int b = blockIdx.y, m0 = blockIdx.x * 128;
    const int warp_m = wid >> 2, warp_c = wid & 3;

    const float* hbase = h + (size_t)b * AH_ * M_ + m0;

    float acc[4][8][4];
#pragma unroll
    for (int mt = 0; mt < 4; mt++)
#pragma unroll
        for (int nt = 0; nt < 8; nt++)
#pragma unroll
            for (int j = 0; j < 4; j++) acc[mt][nt][j] = 0.0f;

    const int g = lane >> 3, lr = lane & 7;
    const int amr  = warp_m * 64 + (g & 1) * 8 + lr;
    const int bcr  = warp_c * 64 + (g >> 1) * 8 + lr;
    const int akb0 = (g >> 1) * 16;
    const int bkb0 = (g & 1) * 16;

    attn2_cpasync(sb, 0, 0, hbase, w2img, tid);
    CP_COMMIT();
    CP_WAIT0();
    __syncthreads();
    attn2_convert(smc, 0, 0, scale, shift, wid, lane);
    __syncthreads();

    for (int cq = 0; cq < 16; cq++) {
        const int s = cq & 1;
        if (cq + 1 < 16) {
            attn2_cpasync(sb, s ^ 1, cq + 1, hbase, w2img, tid);
            CP_COMMIT();
        }
        const uint32_t sA = sb + A_OFF(s);
        const uint32_t sB = sb + B_OFF(s);
#pragma unroll
        for (int ks = 0; ks < 4; ks++) {
            uint32_t Af[4][4], Bf[4][4];
#pragma unroll
            for (int mt = 0; mt < 4; mt++) {
                int m = amr + mt * 16;
                uint32_t ro = (uint32_t)((m >> 3) * 1024 + (m & 7) * 128);
                uint32_t kb = (uint32_t)((ks * 32 + akb0) ^ ((m & 7) << 4));
                ldm_x4(Af[mt], sA + ro + kb);
            }
#pragma unroll
            for (int np = 0; np < 4; np++) {
                int c = bcr + np * 16;
                uint32_t ro = (uint32_t)((c >> 3) * 1024 + (c & 7) * 128);
                uint32_t kb = (uint32_t)((ks * 32 + bkb0) ^ ((c & 7) << 4));
                ldm_x4(Bf[np], sB + ro + kb);
            }
#pragma unroll
            for (int mt = 0; mt < 4; mt++)
#pragma unroll
                for (int np = 0; np < 4; np++) {
                    mma16816h(acc[mt][np * 2],     Af[mt], &Bf[np][0]);
                    mma16816h(acc[mt][np * 2 + 1], Af[mt], &Bf[np][2]);
                }
        }
        if (cq + 1 < 16) {
            CP_WAIT0();
            __syncthreads();
            attn2_convert(smc, s ^ 1, cq + 1, scale, shift, wid, lane);
            __syncthreads();
        }
    }
    __syncthreads();

    float* pes = (float*)smc;
    for (int i = tid; i < 256 * 32; i += 256) {
        int row = i >> 5, q = i & 31;
        float4 v = *(const float4*)(pe + ((size_t)(b * DIM_ + row)) * M_ + m0 + q * 4);
        *(float4*)&pes[row * 132 + q * 4] = v;
    }
    __syncthreads();

#pragma unroll
    for (int mt = 0; mt < 4; mt++) {
        const int mbase = warp_m * 64 + mt * 16;
        const int n = (m0 + mbase) >> 4;
        const int r = lane >> 2;
#pragma unroll
        for (int nt = 0; nt < 8; nt++) {
#pragma unroll
            for (int j = 0; j < 2; j++) {
                int c = warp_c * 64 + nt * 8 + (lane & 3) * 2 + j;
                float v0 = acc[mt][nt][j], v1 = acc[mt][nt][2 + j];
                float mx = fmaxf(v0, v1);
                mx = fmaxf(mx, __shfl_xor_sync(0xffffffffu, mx, 4));
                mx = fmaxf(mx, __shfl_xor_sync(0xffffffffu, mx, 8));
                mx = fmaxf(mx, __shfl_xor_sync(0xffffffffu, mx, 16));
                float e0 = __expf(v0 - mx), e1 = __expf(v1 - mx);
                float se = e0 + e1;
                se += __shfl_xor_sync(0xffffffffu, se, 4);
                se += __shfl_xor_sync(0xffffffffu, se, 8);
                se += __shfl_xor_sync(0xffffffffu, se, 16);
                float p0 = pes[c * 132 + mbase + r];
                float p1 = pes[c * 132 + mbase + r + 8];
                float t = e0 * p0 + e1 * p1;
                t += __shfl_xor_sync(0xffffffffu, t, 4);
                t += __shfl_xor_sync(0xffffffffu, t, 8);
                t += __shfl_xor_sync(0xffffffffu, t, 16);
                if (r == 0) {
                    size_t o = ((size_t)(b * DIM_ + c)) * N_ + n;
                    agg[o] = vf[o] + t / se;
                }
            }
        }
    }
}

// ---------------- launch ----------------------------------------------------
extern "C" void kernel_launch(void* const* d_in, const int* in_sizes, int n_in,
                              void* d_out, int out_size) {
    const float* pos     = (const float*)d_in[0];
    const float* key     = (const float*)d_in[1];
    const float* query   = (const float*)d_in[2];
    const float* mlpv_w1 = (const float*)d_in[3];
    const float* mlpv_b1 = (const float*)d_in[4];
    const float* mlpv_w2 = (const float*)d_in[5];
    const float* mlpv_b2 = (const float*)d_in[6];
    const float* mlpv_ws = (const float*)d_in[7];
    const float* mlpv_bs = (const float*)d_in[8];
    const float* wk      = (const float*)d_in[9];
    const float* bk      = (const float*)d_in[10];
    const float* wq      = (const float*)d_in[11];
    const float* bq      = (const float*)d_in[12];
    const float* wv      = (const float*)d_in[13];
    const float* bv      = (const float*)d_in[14];
    const float* pos_w1  = (const float*)d_in[15];
    const float* pos_b1  = (const float*)d_in[16];
    const float* pos_g1  = (const float*)d_in[17];
    const float* pos_be1 = (const float*)d_in[18];
    const float* pos_w2  = (const float*)d_in[19];
    const float* pos_b2  = (const float*)d_in[20];
    const float* att_w1  = (const float*)d_in[21];
    const float* att_b1  = (const float*)d_in[22];
    const float* att_g1  = (const float*)d_in[23];
    const float* att_be1 = (const float*)d_in[24];
    const float* att_w2  = (const float*)d_in[25];
    const float* we      = (const float*)d_in[27];
    const float* be      = (const float*)d_in[28];
    float* out = (float*)d_out;

    void* p;
#define GETP(sym, var) cudaGetSymbolAddress(&p, sym); float* var = (float*)p;
    GETP(g_x, x_)       GETP(g_t, t_)       GETP(g_value, val)
    GETP(g_vf, vf_)     GETP(g_u, u_)       GETP(g_v, v_)
    GETP(g_vt, vt_)
    GETP(g_t1, t1_)     GETP(g_pe, pe_)     GETP(g_h, h_)
    GETP(g_agg, agg)    GETP(g_part, part)  GETP(g_partp, partp)
    GETP(g_Wuq, Wuq)    GETP(g_Wvk, Wvk)    GETP(g_bias1, bias1)
    GETP(g_scp, scp)    GETP(g_shp, shp)    GETP(g_sca, sca)
    GETP(g_sha, sha)
#undef GETP
    cudaGetSymbolAddress(&p, g_idx);      int* idx = (int*)p;
    cudaGetSymbolAddress(&p, g_w2img);    unsigned int* w2img = (unsigned int*)p;
    cudaGetSymbolAddress(&p, g_wmidimg);  unsigned int* wmidimg = (unsigned int*)p;
    cudaGetSymbolAddress(&p, g_wuqimg);   unsigned int* wuqimg = (unsigned int*)p;
    cudaGetSymbolAddress(&p, g_wvkimg);   unsigned int* wvkimg = (unsigned int*)p;

    // --- precompute folded weights + weight images ---
    smallmm_kernel<<<(AH_ * C_ + 255) / 256, 256>>>(att_w1, wq, Wuq, AH_, DIM_, C_, 0);
    smallmm_kernel<<<(AH_ * C_ + 255) / 256, 256>>>(att_w1, wk, Wvk, AH_, DIM_, C_, 0);
    bias1_kernel<<<(AH_ + 255) / 256, 256>>>(att_w1, bq, bk, pos_b2, att_b1, bias1);
    prep_w2_kernel<<<(256 * 256) / 256, 256>>>(att_w2, w2img);
    prep_wmid_kernel<<<(1280 * 16 + 255) / 256, 256>>>(att_w1, pos_w2, wmidimg);
    prep_wuv_kernel<<<(AH_ * 32 + 255) / 256, 256>>>(Wuq, wuqimg);
    prep_wuv_kernel<<<(AH_ * 32 + 255) / 256, 256>>>(Wvk, wvkimg);

    // --- front end ---
    concat_kernel<<<(unsigned)(((size_t)B_ * 2 * C_ * N_ + 255) / 256), 256>>>(key, query, x_);
    knn_kernel<<<dim3(N_ / 256, B_), 256>>>(pos, idx);
    sgemm_kernel<1><<<dim3(N_ / 128, C_ / 128, B_), 256>>>(mlpv_w1, x_, mlpv_b1, t_, nullptr, C_, 2 * C_, N_);
    sgemm_kernel<0><<<dim3(N_ / 128, C_ / 128, B_), 256>>>(mlpv_w2, t_, mlpv_b2, val, nullptr, C_, C_, N_);
    sgemm_kernel<2><<<dim3(N_ / 128, C_ / 128, B_), 256>>>(mlpv_ws, x_, mlpv_bs, val, nullptr, C_, 2 * C_, N_);
    sgemm_kernel<0><<<dim3(N_ / 128, DIM_ / 128, B_), 256>>>(wv, val, bv, vf_, nullptr, DIM_, C_, N_);

    // --- u/v on fp16 HMMA ---
    cudaFuncSetAttribute(uv_hmma, cudaFuncAttributeMaxDynamicSharedMemorySize, UV_SMEM);
    uv_hmma<<<dim3(N_ / 128, 4), 256, UV_SMEM>>>(query, key, wuqimg, wvkimg, u_, v_);
    transpose_bt<<<dim3(N_ / 32, AH_ / 32, B_), dim3(32, 8)>>>(v_, vt_);

    // --- pos_rel conv1 + pos BN ---
    posrel_kernel<<<(unsigned)(((size_t)B_ * PH_ * M_) / 256), 256>>>(pos, idx, pos_w1, pos_b1, t1_, partp);
    finalize_stats<<<PH_, 256>>>(partp, 512, 1, 512, pos_g1, pos_be1, scp, shp, (float)((size_t)B_ * M_));

    // --- fused mid on fp16 HMMA with smem-staged gather ---
    cudaFuncSetAttribute(fused_mid_hmma, cudaFuncAttributeMaxDynamicSharedMemorySize, FM_SMEM);
    fused_mid_hmma<<<dim3(M_ / 128, B_), 256, FM_SMEM>>>(
        t1_, scp, shp, wmidimg, bias1, pos_b2, u_, vt_, idx, h_, pe_, part);
    finalize_stats<<<AH_, 256>>>(part, B_ * 512, AH_, 1, att_g1, att_be1, sca, sha, (float)((size_t)B_ * M_));

    // --- big GEMM2: fp16 HMMA + softmax + aggregation ---
    cudaFuncSetAttribute(attn2_hmma_kernel, cudaFuncAttributeMaxDynamicSharedMemorySize, SMEM_ATT2);
    attn2_hmma_kernel<<<dim3(M_ / 128, B_), 256, SMEM_ATT2>>>(
        (const uint4*)w2img, h_, sca, sha, pe_, vf_, agg);

    // --- final projection + residual ---
    sgemm_kernel<4><<<dim3(N_ / 128, C_ / 128, B_), 256>>>(we, agg, be, out, val, C_, DIM_, N_);
}

// round 13
// speedup vs baseline: 1.2565x; 1.0458x over previous
#include <cuda_runtime.h>
#include <cuda_bf16.h>
#include <cuda_fp16.h>
#include <math.h>
#include <stdint.h>

#define B_   2
#define C_   128
#define N_   4096
#define K_   16
#define DIM_ 256
#define PH_  64
#define AH_  1024
#define M_   (N_ * K_)          // 65536 columns per batch in (n,k) space

// ---------------- scratch ---------------------------------------------------
__device__ float g_x    [(size_t)B_ * 2 * C_ * N_];
__device__ float g_t    [(size_t)B_ * C_ * N_];
__device__ float g_value[(size_t)B_ * C_ * N_];
__device__ float g_vf   [(size_t)B_ * DIM_ * N_];
__device__ float g_u    [(size_t)B_ * AH_ * N_];
__device__ float g_v    [(size_t)B_ * AH_ * N_];
__device__ __half g_vt  [(size_t)B_ * N_ * AH_];       // v transposed (fp16)
__device__ int   g_idx  [(size_t)B_ * N_ * K_];
__device__ float g_t1   [(size_t)B_ * PH_ * M_];
__device__ __half g_pe  [(size_t)B_ * DIM_ * M_];      // pos_emb (fp16)
__device__ __half g_h   [(size_t)B_ * AH_ * M_];       // h (fp16, c-major)
__device__ float g_agg  [(size_t)B_ * DIM_ * N_];
__device__ float g_part [(size_t)B_ * 512 * AH_ * 2];
__device__ float g_partp[(size_t)PH_ * 512 * 2];
__device__ float g_Wuq  [AH_ * C_];
__device__ float g_Wvk  [AH_ * C_];
__device__ float g_bias1[AH_];
__device__ float g_scp  [PH_];
__device__ float g_shp  [PH_];
__device__ float g_sca  [AH_];
__device__ float g_sha  [AH_];
// fp16 image of att_w2: 16 K-chunks x 32KB = 512KB
__device__ unsigned int g_w2img[16 * 32768 / 4];
// fp16 image of Wmid = concat(att_w1@pos_w2, pos_w2): 10 chunks x 16KB
__device__ unsigned int g_wmidimg[10 * 16384 / 4];
// fp16 images of Wuq/Wvk: 8 c-chunks x 32KB (2 kc x 16KB)
__device__ unsigned int g_wuqimg[8 * 32768 / 4];
__device__ unsigned int g_wvkimg[8 * 32768 / 4];

// ---------------- helpers ---------------------------------------------------
__device__ __forceinline__ uint32_t smem_u32(const void* p) {
    uint32_t a;
    asm("{ .reg .u64 t; cvta.to.shared.u64 t, %1; cvt.u32.u64 %0, t; }" : "=r"(a) : "l"(p));
    return a;
}
#define SWZ128(b) ((b) ^ (((b) >> 3) & 0x70))
__device__ __forceinline__ uint32_t pack_h2(float a, float b) {
    __half2 t = __floats2half2_rn(a, b);
    return *reinterpret_cast<uint32_t*>(&t);
}
__device__ __forceinline__ void ldm_x4(uint32_t* r, uint32_t addr) {
    asm volatile("ldmatrix.sync.aligned.m8n8.x4.shared.b16 {%0,%1,%2,%3}, [%4];"
        : "=r"(r[0]), "=r"(r[1]), "=r"(r[2]), "=r"(r[3]) : "r"(addr));
}
__device__ __forceinline__ void mma16816h(float* d, const uint32_t* a, const uint32_t* b) {
    asm volatile(
        "mma.sync.aligned.m16n8k16.row.col.f32.f16.f16.f32 "
        "{%0,%1,%2,%3}, {%4,%5,%6,%7}, {%8,%9}, {%0,%1,%2,%3};"
        : "+f"(d[0]), "+f"(d[1]), "+f"(d[2]), "+f"(d[3])
        : "r"(a[0]), "r"(a[1]), "r"(a[2]), "r"(a[3]), "r"(b[0]), "r"(b[1]));
}
__device__ __forceinline__ void cp_async16(uint32_t dst, const void* src) {
    asm volatile("cp.async.cg.shared.global [%0], [%1], 16;" :: "r"(dst), "l"(src));
}
#define CP_COMMIT() asm volatile("cp.async.commit_group;" ::: "memory")
#define CP_WAIT0()  asm volatile("cp.async.wait_group 0;" ::: "memory")

// ---------------- concat ----------------------------------------------------
__global__ void concat_kernel(const float* __restrict__ key,
                              const float* __restrict__ query,
                              float* __restrict__ x) {
    size_t i = (size_t)blockIdx.x * blockDim.x + threadIdx.x;
    if (i >= (size_t)B_ * 2 * C_ * N_) return;
    int n = (int)(i % N_);
    int c = (int)((i / N_) % (2 * C_));
    int b = (int)(i / ((size_t)N_ * 2 * C_));
    float v;
    if (c < C_) v = key  [((size_t)b * C_ + c) * N_ + n];
    else        v = query[((size_t)b * C_ + (c - C_)) * N_ + n];
    x[i] = v;
}

// ---------------- KNN -------------------------------------------------------
__global__ void knn_kernel(const float* __restrict__ pos, int* __restrict__ idx) {
    const int b = blockIdx.y;
    const int n = blockIdx.x * blockDim.x + threadIdx.x;
    const float* p = pos + (size_t)b * 3 * N_;
    const float qx = p[n], qy = p[N_ + n], qz = p[2 * N_ + n];
    const float qs = qx * qx + qy * qy + qz * qz;
    float bd[K_]; int bi[K_];
#pragma unroll
    for (int j = 0; j < K_; j++) { bd[j] = 3.4e38f; bi[j] = 0; }
    __shared__ float sx[512], sy[512], sz[512], ss[512];
    for (int t0 = 0; t0 < N_; t0 += 512) {
        __syncthreads();
        for (int i = threadIdx.x; i < 512; i += blockDim.x) {
            float x = p[t0 + i], y = p[N_ + t0 + i], z = p[2 * N_ + t0 + i];
            sx[i] = x; sy[i] = y; sz[i] = z; ss[i] = x * x + y * y + z * z;
        }
        __syncthreads();
        for (int i = 0; i < 512; i++) {
            float d = qs + ss[i] - 2.0f * (qx * sx[i] + qy * sy[i] + qz * sz[i]);
            if (d < bd[K_ - 1]) {
                int j = K_ - 1;
                while (j > 0 && d < bd[j - 1]) { bd[j] = bd[j - 1]; bi[j] = bi[j - 1]; j--; }
                bd[j] = d; bi[j] = t0 + i;
            }
        }
    }
    int* op = idx + ((size_t)b * N_ + n) * K_;
#pragma unroll
    for (int j = 0; j < K_; j++) op[j] = bi[j];
}

// ---------------- precompute small products ---------------------------------
__global__ void smallmm_kernel(const float* __restrict__ A, const float* __restrict__ Bm,
                               float* __restrict__ Cc, int O, int Id, int J, int tr) {
    int t = blockIdx.x * 256 + threadIdx.x;
    if (t >= O * J) return;
    int o = t / J, j = t % J;
    float s = 0.0f;
    for (int d = 0; d < Id; d++) s += A[o * Id + d] * Bm[d * J + j];
    if (tr) Cc[j * O + o] = s; else Cc[o * J + j] = s;
}
__global__ void bias1_kernel(const float* __restrict__ w1, const float* __restrict__ bq,
                             const float* __restrict__ bk, const float* __restrict__ pb2,
                             const float* __restrict__ ab1, float* __restrict__ out) {
    int o = blockIdx.x * 256 + threadIdx.x;
    if (o >= AH_) return;
    float s = ab1[o];
    for (int d = 0; d < DIM_; d++) s += w1[o * DIM_ + d] * (bq[d] - bk[d] + pb2[d]);
    out[o] = s;
}
// v [B][AH][N] fp32 -> v_t [B][N][AH] fp16
__global__ void transpose_bt(const float* __restrict__ src, __half* __restrict__ dst) {
    __shared__ float tile[32][33];
    int b = blockIdx.z;
    int c0 = blockIdx.y * 32, n0 = blockIdx.x * 32;
    int tx = threadIdx.x, ty = threadIdx.y;
    const float* s = src + ((size_t)b * AH_ + c0) * N_ + n0;
#pragma unroll
    for (int i = 0; i < 32; i += 8) tile[ty + i][tx] = s[(size_t)(ty + i) * N_ + tx];
    __syncthreads();
    __half* d = dst + ((size_t)b * N_ + n0) * AH_ + c0;
#pragma unroll
    for (int i = 0; i < 32; i += 8) d[(size_t)(ty + i) * AH_ + tx] = __float2half(tile[tx][ty + i]);
}

// ---------------- att_w2 -> pre-swizzled fp16 image --------------------------
__global__ void prep_w2_kernel(const float* __restrict__ w2, unsigned int* __restrict__ img) {
    int t = blockIdx.x * 256 + threadIdx.x;
    if (t >= 256 * 256) return;
    int c = t >> 8, k4 = t & 255;
    int k = k4 * 4;
    int q = k >> 6, kl = k & 63;
    const float* src = w2 + (size_t)c * AH_ + k;
    uint32_t off = SWZ128((uint32_t)((c >> 3) * 1024 + (c & 7) * 128 + kl * 2));
    char* base = (char*)img + (size_t)q * 32768;
    *(uint2*)(base + off) = make_uint2(pack_h2(src[0], src[1]), pack_h2(src[2], src[3]));
}

// ---------------- Wmid -> pre-swizzled fp16 image ----------------------------
__global__ void prep_wmid_kernel(const float* __restrict__ att_w1,
                                 const float* __restrict__ pos_w2,
                                 unsigned int* __restrict__ img) {
    int t = blockIdx.x * 256 + threadIdx.x;
    if (t >= 1280 * 16) return;
    int c = t >> 4, k4 = t & 15;
    float f[4];
    if (c < AH_) {
#pragma unroll 4
        for (int kk = 0; kk < 4; kk++) {
            float s = 0.0f;
            for (int d = 0; d < DIM_; d++)
                s += att_w1[(size_t)c * DIM_ + d] * pos_w2[d * PH_ + k4 * 4 + kk];
            f[kk] = s;
        }
    } else {
#pragma unroll
        for (int kk = 0; kk < 4; kk++) f[kk] = pos_w2[(c - AH_) * PH_ + k4 * 4 + kk];
    }
    int ct = c >> 7, cl = c & 127;
    uint32_t off = (uint32_t)((cl >> 3) * 1024 + (cl & 7) * 128 +
                              ((k4 * 8) ^ ((cl & 7) << 4)));
    char* base = (char*)img + (size_t)ct * 16384;
    *(uint2*)(base + off) = make_uint2(pack_h2(f[0], f[1]), pack_h2(f[2], f[3]));
}

// ---------------- Wuq/Wvk [AH][C=128] -> fp16 image: 8 c-chunks x 32KB --------
__global__ void prep_wuv_kernel(const float* __restrict__ W, unsigned int* __restrict__ img) {
    int t = blockIdx.x * 256 + threadIdx.x;
    if (t >= AH_ * 32) return;
    int c = t >> 5, k4 = t & 31;
    int k = k4 * 4;
    int kc = k >> 6, kl = k & 63;
    const float* src = W + (size_t)c * C_ + k;
    int ct = c >> 7, cl = c & 127;
    uint32_t off = (uint32_t)((cl >> 3) * 1024 + (cl & 7) * 128 +
                              ((kl * 2) ^ ((cl & 7) << 4)));
    char* base = (char*)img + (size_t)ct * 32768 + (size_t)kc * 16384;
    *(uint2*)(base + off) = make_uint2(pack_h2(src[0], src[1]), pack_h2(src[2], src[3]));
}

// ---------------- generic fp32 SGEMM (small GEMMs) --------------------------
template <int FLAGS>
__global__ void sgemm_kernel(const float* __restrict__ W, const float* __restrict__ Xg,
                             const float* __restrict__ bias, float* __restrict__ outg,
                             const float* __restrict__ resg, int O, int I, int M) {
    const int b = blockIdx.z;
    const float* X = Xg + (size_t)b * I * M;
    float* out = outg + (size_t)b * O * M;
    const float* res = (FLAGS & 4) ? (resg + (size_t)b * O * M) : nullptr;
    __shared__ float Ws[8][132];
    __shared__ float Xs[8][128];
    const int tid = threadIdx.x;
    const int tx = tid & 15, ty = tid >> 4;
    const int o0 = blockIdx.y * 128, m0 = blockIdx.x * 128;
    const int wr = tid >> 1, wc = (tid & 1) * 4;
    const int xr = tid >> 5, xc = (tid & 31) * 4;
    float acc[8][8];
#pragma unroll
    for (int i = 0; i < 8; i++)
#pragma unroll
        for (int j = 0; j < 8; j++) acc[i][j] = 0.0f;
    for (int kt = 0; kt < I; kt += 8) {
        float4 wv = *(const float4*)&W[(size_t)(o0 + wr) * I + kt + wc];
        float4 xv = *(const float4*)&X[(size_t)(kt + xr) * M + m0 + xc];
        __syncthreads();
        Ws[wc + 0][wr] = wv.x; Ws[wc + 1][wr] = wv.y;
        Ws[wc + 2][wr] = wv.z; Ws[wc + 3][wr] = wv.w;
        *(float4*)&Xs[xr][xc] = xv;
        __syncthreads();
#pragma unroll
        for (int k = 0; k < 8; k++) {
            float a[8], bb[8];
            *(float4*)&a[0]  = *(const float4*)&Ws[k][ty * 8];
            *(float4*)&a[4]  = *(const float4*)&Ws[k][ty * 8 + 4];
            *(float4*)&bb[0] = *(const float4*)&Xs[k][tx * 8];
            *(float4*)&bb[4] = *(const float4*)&Xs[k][tx * 8 + 4];
#pragma unroll
            for (int i = 0; i < 8; i++)
#pragma unroll
                for (int j = 0; j < 8; j++) acc[i][j] += a[i] * bb[j];
        }
    }
#pragma unroll
    for (int i = 0; i < 8; i++) {
        const int o = o0 + ty * 8 + i;
        const float bv = bias[o];
        float* orow = out + (size_t)o * M + m0 + tx * 8;
        const float* rrow = (FLAGS & 4) ? (res + (size_t)o * M + m0 + tx * 8) : nullptr;
#pragma unroll
        for (int jj = 0; jj < 8; jj += 4) {
            float4 v;
            v.x = acc[i][jj + 0] + bv; v.y = acc[i][jj + 1] + bv;
            v.z = acc[i][jj + 2] + bv; v.w = acc[i][jj + 3] + bv;
            if (FLAGS & 1) { v.x = fmaxf(v.x, 0.f); v.y = fmaxf(v.y, 0.f);
                             v.z = fmaxf(v.z, 0.f); v.w = fmaxf(v.w, 0.f); }
            if (FLAGS & 2) { float4 old = *(float4*)&orow[jj];
                             v.x += old.x; v.y += old.y; v.z += old.z; v.w += old.w; }
            if (FLAGS & 4) { float4 r = *(const float4*)&rrow[jj];
                             v.x += r.x; v.y += r.y; v.z += r.z; v.w += r.w; }
            *(float4*)&orow[jj] = v;
        }
    }
}

// ---------------- pos_rel conv1 + BN partial stats ---------------------------
__global__ void posrel_kernel(const float* __restrict__ pos, const int* __restrict__ idx,
                              const float* __restrict__ w, const float* __restrict__ bias,
                              float* __restrict__ t1, float* __restrict__ part) {
    size_t i = (size_t)blockIdx.x * 256 + threadIdx.x;
    int k = (int)(i & 15);
    int n = (int)((i >> 4) & (N_ - 1));
    int c = (int)((i >> 16) & (PH_ - 1));
    int b = (int)(i >> 22);
    int m = idx[(((size_t)b * N_ + n) << 4) + k];
    const float* p = pos + (size_t)b * 3 * N_;
    float rx = p[n] - p[m];
    float ry = p[N_ + n] - p[N_ + m];
    float rz = p[2 * N_ + n] - p[2 * N_ + m];
    float val = w[c * 3] * rx + w[c * 3 + 1] * ry + w[c * 3 + 2] * rz + bias[c];
    t1[i] = val;
    __shared__ float ssum[256], ssq[256];
    ssum[threadIdx.x] = val; ssq[threadIdx.x] = val * val;
    __syncthreads();
    for (int st = 128; st > 0; st >>= 1) {
        if ((int)threadIdx.x < st) {
            ssum[threadIdx.x] += ssum[threadIdx.x + st];
            ssq[threadIdx.x]  += ssq[threadIdx.x + st];
        }
        __syncthreads();
    }
    if (threadIdx.x == 0) {
        int cb = (blockIdx.x >> 8) & (PH_ - 1);
        int bb = blockIdx.x >> 14;
        int sblk = blockIdx.x & 255;
        size_t o = ((size_t)cb * 512 + bb * 256 + sblk) * 2;
        part[o] = ssum[0]; part[o + 1] = ssq[0];
    }
}

// ---------------- BN finalize ------------------------------------------------
__global__ void finalize_stats(const float* __restrict__ part, int P, int ps, int cs,
                               const float* __restrict__ g, const float* __restrict__ be,
                               float* __restrict__ sc, float* __restrict__ sh, float cnt) {
    int c = blockIdx.x;
    double s = 0.0, q = 0.0;
    for (int p = threadIdx.x; p < P; p += blockDim.x) {
        size_t o = ((size_t)p * ps + (size_t)c * cs) * 2;
        s += (double)part[o]; q += (double)part[o + 1];
    }
    __shared__ double S[256], Q[256];
    S[threadIdx.x] = s; Q[threadIdx.x] = q;
    __syncthreads();
    for (int st = 128; st > 0; st >>= 1) {
        if ((int)threadIdx.x < st) {
            S[threadIdx.x] += S[threadIdx.x + st];
            Q[threadIdx.x] += Q[threadIdx.x + st];
        }
        __syncthreads();
    }
    if (threadIdx.x == 0) {
        double mean = S[0] / (double)cnt;
        double var  = Q[0] / (double)cnt - mean * mean;
        float scv = g[c] * (float)(1.0 / sqrt(var + 1e-5));
        sc[c] = scv;
        sh[c] = be[c] - (float)mean * scv;
    }
}

// ---------------- u/v GEMM on fp16 HMMA --------------------------------------
#define UV_X     0
#define UV_W(s)  (32768 + (s) * 32768)
#define UV_SMEM  98304

__global__ __launch_bounds__(256, 1) void uv_hmma(
    const float* __restrict__ query, const float* __restrict__ key,
    const unsigned int* __restrict__ wuqimg, const unsigned int* __restrict__ wvkimg,
    float* __restrict__ ug, float* __restrict__ vg) {
    extern __shared__ char smc[];
    const uint32_t sb = smem_u32(smc);
    const int tid = threadIdx.x, lane = tid & 31, wid = tid >> 5;
    const int z = blockIdx.y;
    const int b = z & 1, which = z >> 1;
    const int n0 = blockIdx.x * 128;
    const float* X = (which == 0 ? query : key) + (size_t)b * C_ * N_;
    const unsigned int* wimg = (which == 0 ? wuqimg : wvkimg);
    float* out = (which == 0 ? ug : vg) + (size_t)b * AH_ * N_;
    const int warp_cg = wid >> 1;
    const int warp_mg = wid & 1;

    {
        const uint4* src = (const uint4*)wimg;
        uint32_t dst = sb + UV_W(0);
#pragma unroll
        for (int it = 0; it < 8; it++)
            cp_async16(dst + (it * 256 + tid) * 16, src + it * 256 + tid);
        CP_COMMIT();
    }
    {
        char* xbase = smc + UV_X;
        int m = tid & 127, khalf = tid >> 7;
#pragma unroll
        for (int k2 = 0; k2 < 32; k2++) {
            int k = khalf * 64 + k2 * 2;
            int kl = k & 63;
            float x0 = X[(size_t)k * N_ + n0 + m];
            float x1 = X[(size_t)(k + 1) * N_ + n0 + m];
            uint32_t off = (uint32_t)((m >> 3) * 1024 + (m & 7) * 128 +
                                      ((kl * 2) ^ ((m & 7) << 4)));
            char* dst = xbase + khalf * 16384;
            *(uint32_t*)(dst + off) = pack_h2(x0, x1);
        }
    }
    CP_WAIT0();
    __syncthreads();

    const int g = lane >> 3, lr = lane & 7;
    const int wrow = warp_cg * 32 + (g & 1) * 8 + lr;
    const int xrow = warp_mg * 64 + (g >> 1) * 8 + lr;
    const int wkb0 = (g >> 1) * 16;
    const int xkb0 = (g & 1) * 16;
    const uint32_t sX = sb + UV_X;

    for (int ct = 0; ct < 8; ct++) {
        const int s = ct & 1;
        if (ct + 1 < 8) {
            const uint4* src = (const uint4*)wimg + (ct + 1) * 2048;
            uint32_t dst = sb + UV_W(s ^ 1);
#pragma unroll
            for (int it = 0; it < 8; it++)
                cp_async16(dst + (it * 256 + tid) * 16, src + it * 256 + tid);
            CP_COMMIT();
        }
        const uint32_t sW = sb + UV_W(s);
        float acc[2][8][4];
#pragma unroll
        for (int a = 0; a < 2; a++)
#pragma unroll
            for (int q = 0; q < 8; q++)
#pragma unroll
                for (int j = 0; j < 4; j++) acc[a][q][j] = 0.0f;
#pragma unroll
        for (int kc = 0; kc < 2; kc++) {
#pragma unroll
            for (int ks = 0; ks < 4; ks++) {
                uint32_t Wf[2][4], Xf[4][4];
#pragma unroll
                for (int ct2 = 0; ct2 < 2; ct2++) {
                    int cr = wrow + ct2 * 16;
                    uint32_t ro = (uint32_t)((cr >> 3) * 1024 + (cr & 7) * 128);
                    uint32_t kb = (uint32_t)((ks * 32 + wkb0) ^ ((cr & 7) << 4));
                    ldm_x4(Wf[ct2], sW + kc * 16384 + ro + kb);
                }
#pragma unroll
                for (int np = 0; np < 4; np++) {
                    int mr = xrow + np * 16;
                    uint32_t ro = (uint32_t)((mr >> 3) * 1024 + (mr & 7) * 128);
                    uint32_t kb = (uint32_t)((ks * 32 + xkb0) ^ ((mr & 7) << 4));
                    ldm_x4(Xf[np], sX + kc * 16384 + ro + kb);
                }
#pragma unroll
                for (int ct2 = 0; ct2 < 2; ct2++)
#pragma unroll
                    for (int np = 0; np < 4; np++) {
                        mma16816h(acc[ct2][np * 2],     Wf[ct2], &Xf[np][0]);
                        mma16816h(acc[ct2][np * 2 + 1], Wf[ct2], &Xf[np][2]);
                    }
            }
        }
#pragma unroll
        for (int ct2 = 0; ct2 < 2; ct2++) {
#pragma unroll
            for (int j = 0; j < 4; j++) {
                int c_g = ct * 128 + warp_cg * 32 + ct2 * 16 + (lane >> 2) + (j >> 1) * 8;
                float* orow = out + (size_t)c_g * N_ + n0;
#pragma unroll
                for (int q = 0; q < 8; q++) {
                    int m_loc = warp_mg * 64 + q * 8 + (lane & 3) * 2 + (j & 1);
                    orow[m_loc] = acc[ct2][q][j];
                }
            }
        }
        CP_WAIT0();
        __syncthreads();
    }
}

// ---------------- fused mid on fp16 HMMA, smem-staged gather -----------------
#define FM_X     0
#define FM_W(s)  (16384 + (s) * 16384)
#define FM_VG    49152
#define FM_U     115200
#define FM_RED   119808
#define FM_SIDX  121856
#define FM_SMEM  122368

__global__ __launch_bounds__(256, 1) void fused_mid_hmma(
    const float* __restrict__ t1, const float* __restrict__ psc,
    const float* __restrict__ psh, const unsigned int* __restrict__ wimg,
    const float* __restrict__ bias1, const float* __restrict__ pos_b2,
    const float* __restrict__ u, const __half* __restrict__ vt,
    const int* __restrict__ idx, __half* __restrict__ h,
    __half* __restrict__ pe, float* __restrict__ part) {
    extern __shared__ char smc[];
    const uint32_t sb = smem_u32(smc);
    const int tid = threadIdx.x, lane = tid & 31, wid = tid >> 5;
    const int b = blockIdx.y, m0 = blockIdx.x * 128;
    const int warp_cg = wid >> 1;
    const int warp_mg = wid & 1;

    int* sidx = (int*)(smc + FM_SIDX);
    float* vgs = (float*)(smc + FM_VG);
    float* us  = (float*)(smc + FM_U);
    float* redS = (float*)(smc + FM_RED);
    float* redQ = redS + 256;

    if (tid < 128) sidx[tid] = idx[((size_t)b * N_ + (m0 >> 4)) * K_ + tid];

    {
        const uint4* src = (const uint4*)wimg;
        uint32_t dst = sb + FM_W(0);
#pragma unroll
        for (int it = 0; it < 4; it++)
            cp_async16(dst + (it * 256 + tid) * 16, src + it * 256 + tid);
        CP_COMMIT();
    }
    {
        const float* tb = t1 + (size_t)b * PH_ * M_ + m0;
        char* xd = smc + FM_X;
        int m = tid & 127, khalf = tid >> 7;
#pragma unroll
        for (int k2 = 0; k2 < 16; k2++) {
            int k = khalf * 32 + k2 * 2;
            float x0 = tb[(size_t)k * M_ + m];
            float x1 = tb[(size_t)(k + 1) * M_ + m];
            x0 = fmaxf(x0 * psc[k] + psh[k], 0.f);
            x1 = fmaxf(x1 * psc[k + 1] + psh[k + 1], 0.f);
            uint32_t off = (uint32_t)((m >> 3) * 1024 + (m & 7) * 128 +
                                      ((k * 2) ^ ((m & 7) << 4)));
            *(uint32_t*)(xd + off) = pack_h2(x0, x1);
        }
    }
    CP_WAIT0();
    __syncthreads();

    const int g = lane >> 3, lr = lane & 7;
    const int wrow = warp_cg * 32 + (g & 1) * 8 + lr;
    const int xrow = warp_mg * 64 + (g >> 1) * 8 + lr;
    const int wkb0 = (g >> 1) * 16;
    const int xkb0 = (g & 1) * 16;
    const uint32_t sX = sb + FM_X;
    const __half* vtb = vt + (size_t)b * N_ * AH_;
    const int n0 = m0 >> 4;

    for (int ct = 0; ct < 10; ct++) {
        const int s = ct & 1;
        if (ct + 1 < 10) {
            const uint4* src = (const uint4*)wimg + (ct + 1) * 1024;
            uint32_t dst = sb + FM_W(s ^ 1);
#pragma unroll
            for (int it = 0; it < 4; it++)
                cp_async16(dst + (it * 256 + tid) * 16, src + it * 256 + tid);
            CP_COMMIT();
        }
        if (ct < 8) {
#pragma unroll
            for (int jj = 0; jj < 16; jj++) {
                int j = wid * 16 + jj;
                const __half* row = vtb + (size_t)sidx[j] * AH_ + ct * 128;
#pragma unroll
                for (int cc = 0; cc < 2; cc++) {
                    int c = cc * 64 + lane * 2;
                    float2 f = __half22float2(*(const __half2*)(row + c));
                    vgs[c * 129 + j] = f.x;
                    vgs[(c + 1) * 129 + j] = f.y;
                }
            }
#pragma unroll
            for (int it = 0; it < 4; it++) {
                int e = it * 256 + tid;
                int c = e >> 3, nn = e & 7;
                us[c * 9 + nn] = u[((size_t)b * AH_ + ct * 128 + c) * N_ + n0 + nn]
                               + bias1[ct * 128 + c];
            }
        }
        const uint32_t sW = sb + FM_W(s);
        float acc[2][8][4];
#pragma unroll
        for (int a = 0; a < 2; a++)
#pragma unroll
            for (int q = 0; q < 8; q++)
#pragma unroll
                for (int j = 0; j < 4; j++) acc[a][q][j] = 0.0f;
#pragma unroll
        for (int ks = 0; ks < 4; ks++) {
            uint32_t Wf[2][4], Xf[4][4];
#pragma unroll
            for (int ct2 = 0; ct2 < 2; ct2++) {
                int cr = wrow + ct2 * 16;
                uint32_t ro = (uint32_t)((cr >> 3) * 1024 + (cr & 7) * 128);
                uint32_t kb = (uint32_t)((ks * 32 + wkb0) ^ ((cr & 7) << 4));
                ldm_x4(Wf[ct2], sW + ro + kb);
            }
#pragma unroll
            for (int np = 0; np < 4; np++) {
                int mr = xrow + np * 16;
                uint32_t ro = (uint32_t)((mr >> 3) * 1024 + (mr & 7) * 128);
                uint32_t kb = (uint32_t)((ks * 32 + xkb0) ^ ((mr & 7) << 4));
                ldm_x4(Xf[np], sX + ro + kb);
            }
#pragma unroll
            for (int ct2 = 0; ct2 < 2; ct2++)
#pragma unroll
                for (int np = 0; np < 4; np++) {
                    mma16816h(acc[ct2][np * 2],     Wf[ct2], &Xf[np][0]);
                    mma16816h(acc[ct2][np * 2 + 1], Wf[ct2], &Xf[np][2]);
                }
        }
        if (ct < 8) {
            __syncthreads();
            float sS[2][2], sQ[2][2];
#pragma unroll
            for (int a = 0; a < 2; a++) { sS[a][0] = sS[a][1] = 0.f; sQ[a][0] = sQ[a][1] = 0.f; }
#pragma unroll
            for (int ct2 = 0; ct2 < 2; ct2++) {
#pragma unroll
                for (int rh = 0; rh < 2; rh++) {
                    int c_loc = warp_cg * 32 + ct2 * 16 + (lane >> 2) + rh * 8;
                    int c_g = ct * 128 + c_loc;
                    __half* hrow = h + ((size_t)b * AH_ + c_g) * M_ + m0;
#pragma unroll
                    for (int q = 0; q < 8; q++) {
                        int m_loc = warp_mg * 64 + q * 8 + (lane & 3) * 2;
                        float base = us[c_loc * 9 + (m_loc >> 4)];
                        float v0 = acc[ct2][q][rh * 2]     + base - vgs[c_loc * 129 + m_loc];
                        float v1 = acc[ct2][q][rh * 2 + 1] + base - vgs[c_loc * 129 + m_loc + 1];
                        *(__half2*)(hrow + m_loc) = __floats2half2_rn(v0, v1);
                        sS[ct2][rh] += v0 + v1;
                        sQ[ct2][rh] += v0 * v0 + v1 * v1;
                    }
                }
            }
#pragma unroll
            for (int ct2 = 0; ct2 < 2; ct2++)
#pragma unroll
                for (int rh = 0; rh < 2; rh++) {
                    float s1 = sS[ct2][rh], q1 = sQ[ct2][rh];
                    s1 += __shfl_xor_sync(0xffffffffu, s1, 1);
                    s1 += __shfl_xor_sync(0xffffffffu, s1, 2);
                    q1 += __shfl_xor_sync(0xffffffffu, q1, 1);
                    q1 += __shfl_xor_sync(0xffffffffu, q1, 2);
                    if ((lane & 3) == 0) {
                        int c_loc = warp_cg * 32 + ct2 * 16 + (lane >> 2) + rh * 8;
                        redS[c_loc * 2 + warp_mg] = s1;
                        redQ[c_loc * 2 + warp_mg] = q1;
                    }
                }
            __syncthreads();
            if (tid < 128) {
                float ss = redS[tid * 2] + redS[tid * 2 + 1];
                float qq = redQ[tid * 2] + redQ[tid * 2 + 1];
                size_t po = (((size_t)b * 512 + blockIdx.x) * AH_ + ct * 128 + tid) * 2;
                part[po] = ss; part[po + 1] = qq;
            }
        } else {
#pragma unroll
            for (int ct2 = 0; ct2 < 2; ct2++) {
#pragma unroll
                for (int rh = 0; rh < 2; rh++) {
                    int c_pe = (ct - 8) * 128 + warp_cg * 32 + ct2 * 16 + (lane >> 2) + rh * 8;
                    float bv = pos_b2[c_pe];
                    __half* prow = pe + ((size_t)b * DIM_ + c_pe) * M_ + m0;
#pragma unroll
                    for (int q = 0; q < 8; q++) {
                        int m_loc = warp_mg * 64 + q * 8 + (lane & 3) * 2;
                        *(__half2*)(prow + m_loc) =
                            __floats2half2_rn(acc[ct2][q][rh * 2] + bv,
                                              acc[ct2][q][rh * 2 + 1] + bv);
                    }
                }
            }
        }
        CP_WAIT0();
        __syncthreads();
    }
}

// ---------------- attn GEMM2 (fp16 HMMA, fp16 h/pe) --------------------------
// A fp16 2x16K (0,16K) | B fp16 2x32K (32K,64K) | h staging 16K (96K) = 112K
#define A_OFF(s)  ((s) * 16384)
#define B_OFF(s)  (32768 + (s) * 32768)
#define STG_OFF   98304
#define SMEM_ATT2 135168   // epilogue pes region needs 135168

__device__ __forceinline__ void attn2_cpasync(uint32_t sb, int s, int cq,
                                              const __half* hbase, const uint4* w2img,
                                              int tid) {
    const uint4* src = w2img + (size_t)cq * 2048;
    uint32_t bdst = sb + B_OFF(s);
#pragma unroll
    for (int it = 0; it < 8; it++) {
        int i = it * 256 + tid;
        cp_async16(bdst + i * 16, src + i);
    }
    // h: 64 k-rows x 128 m halves = 256B/row, 16 chunks/row, 1024 chunks
#pragma unroll
    for (int it = 0; it < 4; it++) {
        int ch = it * 256 + tid;
        int krow = ch >> 4, off = ch & 15;
        const __half* srcr = hbase + (size_t)(cq * 64 + krow) * M_ + off * 8;
        cp_async16(sb + STG_OFF + krow * 256 + off * 16, srcr);
    }
}

__device__ __forceinline__ void attn2_convert(char* smc, int s, int cq,
                                              const float* __restrict__ scale,
                                              const float* __restrict__ shift,
                                              int wid, int lane) {
    const __half* stg = (const __half*)(smc + STG_OFF);
    char* dst = smc + A_OFF(s);
#pragma unroll
    for (int g2 = 0; g2 < 2; g2++) {
        int base_k = wid * 8 + g2 * 4;
        float X[4][4];
#pragma unroll
        for (int r = 0; r < 4; r++) {
            uint2 raw = *(const uint2*)&stg[(base_k + r) * 128 + lane * 4];
            float2 f01 = __half22float2(*(__half2*)&raw.x);
            float2 f23 = __half22float2(*(__half2*)&raw.y);
            float sc = scale[cq * 64 + base_k + r];
            float sh = shift[cq * 64 + base_k + r];
            X[0][r] = fmaxf(f01.x * sc + sh, 0.f);
            X[1][r] = fmaxf(f01.y * sc + sh, 0.f);
            X[2][r] = fmaxf(f23.x * sc + sh, 0.f);
            X[3][r] = fmaxf(f23.y * sc + sh, 0.f);
        }
#pragma unroll
        for (int mm = 0; mm < 4; mm++) {
            int m = lane * 4 + mm;
            uint32_t off = (uint32_t)((m >> 3) * 1024 + (m & 7) * 128 +
                                      ((base_k * 2) ^ ((m & 7) << 4)));
            *(uint2*)(dst + off) = make_uint2(pack_h2(X[mm][0], X[mm][1]),
                                              pack_h2(X[mm][2], X[mm][3]));
        }
    }
}

__global__ __launch_bounds__(256, 1) void attn2_hmma_kernel(
    const uint4* __restrict__ w2img, const __half* __restrict__ h,
    const float* __restrict__ scale, const float* __restrict__ shift,
    const __half* __restrict__ pe, const float* __restrict__ vf,
    float* __restrict__ agg) {
    extern __shared__ char smc[];
    const uint32_t sb = smem_u32(smc);
    const int tid = threadIdx.x, lane = tid & 31, wid = tid >> 5;
    const int b = blockIdx.y, m0 = blockIdx.x * 128;
    const int warp_m = wid >> 2, warp_c = wid & 3;

    const __half* hbase = h + (size_t)b * AH_ * M_ + m0;

    float acc[4][8][4];
#pragma unroll
    for (int mt = 0; mt < 4; mt++)
#pragma unroll
        for (int nt = 0; nt < 8; nt++)
#pragma unroll
            for (int j = 0; j < 4; j++) acc[mt][nt][j] = 0.0f;

    const int g = lane >> 3, lr = lane & 7;
    const int amr  = warp_m * 64 + (g & 1) * 8 + lr;
    const int bcr  = warp_c * 64 + (g >> 1) * 8 + lr;
    const int akb0 = (g >> 1) * 16;
    const int bkb0 = (g & 1) * 16;

    attn2_cpasync(sb, 0, 0, hbase, w2img, tid);
    CP_COMMIT();
    CP_WAIT0();
    __syncthreads();
    attn2_convert(smc, 0, 0, scale, shift, wid, lane);
    __syncthreads();

    for (int cq = 0; cq < 16; cq++) {
        const int s = cq & 1;
        if (cq + 1 < 16) {
            attn2_cpasync(sb, s ^ 1, cq + 1, hbase, w2img, tid);
            CP_COMMIT();
        }
        const uint32_t sA = sb + A_OFF(s);
        const uint32_t sB = sb + B_OFF(s);
#pragma unroll
        for (int ks = 0; ks < 4; ks++) {
            uint32_t Af[4][4], Bf[4][4];
#pragma unroll
            for (int mt = 0; mt < 4; mt++) {
                int m = amr + mt * 16;
                uint32_t ro = (uint32_t)((m >> 3) * 1024 + (m & 7) * 128);
                uint32_t kb = (uint32_t)((ks * 32 + akb0) ^ ((m & 7) << 4));
                ldm_x4(Af[mt], sA + ro + kb);
            }
#pragma unroll
            for (int np = 0; np < 4; np++) {
                int c = bcr + np * 16;
                uint32_t ro = (uint32_t)((c >> 3) * 1024 + (c & 7) * 128);
                uint32_t kb = (uint32_t)((ks * 32 + bkb0) ^ ((c & 7) << 4));
                ldm_x4(Bf[np], sB + ro + kb);
            }
#pragma unroll
            for (int mt = 0; mt < 4; mt++)
#pragma unroll
                for (int np = 0; np < 4; np++) {
                    mma16816h(acc[mt][np * 2],     Af[mt], &Bf[np][0]);
                    mma16816h(acc[mt][np * 2 + 1], Af[mt], &Bf[np][2]);
                }
        }
        if (cq + 1 < 16) {
            CP_WAIT0();
            __syncthreads();
            attn2_convert(smc, s ^ 1, cq + 1, scale, shift, wid, lane);
            __syncthreads();
        }
    }
    __syncthreads();

    // epilogue: stage pe tile (fp16 -> fp32 smem, c=256 rows x m=128, stride 132)
    float* pes = (float*)smc;
    for (int i = tid; i < 256 * 32; i += 256) {
        int row = i >> 5, q = i & 31;
        uint2 raw = *(const uint2*)(pe + ((size_t)(b * DIM_ + row)) * M_ + m0 + q * 4);
        float2 f01 = __half22float2(*(__half2*)&raw.x);
        float2 f23 = __half22float2(*(__half2*)&raw.y);
        float* d = &pes[row * 132 + q * 4];
        d[0] = f01.x; d[1] = f01.y; d[2] = f23.x; d[3] = f23.y;
    }
    __syncthreads();

#pragma unroll
    for (int mt = 0; mt < 4; mt++) {
        const int mbase = warp_m * 64 + mt * 16;
        const int n = (m0 + mbase) >> 4;
        const int r = lane >> 2;
#pragma unroll
        for (int nt = 0; nt < 8; nt++) {
#pragma unroll
            for (int j = 0; j < 2; j++) {
                int c = warp_c * 64 + nt * 8 + (lane & 3) * 2 + j;
                float v0 = acc[mt][nt][j], v1 = acc[mt][nt][2 + j];
                float mx = fmaxf(v0, v1);
                mx = fmaxf(mx, __shfl_xor_sync(0xffffffffu, mx, 4));
                mx = fmaxf(mx, __shfl_xor_sync(0xffffffffu, mx, 8));
                mx = fmaxf(mx, __shfl_xor_sync(0xffffffffu, mx, 16));
                float e0 = __expf(v0 - mx), e1 = __expf(v1 - mx);
                float se = e0 + e1;
                se += __shfl_xor_sync(0xffffffffu, se, 4);
                se += __shfl_xor_sync(0xffffffffu, se, 8);
                se += __shfl_xor_sync(0xffffffffu, se, 16);
                float p0 = pes[c * 132 + mbase + r];
                float p1 = pes[c * 132 + mbase + r + 8];
                float t = e0 * p0 + e1 * p1;
                t += __shfl_xor_sync(0xffffffffu, t, 4);
                t += __shfl_xor_sync(0xffffffffu, t, 8);
                t += __shfl_xor_sync(0xffffffffu, t, 16);
                if (r == 0) {
                    size_t o = ((size_t)(b * DIM_ + c)) * N_ + n;
                    agg[o] = vf[o] + t / se;
                }
            }
        }
    }
}

// ---------------- launch ----------------------------------------------------
extern "C" void kernel_launch(void* const* d_in, const int* in_sizes, int n_in,
                              void* d_out, int out_size) {
    const float* pos     = (const float*)d_in[0];
    const float* key     = (const float*)d_in[1];
    const float* query   = (const float*)d_in[2];
    const float* mlpv_w1 = (const float*)d_in[3];
    const float* mlpv_b1 = (const float*)d_in[4];
    const float* mlpv_w2 = (const float*)d_in[5];
    const float* mlpv_b2 = (const float*)d_in[6];
    const float* mlpv_ws = (const float*)d_in[7];
    const float* mlpv_bs = (const float*)d_in[8];
    const float* wk      = (const float*)d_in[9];
    const float* bk      = (const float*)d_in[10];
    const float* wq      = (const float*)d_in[11];
    const float* bq      = (const float*)d_in[12];
    const float* wv      = (const float*)d_in[13];
    const float* bv      = (const float*)d_in[14];
    const float* pos_w1  = (const float*)d_in[15];
    const float* pos_b1  = (const float*)d_in[16];
    const float* pos_g1  = (const float*)d_in[17];
    const float* pos_be1 = (const float*)d_in[18];
    const float* pos_w2  = (const float*)d_in[19];
    const float* pos_b2  = (const float*)d_in[20];
    const float* att_w1  = (const float*)d_in[21];
    const float* att_b1  = (const float*)d_in[22];
    const float* att_g1  = (const float*)d_in[23];
    const float* att_be1 = (const float*)d_in[24];
    const float* att_w2  = (const float*)d_in[25];
    const float* we      = (const float*)d_in[27];
    const float* be      = (const float*)d_in[28];
    float* out = (float*)d_out;

    void* p;
#define GETP(sym, var) cudaGetSymbolAddress(&p, sym); float* var = (float*)p;
    GETP(g_x, x_)       GETP(g_t, t_)       GETP(g_value, val)
    GETP(g_vf, vf_)     GETP(g_u, u_)       GETP(g_v, v_)
    GETP(g_t1, t1_)
    GETP(g_agg, agg)    GETP(g_part, part)  GETP(g_partp, partp)
    GETP(g_Wuq, Wuq)    GETP(g_Wvk, Wvk)    GETP(g_bias1, bias1)
    GETP(g_scp, scp)    GETP(g_shp, shp)    GETP(g_sca, sca)
    GETP(g_sha, sha)
#undef GETP
    cudaGetSymbolAddress(&p, g_idx);      int* idx = (int*)p;
    cudaGetSymbolAddress(&p, g_vt);       __half* vt_ = (__half*)p;
    cudaGetSymbolAddress(&p, g_pe);       __half* pe_ = (__half*)p;
    cudaGetSymbolAddress(&p, g_h);        __half* h_ = (__half*)p;
    cudaGetSymbolAddress(&p, g_w2img);    unsigned int* w2img = (unsigned int*)p;
    cudaGetSymbolAddress(&p, g_wmidimg);  unsigned int* wmidimg = (unsigned int*)p;
    cudaGetSymbolAddress(&p, g_wuqimg);   unsigned int* wuqimg = (unsigned int*)p;
    cudaGetSymbolAddress(&p, g_wvkimg);   unsigned int* wvkimg = (unsigned int*)p;

    // --- precompute folded weights + weight images ---
    smallmm_kernel<<<(AH_ * C_ + 255) / 256, 256>>>(att_w1, wq, Wuq, AH_, DIM_, C_, 0);
    smallmm_kernel<<<(AH_ * C_ + 255) / 256, 256>>>(att_w1, wk, Wvk, AH_, DIM_, C_, 0);
    bias1_kernel<<<(AH_ + 255) / 256, 256>>>(att_w1, bq, bk, pos_b2, att_b1, bias1);
    prep_w2_kernel<<<(256 * 256) / 256, 256>>>(att_w2, w2img);
    prep_wmid_kernel<<<(1280 * 16 + 255) / 256, 256>>>(att_w1, pos_w2, wmidimg);
    prep_wuv_kernel<<<(AH_ * 32 + 255) / 256, 256>>>(Wuq, wuqimg);
    prep_wuv_kernel<<<(AH_ * 32 + 255) / 256, 256>>>(Wvk, wvkimg);

    // --- front end ---
    concat_kernel<<<(unsigned)(((size_t)B_ * 2 * C_ * N_ + 255) / 256), 256>>>(key, query, x_);
    knn_kernel<<<dim3(N_ / 256, B_), 256>>>(pos, idx);
    sgemm_kernel<1><<<dim3(N_ / 128, C_ / 128, B_), 256>>>(mlpv_w1, x_, mlpv_b1, t_, nullptr, C_, 2 * C_, N_);
    sgemm_kernel<0><<<dim3(N_ / 128, C_ / 128, B_), 256>>>(mlpv_w2, t_, mlpv_b2, val, nullptr, C_, C_, N_);
    sgemm_kernel<2><<<dim3(N_ / 128, C_ / 128, B_), 256>>>(mlpv_ws, x_, mlpv_bs, val, nullptr, C_, 2 * C_, N_);
    sgemm_kernel<0><<<dim3(N_ / 128, DIM_ / 128, B_), 256>>>(wv, val, bv, vf_, nullptr, DIM_, C_, N_);

    // --- u/v on fp16 HMMA ---
    cudaFuncSetAttribute(uv_hmma, cudaFuncAttributeMaxDynamicSharedMemorySize, UV_SMEM);
    uv_hmma<<<dim3(N_ / 128, 4), 256, UV_SMEM>>>(query, key, wuqimg, wvkimg, u_, v_);
    transpose_bt<<<dim3(N_ / 32, AH_ / 32, B_), dim3(32, 8)>>>(v_, vt_);

    // --- pos_rel conv1 + pos BN ---
    posrel_kernel<<<(unsigned)(((size_t)B_ * PH_ * M_) / 256), 256>>>(pos, idx, pos_w1, pos_b1, t1_, partp);
    finalize_stats<<<PH_, 256>>>(partp, 512, 1, 512, pos_g1, pos_be1, scp, shp, (float)((size_t)B_ * M_));

    // --- fused mid on fp16 HMMA with smem-staged gather (fp16 h/pe out) ---
    cudaFuncSetAttribute(fused_mid_hmma, cudaFuncAttributeMaxDynamicSharedMemorySize, FM_SMEM);
    fused_mid_hmma<<<dim3(M_ / 128, B_), 256, FM_SMEM>>>(
        t1_, scp, shp, wmidimg, bias1, pos_b2, u_, vt_, idx, h_, pe_, part);
    finalize_stats<<<AH_, 256>>>(part, B_ * 512, AH_, 1, att_g1, att_be1, sca, sha, (float)((size_t)B_ * M_));

    // --- big GEMM2: fp16 HMMA on fp16 h + softmax + aggregation ---
    cudaFuncSetAttribute(attn2_hmma_kernel, cudaFuncAttributeMaxDynamicSharedMemorySize, SMEM_ATT2);
    attn2_hmma_kernel<<<dim3(M_ / 128, B_), 256, SMEM_ATT2>>>(
        (const uint4*)w2img, h_, sca, sha, pe_, vf_, agg);

    // --- final projection + residual ---
    sgemm_kernel<4><<<dim3(N_ / 128, C_ / 128, B_), 256>>>(we, agg, be, out, val, C_, DIM_, N_);
}

// round 14
// speedup vs baseline: 1.2651x; 1.0069x over previous
#include <cuda_runtime.h>
#include <cuda_bf16.h>
#include <cuda_fp16.h>
#include <math.h>
#include <stdint.h>

#define B_   2
#define C_   128
#define N_   4096
#define K_   16
#define DIM_ 256
#define PH_  64
#define AH_  1024
#define M_   (N_ * K_)          // 65536 columns per batch in (n,k) space

// ---------------- scratch ---------------------------------------------------
__device__ float g_x    [(size_t)B_ * 2 * C_ * N_];
__device__ float g_t    [(size_t)B_ * C_ * N_];
__device__ float g_value[(size_t)B_ * C_ * N_];
__device__ float g_vf   [(size_t)B_ * DIM_ * N_];
__device__ float g_u    [(size_t)B_ * AH_ * N_];
__device__ __half g_vt  [(size_t)B_ * N_ * AH_];       // v transposed (fp16)
__device__ int   g_idx  [(size_t)B_ * N_ * K_];
__device__ float g_t1   [(size_t)B_ * PH_ * M_];
__device__ __half g_h   [(size_t)B_ * AH_ * M_];       // h (fp16, c-major)
__device__ float g_agg  [(size_t)B_ * DIM_ * N_];
__device__ float g_part [(size_t)B_ * 512 * AH_ * 2];
__device__ float g_partp[(size_t)PH_ * 512 * 2];
__device__ float g_Wuq  [AH_ * C_];
__device__ float g_Wvk  [AH_ * C_];
__device__ float g_bias1[AH_];
__device__ float g_scp  [PH_];
__device__ float g_shp  [PH_];
__device__ float g_sca  [AH_];
__device__ float g_sha  [AH_];
// fp16 image of att_w2: 16 K-chunks x 32KB = 512KB
__device__ unsigned int g_w2img[16 * 32768 / 4];
// fp16 image of Wmid = concat(att_w1@pos_w2, pos_w2): 10 chunks x 16KB
__device__ unsigned int g_wmidimg[10 * 16384 / 4];
// fp16 images of Wuq/Wvk: 8 c-chunks x 32KB (2 kc x 16KB)
__device__ unsigned int g_wuqimg[8 * 32768 / 4];
__device__ unsigned int g_wvkimg[8 * 32768 / 4];

// ---------------- helpers ---------------------------------------------------
__device__ __forceinline__ uint32_t smem_u32(const void* p) {
    uint32_t a;
    asm("{ .reg .u64 t; cvta.to.shared.u64 t, %1; cvt.u32.u64 %0, t; }" : "=r"(a) : "l"(p));
    return a;
}
#define SWZ128(b) ((b) ^ (((b) >> 3) & 0x70))
__device__ __forceinline__ uint32_t pack_h2(float a, float b) {
    __half2 t = __floats2half2_rn(a, b);
    return *reinterpret_cast<uint32_t*>(&t);
}
__device__ __forceinline__ void ldm_x4(uint32_t* r, uint32_t addr) {
    asm volatile("ldmatrix.sync.aligned.m8n8.x4.shared.b16 {%0,%1,%2,%3}, [%4];"
        : "=r"(r[0]), "=r"(r[1]), "=r"(r[2]), "=r"(r[3]) : "r"(addr));
}
__device__ __forceinline__ void mma16816h(float* d, const uint32_t* a, const uint32_t* b) {
    asm volatile(
        "mma.sync.aligned.m16n8k16.row.col.f32.f16.f16.f32 "
        "{%0,%1,%2,%3}, {%4,%5,%6,%7}, {%8,%9}, {%0,%1,%2,%3};"
        : "+f"(d[0]), "+f"(d[1]), "+f"(d[2]), "+f"(d[3])
        : "r"(a[0]), "r"(a[1]), "r"(a[2]), "r"(a[3]), "r"(b[0]), "r"(b[1]));
}
__device__ __forceinline__ void cp_async16(uint32_t dst, const void* src) {
    asm volatile("cp.async.cg.shared.global [%0], [%1], 16;" :: "r"(dst), "l"(src));
}
#define CP_COMMIT() asm volatile("cp.async.commit_group;" ::: "memory")
#define CP_WAIT0()  asm volatile("cp.async.wait_group 0;" ::: "memory")

// ---------------- concat ----------------------------------------------------
__global__ void concat_kernel(const float* __restrict__ key,
                              const float* __restrict__ query,
                              float* __restrict__ x) {
    size_t i = (size_t)blockIdx.x * blockDim.x + threadIdx.x;
    if (i >= (size_t)B_ * 2 * C_ * N_) return;
    int n = (int)(i % N_);
    int c = (int)((i / N_) % (2 * C_));
    int b = (int)(i / ((size_t)N_ * 2 * C_));
    float v;
    if (c < C_) v = key  [((size_t)b * C_ + c) * N_ + n];
    else        v = query[((size_t)b * C_ + (c - C_)) * N_ + n];
    x[i] = v;
}

// ---------------- KNN -------------------------------------------------------
__global__ void knn_kernel(const float* __restrict__ pos, int* __restrict__ idx) {
    const int b = blockIdx.y;
    const int n = blockIdx.x * blockDim.x + threadIdx.x;
    const float* p = pos + (size_t)b * 3 * N_;
    const float qx = p[n], qy = p[N_ + n], qz = p[2 * N_ + n];
    const float qs = qx * qx + qy * qy + qz * qz;
    float bd[K_]; int bi[K_];
#pragma unroll
    for (int j = 0; j < K_; j++) { bd[j] = 3.4e38f; bi[j] = 0; }
    __shared__ float sx[512], sy[512], sz[512], ss[512];
    for (int t0 = 0; t0 < N_; t0 += 512) {
        __syncthreads();
        for (int i = threadIdx.x; i < 512; i += blockDim.x) {
            float x = p[t0 + i], y = p[N_ + t0 + i], z = p[2 * N_ + t0 + i];
            sx[i] = x; sy[i] = y; sz[i] = z; ss[i] = x * x + y * y + z * z;
        }
        __syncthreads();
        for (int i = 0; i < 512; i++) {
            float d = qs + ss[i] - 2.0f * (qx * sx[i] + qy * sy[i] + qz * sz[i]);
            if (d < bd[K_ - 1]) {
                int j = K_ - 1;
                while (j > 0 && d < bd[j - 1]) { bd[j] = bd[j - 1]; bi[j] = bi[j - 1]; j--; }
                bd[j] = d; bi[j] = t0 + i;
            }
        }
    }
    int* op = idx + ((size_t)b * N_ + n) * K_;
#pragma unroll
    for (int j = 0; j < K_; j++) op[j] = bi[j];
}

// ---------------- precompute small products ---------------------------------
__global__ void smallmm_kernel(const float* __restrict__ A, const float* __restrict__ Bm,
                               float* __restrict__ Cc, int O, int Id, int J, int tr) {
    int t = blockIdx.x * 256 + threadIdx.x;
    if (t >= O * J) return;
    int o = t / J, j = t % J;
    float s = 0.0f;
    for (int d = 0; d < Id; d++) s += A[o * Id + d] * Bm[d * J + j];
    if (tr) Cc[j * O + o] = s; else Cc[o * J + j] = s;
}
__global__ void bias1_kernel(const float* __restrict__ w1, const float* __restrict__ bq,
                             const float* __restrict__ bk, const float* __restrict__ pb2,
                             const float* __restrict__ ab1, float* __restrict__ out) {
    int o = blockIdx.x * 256 + threadIdx.x;
    if (o >= AH_) return;
    float s = ab1[o];
    for (int d = 0; d < DIM_; d++) s += w1[o * DIM_ + d] * (bq[d] - bk[d] + pb2[d]);
    out[o] = s;
}

// ---------------- att_w2 -> pre-swizzled fp16 image --------------------------
__global__ void prep_w2_kernel(const float* __restrict__ w2, unsigned int* __restrict__ img) {
    int t = blockIdx.x * 256 + threadIdx.x;
    if (t >= 256 * 256) return;
    int c = t >> 8, k4 = t & 255;
    int k = k4 * 4;
    int q = k >> 6, kl = k & 63;
    const float* src = w2 + (size_t)c * AH_ + k;
    uint32_t off = SWZ128((uint32_t)((c >> 3) * 1024 + (c & 7) * 128 + kl * 2));
    char* base = (char*)img + (size_t)q * 32768;
    *(uint2*)(base + off) = make_uint2(pack_h2(src[0], src[1]), pack_h2(src[2], src[3]));
}

// ---------------- Wmid -> pre-swizzled fp16 image ----------------------------
__global__ void prep_wmid_kernel(const float* __restrict__ att_w1,
                                 const float* __restrict__ pos_w2,
                                 unsigned int* __restrict__ img) {
    int t = blockIdx.x * 256 + threadIdx.x;
    if (t >= 1280 * 16) return;
    int c = t >> 4, k4 = t & 15;
    float f[4];
    if (c < AH_) {
#pragma unroll 4
        for (int kk = 0; kk < 4; kk++) {
            float s = 0.0f;
            for (int d = 0; d < DIM_; d++)
                s += att_w1[(size_t)c * DIM_ + d] * pos_w2[d * PH_ + k4 * 4 + kk];
            f[kk] = s;
        }
    } else {
#pragma unroll
        for (int kk = 0; kk < 4; kk++) f[kk] = pos_w2[(c - AH_) * PH_ + k4 * 4 + kk];
    }
    int ct = c >> 7, cl = c & 127;
    uint32_t off = (uint32_t)((cl >> 3) * 1024 + (cl & 7) * 128 +
                              ((k4 * 8) ^ ((cl & 7) << 4)));
    char* base = (char*)img + (size_t)ct * 16384;
    *(uint2*)(base + off) = make_uint2(pack_h2(f[0], f[1]), pack_h2(f[2], f[3]));
}

// ---------------- Wuq/Wvk [AH][C=128] -> fp16 image: 8 c-chunks x 32KB --------
__global__ void prep_wuv_kernel(const float* __restrict__ W, unsigned int* __restrict__ img) {
    int t = blockIdx.x * 256 + threadIdx.x;
    if (t >= AH_ * 32) return;
    int c = t >> 5, k4 = t & 31;
    int k = k4 * 4;
    int kc = k >> 6, kl = k & 63;
    const float* src = W + (size_t)c * C_ + k;
    int ct = c >> 7, cl = c & 127;
    uint32_t off = (uint32_t)((cl >> 3) * 1024 + (cl & 7) * 128 +
                              ((kl * 2) ^ ((cl & 7) << 4)));
    char* base = (char*)img + (size_t)ct * 32768 + (size_t)kc * 16384;
    *(uint2*)(base + off) = make_uint2(pack_h2(src[0], src[1]), pack_h2(src[2], src[3]));
}

// ---------------- generic fp32 SGEMM (small GEMMs) --------------------------
template <int FLAGS>
__global__ void sgemm_kernel(const float* __restrict__ W, const float* __restrict__ Xg,
                             const float* __restrict__ bias, float* __restrict__ outg,
                             const float* __restrict__ resg, int O, int I, int M) {
    const int b = blockIdx.z;
    const float* X = Xg + (size_t)b * I * M;
    float* out = outg + (size_t)b * O * M;
    const float* res = (FLAGS & 4) ? (resg + (size_t)b * O * M) : nullptr;
    __shared__ float Ws[8][132];
    __shared__ float Xs[8][128];
    const int tid = threadIdx.x;
    const int tx = tid & 15, ty = tid >> 4;
    const int o0 = blockIdx.y * 128, m0 = blockIdx.x * 128;
    const int wr = tid >> 1, wc = (tid & 1) * 4;
    const int xr = tid >> 5, xc = (tid & 31) * 4;
    float acc[8][8];
#pragma unroll
    for (int i = 0; i < 8; i++)
#pragma unroll
        for (int j = 0; j < 8; j++) acc[i][j] = 0.0f;
    for (int kt = 0; kt < I; kt += 8) {
        float4 wv = *(const float4*)&W[(size_t)(o0 + wr) * I + kt + wc];
        float4 xv = *(const float4*)&X[(size_t)(kt + xr) * M + m0 + xc];
        __syncthreads();
        Ws[wc + 0][wr] = wv.x; Ws[wc + 1][wr] = wv.y;
        Ws[wc + 2][wr] = wv.z; Ws[wc + 3][wr] = wv.w;
        *(float4*)&Xs[xr][xc] = xv;
        __syncthreads();
#pragma unroll
        for (int k = 0; k < 8; k++) {
            float a[8], bb[8];
            *(float4*)&a[0]  = *(const float4*)&Ws[k][ty * 8];
            *(float4*)&a[4]  = *(const float4*)&Ws[k][ty * 8 + 4];
            *(float4*)&bb[0] = *(const float4*)&Xs[k][tx * 8];
            *(float4*)&bb[4] = *(const float4*)&Xs[k][tx * 8 + 4];
#pragma unroll
            for (int i = 0; i < 8; i++)
#pragma unroll
                for (int j = 0; j < 8; j++) acc[i][j] += a[i] * bb[j];
        }
    }
#pragma unroll
    for (int i = 0; i < 8; i++) {
        const int o = o0 + ty * 8 + i;
        const float bv = bias[o];
        float* orow = out + (size_t)o * M + m0 + tx * 8;
        const float* rrow = (FLAGS & 4) ? (res + (size_t)o * M + m0 + tx * 8) : nullptr;
#pragma unroll
        for (int jj = 0; jj < 8; jj += 4) {
            float4 v;
            v.x = acc[i][jj + 0] + bv; v.y = acc[i][jj + 1] + bv;
            v.z = acc[i][jj + 2] + bv; v.w = acc[i][jj + 3] + bv;
            if (FLAGS & 1) { v.x = fmaxf(v.x, 0.f); v.y = fmaxf(v.y, 0.f);
                             v.z = fmaxf(v.z, 0.f); v.w = fmaxf(v.w, 0.f); }
            if (FLAGS & 2) { float4 old = *(float4*)&orow[jj];
                             v.x += old.x; v.y += old.y; v.z += old.z; v.w += old.w; }
            if (FLAGS & 4) { float4 r = *(const float4*)&rrow[jj];
                             v.x += r.x; v.y += r.y; v.z += r.z; v.w += r.w; }
            *(float4*)&orow[jj] = v;
        }
    }
}

// ---------------- pos_rel conv1 + BN partial stats ---------------------------
__global__ void posrel_kernel(const float* __restrict__ pos, const int* __restrict__ idx,
                              const float* __restrict__ w, const float* __restrict__ bias,
                              float* __restrict__ t1, float* __restrict__ part) {
    size_t i = (size_t)blockIdx.x * 256 + threadIdx.x;
    int k = (int)(i & 15);
    int n = (int)((i >> 4) & (N_ - 1));
    int c = (int)((i >> 16) & (PH_ - 1));
    int b = (int)(i >> 22);
    int m = idx[(((size_t)b * N_ + n) << 4) + k];
    const float* p = pos + (size_t)b * 3 * N_;
    float rx = p[n] - p[m];
    float ry = p[N_ + n] - p[N_ + m];
    float rz = p[2 * N_ + n] - p[2 * N_ + m];
    float val = w[c * 3] * rx + w[c * 3 + 1] * ry + w[c * 3 + 2] * rz + bias[c];
    t1[i] = val;
    __shared__ float ssum[256], ssq[256];
    ssum[threadIdx.x] = val; ssq[threadIdx.x] = val * val;
    __syncthreads();
    for (int st = 128; st > 0; st >>= 1) {
        if ((int)threadIdx.x < st) {
            ssum[threadIdx.x] += ssum[threadIdx.x + st];
            ssq[threadIdx.x]  += ssq[threadIdx.x + st];
        }
        __syncthreads();
    }
    if (threadIdx.x == 0) {
        int cb = (blockIdx.x >> 8) & (PH_ - 1);
        int bb = blockIdx.x >> 14;
        int sblk = blockIdx.x & 255;
        size_t o = ((size_t)cb * 512 + bb * 256 + sblk) * 2;
        part[o] = ssum[0]; part[o + 1] = ssq[0];
    }
}

// ---------------- BN finalize ------------------------------------------------
__global__ void finalize_stats(const float* __restrict__ part, int P, int ps, int cs,
                               const float* __restrict__ g, const float* __restrict__ be,
                               float* __restrict__ sc, float* __restrict__ sh, float cnt) {
    int c = blockIdx.x;
    double s = 0.0, q = 0.0;
    for (int p = threadIdx.x; p < P; p += blockDim.x) {
        size_t o = ((size_t)p * ps + (size_t)c * cs) * 2;
        s += (double)part[o]; q += (double)part[o + 1];
    }
    __shared__ double S[256], Q[256];
    S[threadIdx.x] = s; Q[threadIdx.x] = q;
    __syncthreads();
    for (int st = 128; st > 0; st >>= 1) {
        if ((int)threadIdx.x < st) {
            S[threadIdx.x] += S[threadIdx.x + st];
            Q[threadIdx.x] += Q[threadIdx.x + st];
        }
        __syncthreads();
    }
    if (threadIdx.x == 0) {
        double mean = S[0] / (double)cnt;
        double var  = Q[0] / (double)cnt - mean * mean;
        float scv = g[c] * (float)(1.0 / sqrt(var + 1e-5));
        sc[c] = scv;
        sh[c] = be[c] - (float)mean * scv;
    }
}

// ---------------- u/v GEMM on fp16 HMMA (v written transposed fp16) ----------
#define UV_X     0
#define UV_W(s)  (32768 + (s) * 32768)
#define UV_TR    98304
#define UV_SMEM  133120

__global__ __launch_bounds__(256) void uv_hmma(
    const float* __restrict__ query, const float* __restrict__ key,
    const unsigned int* __restrict__ wuqimg, const unsigned int* __restrict__ wvkimg,
    float* __restrict__ ug, __half* __restrict__ vt) {
    extern __shared__ char smc[];
    const uint32_t sb = smem_u32(smc);
    const int tid = threadIdx.x, lane = tid & 31, wid = tid >> 5;
    const int z = blockIdx.y;
    const int b = z & 1, which = z >> 1;
    const int n0 = blockIdx.x * 128;
    const float* X = (which == 0 ? query : key) + (size_t)b * C_ * N_;
    const unsigned int* wimg = (which == 0 ? wuqimg : wvkimg);
    float* uout = ug + (size_t)b * AH_ * N_;
    const int warp_cg = wid >> 1;
    const int warp_mg = wid & 1;

    {
        const uint4* src = (const uint4*)wimg;
        uint32_t dst = sb + UV_W(0);
#pragma unroll
        for (int it = 0; it < 8; it++)
            cp_async16(dst + (it * 256 + tid) * 16, src + it * 256 + tid);
        CP_COMMIT();
    }
    {
        char* xbase = smc + UV_X;
        int m = tid & 127, khalf = tid >> 7;
#pragma unroll
        for (int k2 = 0; k2 < 32; k2++) {
            int k = khalf * 64 + k2 * 2;
            int kl = k & 63;
            float x0 = X[(size_t)k * N_ + n0 + m];
            float x1 = X[(size_t)(k + 1) * N_ + n0 + m];
            uint32_t off = (uint32_t)((m >> 3) * 1024 + (m & 7) * 128 +
                                      ((kl * 2) ^ ((m & 7) << 4)));
            char* dst = xbase + khalf * 16384;
            *(uint32_t*)(dst + off) = pack_h2(x0, x1);
        }
    }
    CP_WAIT0();
    __syncthreads();

    const int g = lane >> 3, lr = lane & 7;
    const int wrow = warp_cg * 32 + (g & 1) * 8 + lr;
    const int xrow = warp_mg * 64 + (g >> 1) * 8 + lr;
    const int wkb0 = (g >> 1) * 16;
    const int xkb0 = (g & 1) * 16;
    const uint32_t sX = sb + UV_X;

    for (int ct = 0; ct < 8; ct++) {
        const int s = ct & 1;
        if (ct + 1 < 8) {
            const uint4* src = (const uint4*)wimg + (ct + 1) * 2048;
            uint32_t dst = sb + UV_W(s ^ 1);
#pragma unroll
            for (int it = 0; it < 8; it++)
                cp_async16(dst + (it * 256 + tid) * 16, src + it * 256 + tid);
            CP_COMMIT();
        }
        const uint32_t sW = sb + UV_W(s);
        float acc[2][8][4];
#pragma unroll
        for (int a = 0; a < 2; a++)
#pragma unroll
            for (int q = 0; q < 8; q++)
#pragma unroll
                for (int j = 0; j < 4; j++) acc[a][q][j] = 0.0f;
#pragma unroll
        for (int kc = 0; kc < 2; kc++) {
#pragma unroll
            for (int ks = 0; ks < 4; ks++) {
                uint32_t Wf[2][4], Xf[4][4];
#pragma unroll
                for (int ct2 = 0; ct2 < 2; ct2++) {
                    int cr = wrow + ct2 * 16;
                    uint32_t ro = (uint32_t)((cr >> 3) * 1024 + (cr & 7) * 128);
                    uint32_t kb = (uint32_t)((ks * 32 + wkb0) ^ ((cr & 7) << 4));
                    ldm_x4(Wf[ct2], sW + kc * 16384 + ro + kb);
                }
#pragma unroll
                for (int np = 0; np < 4; np++) {
                    int mr = xrow + np * 16;
                    uint32_t ro = (uint32_t)((mr >> 3) * 1024 + (mr & 7) * 128);
                    uint32_t kb = (uint32_t)((ks * 32 + xkb0) ^ ((mr & 7) << 4));
                    ldm_x4(Xf[np], sX + kc * 16384 + ro + kb);
                }
#pragma unroll
                for (int ct2 = 0; ct2 < 2; ct2++)
#pragma unroll
                    for (int np = 0; np < 4; np++) {
                        mma16816h(acc[ct2][np * 2],     Wf[ct2], &Xf[np][0]);
                        mma16816h(acc[ct2][np * 2 + 1], Wf[ct2], &Xf[np][2]);
                    }
            }
        }
        if (which == 0) {
#pragma unroll
            for (int ct2 = 0; ct2 < 2; ct2++) {
#pragma unroll
                for (int j = 0; j < 4; j++) {
                    int c_g = ct * 128 + warp_cg * 32 + ct2 * 16 + (lane >> 2) + (j >> 1) * 8;
                    float* orow = uout + (size_t)c_g * N_ + n0;
#pragma unroll
                    for (int q = 0; q < 8; q++) {
                        int m_loc = warp_mg * 64 + q * 8 + (lane & 3) * 2 + (j & 1);
                        orow[m_loc] = acc[ct2][q][j];
                    }
                }
            }
        } else {
            __half* trs = (__half*)(smc + UV_TR);
#pragma unroll
            for (int ct2 = 0; ct2 < 2; ct2++)
#pragma unroll
                for (int j = 0; j < 4; j++) {
                    int c_loc = warp_cg * 32 + ct2 * 16 + (lane >> 2) + (j >> 1) * 8;
#pragma unroll
                    for (int q = 0; q < 8; q++) {
                        int m_loc = warp_mg * 64 + q * 8 + (lane & 3) * 2 + (j & 1);
                        trs[m_loc * 136 + c_loc] = __float2half(acc[ct2][q][j]);
                    }
                }
            __syncthreads();
            __half* dvt = vt + ((size_t)b * N_ + n0) * AH_ + ct * 128;
#pragma unroll
            for (int it = 0; it < 8; it++) {
                int e = it * 256 + tid;
                int row = e >> 4, col = e & 15;
                *(uint4*)(dvt + (size_t)row * AH_ + col * 8) =
                    *(uint4*)&trs[row * 136 + col * 8];
            }
        }
        CP_WAIT0();
        __syncthreads();
    }
}

// ---------------- fused mid on fp16 HMMA (h only; pe moved to attn2) ---------
#define FM_X     0
#define FM_W(s)  (16384 + (s) * 16384)
#define FM_VG    49152
#define FM_U     82944
#define FM_RED   87552
#define FM_SIDX  89600
#define FM_SMEM  90112

__global__ __launch_bounds__(256) void fused_mid_hmma(
    const float* __restrict__ t1, const float* __restrict__ psc,
    const float* __restrict__ psh, const unsigned int* __restrict__ wimg,
    const float* __restrict__ bias1, const float* __restrict__ u,
    const __half* __restrict__ vt, const int* __restrict__ idx,
    __half* __restrict__ h, float* __restrict__ part) {
    extern __shared__ char smc[];
    const uint32_t sb = smem_u32(smc);
    const int tid = threadIdx.x, lane = tid & 31, wid = tid >> 5;
    const int b = blockIdx.y, m0 = blockIdx.x * 128;
    const int warp_cg = wid >> 1;
    const int warp_mg = wid & 1;

    int* sidx = (int*)(smc + FM_SIDX);
    __half* vgsh = (__half*)(smc + FM_VG);
    float* us  = (float*)(smc + FM_U);
    float* redS = (float*)(smc + FM_RED);
    float* redQ = redS + 256;

    if (tid < 128) sidx[tid] = idx[((size_t)b * N_ + (m0 >> 4)) * K_ + tid];

    {
        const uint4* src = (const uint4*)wimg;
        uint32_t dst = sb + FM_W(0);
#pragma unroll
        for (int it = 0; it < 4; it++)
            cp_async16(dst + (it * 256 + tid) * 16, src + it * 256 + tid);
        CP_COMMIT();
    }
    {
        const float* tb = t1 + (size_t)b * PH_ * M_ + m0;
        char* xd = smc + FM_X;
        int m = tid & 127, khalf = tid >> 7;
#pragma unroll
        for (int k2 = 0; k2 < 16; k2++) {
            int k = khalf * 32 + k2 * 2;
            float x0 = tb[(size_t)k * M_ + m];
            float x1 = tb[(size_t)(k + 1) * M_ + m];
            x0 = fmaxf(x0 * psc[k] + psh[k], 0.f);
            x1 = fmaxf(x1 * psc[k + 1] + psh[k + 1], 0.f);
            uint32_t off = (uint32_t)((m >> 3) * 1024 + (m & 7) * 128 +
                                      ((k * 2) ^ ((m & 7) << 4)));
            *(uint32_t*)(xd + off) = pack_h2(x0, x1);
        }
    }
    CP_WAIT0();
    __syncthreads();

    const int g = lane >> 3, lr = lane & 7;
    const int wrow = warp_cg * 32 + (g & 1) * 8 + lr;
    const int xrow = warp_mg * 64 + (g >> 1) * 8 + lr;
    const int wkb0 = (g >> 1) * 16;
    const int xkb0 = (g & 1) * 16;
    const uint32_t sX = sb + FM_X;
    const __half* vtb = vt + (size_t)b * N_ * AH_;
    const int n0 = m0 >> 4;

    for (int ct = 0; ct < 8; ct++) {
        const int s = ct & 1;
        if (ct + 1 < 8) {
            const uint4* src = (const uint4*)wimg + (ct + 1) * 1024;
            uint32_t dst = sb + FM_W(s ^ 1);
#pragma unroll
            for (int it = 0; it < 4; it++)
                cp_async16(dst + (it * 256 + tid) * 16, src + it * 256 + tid);
            CP_COMMIT();
        }
        {
#pragma unroll
            for (int jj = 0; jj < 16; jj++) {
                int j = wid * 16 + jj;
                const __half* row = vtb + (size_t)sidx[j] * AH_ + ct * 128;
#pragma unroll
                for (int cc = 0; cc < 2; cc++) {
                    int c = cc * 64 + lane * 2;
                    __half2 hv = *(const __half2*)(row + c);
                    vgsh[c * 132 + j] = hv.x;
                    vgsh[(c + 1) * 132 + j] = hv.y;
                }
            }
#pragma unroll
            for (int it = 0; it < 4; it++) {
                int e = it * 256 + tid;
                int c = e >> 3, nn = e & 7;
                us[c * 9 + nn] = u[((size_t)b * AH_ + ct * 128 + c) * N_ + n0 + nn]
                               + bias1[ct * 128 + c];
            }
        }
        const uint32_t sW = sb + FM_W(s);
        float acc[2][8][4];
#pragma unroll
        for (int a = 0; a < 2; a++)
#pragma unroll
            for (int q = 0; q < 8; q++)
#pragma unroll
                for (int j = 0; j < 4; j++) acc[a][q][j] = 0.0f;
#pragma unroll
        for (int ks = 0; ks < 4; ks++) {
            uint32_t Wf[2][4], Xf[4][4];
#pragma unroll
            for (int ct2 = 0; ct2 < 2; ct2++) {
                int cr = wrow + ct2 * 16;
                uint32_t ro = (uint32_t)((cr >> 3) * 1024 + (cr & 7) * 128);
                uint32_t kb = (uint32_t)((ks * 32 + wkb0) ^ ((cr & 7) << 4));
                ldm_x4(Wf[ct2], sW + ro + kb);
            }
#pragma unroll
            for (int np = 0; np < 4; np++) {
                int mr = xrow + np * 16;
                uint32_t ro = (uint32_t)((mr >> 3) * 1024 + (mr & 7) * 128);
                uint32_t kb = (uint32_t)((ks * 32 + xkb0) ^ ((mr & 7) << 4));
                ldm_x4(Xf[np], sX + ro + kb);
            }
#pragma unroll
            for (int ct2 = 0; ct2 < 2; ct2++)
#pragma unroll
                for (int np = 0; np < 4; np++) {
                    mma16816h(acc[ct2][np * 2],     Wf[ct2], &Xf[np][0]);
                    mma16816h(acc[ct2][np * 2 + 1], Wf[ct2], &Xf[np][2]);
                }
        }
        __syncthreads();
        {
            float sS[2][2], sQ[2][2];
#pragma unroll
            for (int a = 0; a < 2; a++) { sS[a][0] = sS[a][1] = 0.f; sQ[a][0] = sQ[a][1] = 0.f; }
#pragma unroll
            for (int ct2 = 0; ct2 < 2; ct2++) {
#pragma unroll
                for (int rh = 0; rh < 2; rh++) {
                    int c_loc = warp_cg * 32 + ct2 * 16 + (lane >> 2) + rh * 8;
                    int c_g = ct * 128 + c_loc;
                    __half* hrow = h + ((size_t)b * AH_ + c_g) * M_ + m0;
#pragma unroll
                    for (int q = 0; q < 8; q++) {
                        int m_loc = warp_mg * 64 + q * 8 + (lane & 3) * 2;
                        float base = us[c_loc * 9 + (m_loc >> 4)];
                        float v0 = acc[ct2][q][rh * 2]     + base
                                 - __half2float(vgsh[c_loc * 132 + m_loc]);
                        float v1 = acc[ct2][q][rh * 2 + 1] + base
                                 - __half2float(vgsh[c_loc * 132 + m_loc + 1]);
                        *(__half2*)(hrow + m_loc) = __floats2half2_rn(v0, v1);
                        sS[ct2][rh] += v0 + v1;
                        sQ[ct2][rh] += v0 * v0 + v1 * v1;
                    }
                }
            }
#pragma unroll
            for (int ct2 = 0; ct2 < 2; ct2++)
#pragma unroll
                for (int rh = 0; rh < 2; rh++) {
                    float s1 = sS[ct2][rh], q1 = sQ[ct2][rh];
                    s1 += __shfl_xor_sync(0xffffffffu, s1, 1);
                    s1 += __shfl_xor_sync(0xffffffffu, s1, 2);
                    q1 += __shfl_xor_sync(0xffffffffu, q1, 1);
                    q1 += __shfl_xor_sync(0xffffffffu, q1, 2);
                    if ((lane & 3) == 0) {
                        int c_loc = warp_cg * 32 + ct2 * 16 + (lane >> 2) + rh * 8;
                        redS[c_loc * 2 + warp_mg] = s1;
                        redQ[c_loc * 2 + warp_mg] = q1;
                    }
                }
            __syncthreads();
            if (tid < 128) {
                float ss = redS[tid * 2] + redS[tid * 2 + 1];
                float qq = redQ[tid * 2] + redQ[tid * 2 + 1];
                size_t po = (((size_t)b * 512 + blockIdx.x) * AH_ + ct * 128 + tid) * 2;
                part[po] = ss; part[po + 1] = qq;
            }
        }
        CP_WAIT0();
        __syncthreads();
    }
}

// ---------------- attn GEMM2 (fp16 HMMA; pe computed in-kernel) --------------
// smem: A 16K @0 | B 2x32K @16K | h stg 16K @80K | pes half 67.6K @96K
#define A2_A      0
#define A2_B(s)   (16384 + (s) * 32768)
#define A2_STG    81920
#define A2_PES    98304
#define SMEM_ATT2 165888

__device__ __forceinline__ void attn2_cpasync(uint32_t sb, int s, int cq,
                                              const __half* hbase, const uint4* w2img,
                                              int tid) {
    const uint4* src = w2img + (size_t)cq * 2048;
    uint32_t bdst = sb + A2_B(s);
#pragma unroll
    for (int it = 0; it < 8; it++) {
        int i = it * 256 + tid;
        cp_async16(bdst + i * 16, src + i);
    }
#pragma unroll
    for (int it = 0; it < 4; it++) {
        int ch = it * 256 + tid;
        int krow = ch >> 4, off = ch & 15;
        const __half* srcr = hbase + (size_t)(cq * 64 + krow) * M_ + off * 8;
        cp_async16(sb + A2_STG + krow * 256 + off * 16, srcr);
    }
}

__device__ __forceinline__ void attn2_convert(char* smc, int cq,
                                              const float* __restrict__ scale,
                                              const float* __restrict__ shift,
                                              int wid, int lane) {
    const __half* stg = (const __half*)(smc + A2_STG);
    char* dst = smc + A2_A;
#pragma unroll
    for (int g2 = 0; g2 < 2; g2++) {
        int base_k = wid * 8 + g2 * 4;
        float X[4][4];
#pragma unroll
        for (int r = 0; r < 4; r++) {
            uint2 raw = *(const uint2*)&stg[(base_k + r) * 128 + lane * 4];
            float2 f01 = __half22float2(*(__half2*)&raw.x);
            float2 f23 = __half22float2(*(__half2*)&raw.y);
            float sc = scale[cq * 64 + base_k + r];
            float sh = shift[cq * 64 + base_k + r];
            X[0][r] = fmaxf(f01.x * sc + sh, 0.f);
            X[1][r] = fmaxf(f01.y * sc + sh, 0.f);
            X[2][r] = fmaxf(f23.x * sc + sh, 0.f);
            X[3][r] = fmaxf(f23.y * sc + sh, 0.f);
        }
#pragma unroll
        for (int mm = 0; mm < 4; mm++) {
            int m = lane * 4 + mm;
            uint32_t off = (uint32_t)((m >> 3) * 1024 + (m & 7) * 128 +
                                      ((base_k * 2) ^ ((m & 7) << 4)));
            *(uint2*)(dst + off) = make_uint2(pack_h2(X[mm][0], X[mm][1]),
                                              pack_h2(X[mm][2], X[mm][3]));
        }
    }
}

__global__ __launch_bounds__(256) void attn2_hmma_kernel(
    const uint4* __restrict__ w2img, const __half* __restrict__ h,
    const float* __restrict__ scale, const float* __restrict__ shift,
    const float* __restrict__ t1, const float* __restrict__ psc,
    const float* __restrict__ psh, const uint4* __restrict__ wmid89,
    const float* __restrict__ pos_b2, const float* __restrict__ vf,
    float* __restrict__ agg) {
    extern __shared__ char smc[];
    const uint32_t sb = smem_u32(smc);
    const int tid = threadIdx.x, lane = tid & 31, wid = tid >> 5;
    const int b = blockIdx.y, m0 = blockIdx.x * 128;
    const int warp_m = wid >> 2, warp_c = wid & 3;

    const __half* hbase = h + (size_t)b * AH_ * M_ + m0;

    const int g = lane >> 3, lr = lane & 7;
    const int amr  = warp_m * 64 + (g & 1) * 8 + lr;
    const int bcr  = warp_c * 64 + (g >> 1) * 8 + lr;
    const int akb0 = (g >> 1) * 16;
    const int bkb0 = (g & 1) * 16;

    float acc[4][8][4];

    // ---- phase 1: compute pe tile into pes smem ----
    {
        {
            uint32_t dst = sb + A2_B(0);
#pragma unroll
            for (int it = 0; it < 8; it++)
                cp_async16(dst + (it * 256 + tid) * 16, wmid89 + it * 256 + tid);
            CP_COMMIT();
        }
        {
            const float* tb = t1 + (size_t)b * PH_ * M_ + m0;
            char* xd = smc + A2_A;
            int m = tid & 127, khalf = tid >> 7;
#pragma unroll
            for (int k2 = 0; k2 < 16; k2++) {
                int k = khalf * 32 + k2 * 2;
                float x0 = tb[(size_t)k * M_ + m];
                float x1 = tb[(size_t)(k + 1) * M_ + m];
                x0 = fmaxf(x0 * psc[k] + psh[k], 0.f);
                x1 = fmaxf(x1 * psc[k + 1] + psh[k + 1], 0.f);
                uint32_t off = (uint32_t)((m >> 3) * 1024 + (m & 7) * 128 +
                                          ((k * 2) ^ ((m & 7) << 4)));
                *(uint32_t*)(xd + off) = pack_h2(x0, x1);
            }
        }
        CP_WAIT0();
        __syncthreads();
#pragma unroll
        for (int mt = 0; mt < 4; mt++)
#pragma unroll
            for (int nt = 0; nt < 8; nt++)
#pragma unroll
                for (int j = 0; j < 4; j++) acc[mt][nt][j] = 0.0f;
        const uint32_t sA = sb + A2_A;
        const uint32_t sB = sb + A2_B(0);
#pragma unroll
        for (int ks = 0; ks < 4; ks++) {
            uint32_t Af[4][4], Bf[4][4];
#pragma unroll
            for (int mt = 0; mt < 4; mt++) {
                int m = amr + mt * 16;
                uint32_t ro = (uint32_t)((m >> 3) * 1024 + (m & 7) * 128);
                uint32_t kb = (uint32_t)((ks * 32 + akb0) ^ ((m & 7) << 4));
                ldm_x4(Af[mt], sA + ro + kb);
            }
#pragma unroll
            for (int np = 0; np < 4; np++) {
                int c = bcr + np * 16;
                uint32_t ro = (uint32_t)((c >> 3) * 1024 + (c & 7) * 128);
                uint32_t kb = (uint32_t)((ks * 32 + bkb0) ^ ((c & 7) << 4));
                ldm_x4(Bf[np], sB + ro + kb);
            }
#pragma unroll
            for (int mt = 0; mt < 4; mt++)
#pragma unroll
                for (int np = 0; np < 4; np++) {
                    mma16816h(acc[mt][np * 2],     Af[mt], &Bf[np][0]);
                    mma16816h(acc[mt][np * 2 + 1], Af[mt], &Bf[np][2]);
                }
        }
        __half* pesh = (__half*)(smc + A2_PES);
        const int r = lane >> 2;
#pragma unroll
        for (int mt = 0; mt < 4; mt++) {
            int mbase = warp_m * 64 + mt * 16;
#pragma unroll
            for (int nt = 0; nt < 8; nt++)
#pragma unroll
                for (int j = 0; j < 2; j++) {
                    int c = warp_c * 64 + nt * 8 + (lane & 3) * 2 + j;
                    float bv = pos_b2[c];
                    pesh[c * 132 + mbase + r]     = __float2half(acc[mt][nt][j] + bv);
                    pesh[c * 132 + mbase + r + 8] = __float2half(acc[mt][nt][2 + j] + bv);
                }
        }
        __syncthreads();
    }

    // ---- main loop: logits GEMM ----
#pragma unroll
    for (int mt = 0; mt < 4; mt++)
#pragma unroll
        for (int nt = 0; nt < 8; nt++)
#pragma unroll
            for (int j = 0; j < 4; j++) acc[mt][nt][j] = 0.0f;

    attn2_cpasync(sb, 0, 0, hbase, w2img, tid);
    CP_COMMIT();
    CP_WAIT0();
    __syncthreads();
    attn2_convert(smc, 0, scale, shift, wid, lane);
    __syncthreads();

    for (int cq = 0; cq < 16; cq++) {
        const int s = cq & 1;
        if (cq + 1 < 16) {
            attn2_cpasync(sb, s ^ 1, cq + 1, hbase, w2img, tid);
            CP_COMMIT();
        }
        const uint32_t sA = sb + A2_A;
        const uint32_t sB = sb + A2_B(s);
#pragma unroll
        for (int ks = 0; ks < 4; ks++) {
            uint32_t Af[4][4], Bf[4][4];
#pragma unroll
            for (int mt = 0; mt < 4; mt++) {
                int m = amr + mt * 16;
                uint32_t ro = (uint32_t)((m >> 3) * 1024 + (m & 7) * 128);
                uint32_t kb = (uint32_t)((ks * 32 + akb0) ^ ((m & 7) << 4));
                ldm_x4(Af[mt], sA + ro + kb);
            }
#pragma unroll
            for (int np = 0; np < 4; np++) {
                int c = bcr + np * 16;
                uint32_t ro = (uint32_t)((c >> 3) * 1024 + (c & 7) * 128);
                uint32_t kb = (uint32_t)((ks * 32 + bkb0) ^ ((c & 7) << 4));
                ldm_x4(Bf[np], sB + ro + kb);
            }
#pragma unroll
            for (int mt = 0; mt < 4; mt++)
#pragma unroll
                for (int np = 0; np < 4; np++) {
                    mma16816h(acc[mt][np * 2],     Af[mt], &Bf[np][0]);
                    mma16816h(acc[mt][np * 2 + 1], Af[mt], &Bf[np][2]);
                }
        }
        if (cq + 1 < 16) {
            CP_WAIT0();
            __syncthreads();
            attn2_convert(smc, cq + 1, scale, shift, wid, lane);
            __syncthreads();
        }
    }
    __syncthreads();

    // ---- epilogue: softmax + aggregation (pes already staged) ----
    const __half* pesh = (const __half*)(smc + A2_PES);
#pragma unroll
    for (int mt = 0; mt < 4; mt++) {
        const int mbase = warp_m * 64 + mt * 16;
        const int n = (m0 + mbase) >> 4;
        const int r = lane >> 2;
#pragma unroll
        for (int nt = 0; nt < 8; nt++) {
#pragma unroll
            for (int j = 0; j < 2; j++) {
                int c = warp_c * 64 + nt * 8 + (lane & 3) * 2 + j;
                float v0 = acc[mt][nt][j], v1 = acc[mt][nt][2 + j];
                float mx = fmaxf(v0, v1);
                mx = fmaxf(mx, __shfl_xor_sync(0xffffffffu, mx, 4));
                mx = fmaxf(mx, __shfl_xor_sync(0xffffffffu, mx, 8));
                mx = fmaxf(mx, __shfl_xor_sync(0xffffffffu, mx, 16));
                float e0 = __expf(v0 - mx), e1 = __expf(v1 - mx);
                float se = e0 + e1;
                se += __shfl_xor_sync(0xffffffffu, se, 4);
                se += __shfl_xor_sync(0xffffffffu, se, 8);
                se += __shfl_xor_sync(0xffffffffu, se, 16);
                float p0 = __half2float(pesh[c * 132 + mbase + r]);
                float p1 = __half2float(pesh[c * 132 + mbase + r + 8]);
                float t = e0 * p0 + e1 * p1;
                t += __shfl_xor_sync(0xffffffffu, t, 4);
                t += __shfl_xor_sync(0xffffffffu, t, 8);
                t += __shfl_xor_sync(0xffffffffu, t, 16);
                if (r == 0) {
                    size_t o = ((size_t)(b * DIM_ + c)) * N_ + n;
                    agg[o] = vf[o] + t / se;
                }
            }
        }
    }
}

// ---------------- launch ----------------------------------------------------
extern "C" void kernel_launch(void* const* d_in, const int* in_sizes, int n_in,
                              void* d_out, int out_size) {
    const float* pos     = (const float*)d_in[0];
    const float* key     = (const float*)d_in[1];
    const float* query   = (const float*)d_in[2];
    const float* mlpv_w1 = (const float*)d_in[3];
    const float* mlpv_b1 = (const float*)d_in[4];
    const float* mlpv_w2 = (const float*)d_in[5];
    const float* mlpv_b2 = (const float*)d_in[6];
    const float* mlpv_ws = (const float*)d_in[7];
    const float* mlpv_bs = (const float*)d_in[8];
    const float* wk      = (const float*)d_in[9];
    const float* bk      = (const float*)d_in[10];
    const float* wq      = (const float*)d_in[11];
    const float* bq      = (const float*)d_in[12];
    const float* wv      = (const float*)d_in[13];
    const float* bv      = (const float*)d_in[14];
    const float* pos_w1  = (const float*)d_in[15];
    const float* pos_b1  = (const float*)d_in[16];
    const float* pos_g1  = (const float*)d_in[17];
    const float* pos_be1 = (const float*)d_in[18];
    const float* pos_w2  = (const float*)d_in[19];
    const float* pos_b2  = (const float*)d_in[20];
    const float* att_w1  = (const float*)d_in[21];
    const float* att_b1  = (const float*)d_in[22];
    const float* att_g1  = (const float*)d_in[23];
    const float* att_be1 = (const float*)d_in[24];
    const float* att_w2  = (const float*)d_in[25];
    const float* we      = (const float*)d_in[27];
    const float* be      = (const float*)d_in[28];
    float* out = (float*)d_out;

    void* p;
#define GETP(sym, var) cudaGetSymbolAddress(&p, sym); float* var = (float*)p;
    GETP(g_x, x_)       GETP(g_t, t_)       GETP(g_value, val)
    GETP(g_vf, vf_)     GETP(g_u, u_)
    GETP(g_t1, t1_)
    GETP(g_agg, agg)    GETP(g_part, part)  GETP(g_partp, partp)
    GETP(g_Wuq, Wuq)    GETP(g_Wvk, Wvk)    GETP(g_bias1, bias1)
    GETP(g_scp, scp)    GETP(g_shp, shp)    GETP(g_sca, sca)
    GETP(g_sha, sha)
#undef GETP
    cudaGetSymbolAddress(&p, g_idx);      int* idx = (int*)p;
    cudaGetSymbolAddress(&p, g_vt);       __half* vt_ = (__half*)p;
    cudaGetSymbolAddress(&p, g_h);        __half* h_ = (__half*)p;
    cudaGetSymbolAddress(&p, g_w2img);    unsigned int* w2img = (unsigned int*)p;
    cudaGetSymbolAddress(&p, g_wmidimg);  unsigned int* wmidimg = (unsigned int*)p;
    cudaGetSymbolAddress(&p, g_wuqimg);   unsigned int* wuqimg = (unsigned int*)p;
    cudaGetSymbolAddress(&p, g_wvkimg);   unsigned int* wvkimg = (unsigned int*)p;

    // --- precompute folded weights + weight images ---
    smallmm_kernel<<<(AH_ * C_ + 255) / 256, 256>>>(att_w1, wq, Wuq, AH_, DIM_, C_, 0);
    smallmm_kernel<<<(AH_ * C_ + 255) / 256, 256>>>(att_w1, wk, Wvk, AH_, DIM_, C_, 0);
    bias1_kernel<<<(AH_ + 255) / 256, 256>>>(att_w1, bq, bk, pos_b2, att_b1, bias1);
    prep_w2_kernel<<<(256 * 256) / 256, 256>>>(att_w2, w2img);
    prep_wmid_kernel<<<(1280 * 16 + 255) / 256, 256>>>(att_w1, pos_w2, wmidimg);
    prep_wuv_kernel<<<(AH_ * 32 + 255) / 256, 256>>>(Wuq, wuqimg);
    prep_wuv_kernel<<<(AH_ * 32 + 255) / 256, 256>>>(Wvk, wvkimg);

    // --- front end ---
    concat_kernel<<<(unsigned)(((size_t)B_ * 2 * C_ * N_ + 255) / 256), 256>>>(key, query, x_);
    knn_kernel<<<dim3(N_ / 256, B_), 256>>>(pos, idx);
    sgemm_kernel<1><<<dim3(N_ / 128, C_ / 128, B_), 256>>>(mlpv_w1, x_, mlpv_b1, t_, nullptr, C_, 2 * C_, N_);
    sgemm_kernel<0><<<dim3(N_ / 128, C_ / 128, B_), 256>>>(mlpv_w2, t_, mlpv_b2, val, nullptr, C_, C_, N_);
    sgemm_kernel<2><<<dim3(N_ / 128, C_ / 128, B_), 256>>>(mlpv_ws, x_, mlpv_bs, val, nullptr, C_, 2 * C_, N_);
    sgemm_kernel<0><<<dim3(N_ / 128, DIM_ / 128, B_), 256>>>(wv, val, bv, vf_, nullptr, DIM_, C_, N_);

    // --- u/v on fp16 HMMA (v written transposed) ---
    cudaFuncSetAttribute(uv_hmma, cudaFuncAttributeMaxDynamicSharedMemorySize, UV_SMEM);
    uv_hmma<<<dim3(N_ / 128, 4), 256, UV_SMEM>>>(query, key, wuqimg, wvkimg, u_, vt_);

    // --- pos_rel conv1 + pos BN ---
    posrel_kernel<<<(unsigned)(((size_t)B_ * PH_ * M_) / 256), 256>>>(pos, idx, pos_w1, pos_b1, t1_, partp);
    finalize_stats<<<PH_, 256>>>(partp, 512, 1, 512, pos_g1, pos_be1, scp, shp, (float)((size_t)B_ * M_));

    // --- fused mid on fp16 HMMA (h only) ---
    cudaFuncSetAttribute(fused_mid_hmma, cudaFuncAttributeMaxDynamicSharedMemorySize, FM_SMEM);
    fused_mid_hmma<<<dim3(M_ / 128, B_), 256, FM_SMEM>>>(
        t1_, scp, shp, wmidimg, bias1, u_, vt_, idx, h_, part);
    finalize_stats<<<AH_, 256>>>(part, B_ * 512, AH_, 1, att_g1, att_be1, sca, sha, (float)((size_t)B_ * M_));

    // --- big GEMM2: fp16 HMMA + in-kernel pe + softmax + aggregation ---
    cudaFuncSetAttribute(attn2_hmma_kernel, cudaFuncAttributeMaxDynamicSharedMemorySize, SMEM_ATT2);
    attn2_hmma_kernel<<<dim3(M_ / 128, B_), 256, SMEM_ATT2>>>(
        (const uint4*)w2img, h_, sca, sha, t1_, scp, shp,
        (const uint4*)wmidimg + 8 * 1024, pos_b2, vf_, agg);

    // --- final projection + residual ---
    sgemm_kernel<4><<<dim3(N_ / 128, C_ / 128, B_), 256>>>(we, agg, be, out, val, C_, DIM_, N_);
}

// round 15
// speedup vs baseline: 1.3523x; 1.0689x over previous
#include <cuda_runtime.h>
#include <cuda_bf16.h>
#include <cuda_fp16.h>
#include <math.h>
#include <stdint.h>

#define B_   2
#define C_   128
#define N_   4096
#define K_   16
#define DIM_ 256
#define PH_  64
#define AH_  1024
#define M_   (N_ * K_)          // 65536 columns per batch in (n,k) space

// ---------------- scratch ---------------------------------------------------
__device__ float g_x    [(size_t)B_ * 2 * C_ * N_];
__device__ float g_t    [(size_t)B_ * C_ * N_];
__device__ float g_value[(size_t)B_ * C_ * N_];
__device__ float g_vf   [(size_t)B_ * DIM_ * N_];
__device__ float g_u    [(size_t)B_ * AH_ * N_];
__device__ __half g_vt  [(size_t)B_ * N_ * AH_];       // v transposed (fp16)
__device__ int   g_idx  [(size_t)B_ * N_ * K_];
__device__ float g_t1   [(size_t)B_ * PH_ * M_];
__device__ __half g_h   [(size_t)B_ * AH_ * M_];       // h (fp16, c-major)
__device__ float g_agg  [(size_t)B_ * DIM_ * N_];
__device__ float g_part [(size_t)B_ * 512 * AH_ * 2];
__device__ float g_partp[(size_t)PH_ * 512 * 2];
__device__ float g_Wuq  [AH_ * C_];
__device__ float g_Wvk  [AH_ * C_];
__device__ float g_bias1[AH_];
__device__ float g_scp  [PH_];
__device__ float g_shp  [PH_];
__device__ float g_sca  [AH_];
__device__ float g_sha  [AH_];
// fp16 image of att_w2: 16 K-chunks x 32KB = 512KB
__device__ unsigned int g_w2img[16 * 32768 / 4];
// fp16 image of Wmid = concat(att_w1@pos_w2, pos_w2): 10 chunks x 16KB
__device__ unsigned int g_wmidimg[10 * 16384 / 4];
// fp16 images of Wuq/Wvk: 8 c-chunks x 32KB (2 kc x 16KB)
__device__ unsigned int g_wuqimg[8 * 32768 / 4];
__device__ unsigned int g_wvkimg[8 * 32768 / 4];

// ---------------- helpers ---------------------------------------------------
__device__ __forceinline__ uint32_t smem_u32(const void* p) {
    uint32_t a;
    asm("{ .reg .u64 t; cvta.to.shared.u64 t, %1; cvt.u32.u64 %0, t; }" : "=r"(a) : "l"(p));
    return a;
}
#define SWZ128(b) ((b) ^ (((b) >> 3) & 0x70))
__device__ __forceinline__ uint32_t pack_h2(float a, float b) {
    __half2 t = __floats2half2_rn(a, b);
    return *reinterpret_cast<uint32_t*>(&t);
}
__device__ __forceinline__ void ldm_x4(uint32_t* r, uint32_t addr) {
    asm volatile("ldmatrix.sync.aligned.m8n8.x4.shared.b16 {%0,%1,%2,%3}, [%4];"
        : "=r"(r[0]), "=r"(r[1]), "=r"(r[2]), "=r"(r[3]) : "r"(addr));
}
__device__ __forceinline__ void mma16816h(float* d, const uint32_t* a, const uint32_t* b) {
    asm volatile(
        "mma.sync.aligned.m16n8k16.row.col.f32.f16.f16.f32 "
        "{%0,%1,%2,%3}, {%4,%5,%6,%7}, {%8,%9}, {%0,%1,%2,%3};"
        : "+f"(d[0]), "+f"(d[1]), "+f"(d[2]), "+f"(d[3])
        : "r"(a[0]), "r"(a[1]), "r"(a[2]), "r"(a[3]), "r"(b[0]), "r"(b[1]));
}
__device__ __forceinline__ void cp_async16(uint32_t dst, const void* src) {
    asm volatile("cp.async.cg.shared.global [%0], [%1], 16;" :: "r"(dst), "l"(src));
}
#define CP_COMMIT() asm volatile("cp.async.commit_group;" ::: "memory")
#define CP_WAIT0()  asm volatile("cp.async.wait_group 0;" ::: "memory")

// ---------------- concat ----------------------------------------------------
__global__ void concat_kernel(const float* __restrict__ key,
                              const float* __restrict__ query,
                              float* __restrict__ x) {
    size_t i = (size_t)blockIdx.x * blockDim.x + threadIdx.x;
    if (i >= (size_t)B_ * 2 * C_ * N_) return;
    int n = (int)(i % N_);
    int c = (int)((i / N_) % (2 * C_));
    int b = (int)(i / ((size_t)N_ * 2 * C_));
    float v;
    if (c < C_) v = key  [((size_t)b * C_ + c) * N_ + n];
    else        v = query[((size_t)b * C_ + (c - C_)) * N_ + n];
    x[i] = v;
}

// ---------------- KNN -------------------------------------------------------
__global__ void knn_kernel(const float* __restrict__ pos, int* __restrict__ idx) {
    const int b = blockIdx.y;
    const int n = blockIdx.x * blockDim.x + threadIdx.x;
    const float* p = pos + (size_t)b * 3 * N_;
    const float qx = p[n], qy = p[N_ + n], qz = p[2 * N_ + n];
    const float qs = qx * qx + qy * qy + qz * qz;
    float bd[K_]; int bi[K_];
#pragma unroll
    for (int j = 0; j < K_; j++) { bd[j] = 3.4e38f; bi[j] = 0; }
    __shared__ float sx[512], sy[512], sz[512], ss[512];
    for (int t0 = 0; t0 < N_; t0 += 512) {
        __syncthreads();
        for (int i = threadIdx.x; i < 512; i += blockDim.x) {
            float x = p[t0 + i], y = p[N_ + t0 + i], z = p[2 * N_ + t0 + i];
            sx[i] = x; sy[i] = y; sz[i] = z; ss[i] = x * x + y * y + z * z;
        }
        __syncthreads();
        for (int i = 0; i < 512; i++) {
            float d = qs + ss[i] - 2.0f * (qx * sx[i] + qy * sy[i] + qz * sz[i]);
            if (d < bd[K_ - 1]) {
                int j = K_ - 1;
                while (j > 0 && d < bd[j - 1]) { bd[j] = bd[j - 1]; bi[j] = bi[j - 1]; j--; }
                bd[j] = d; bi[j] = t0 + i;
            }
        }
    }
    int* op = idx + ((size_t)b * N_ + n) * K_;
#pragma unroll
    for (int j = 0; j < K_; j++) op[j] = bi[j];
}

// ---------------- precompute small products ---------------------------------
__global__ void smallmm_kernel(const float* __restrict__ A, const float* __restrict__ Bm,
                               float* __restrict__ Cc, int O, int Id, int J, int tr) {
    int t = blockIdx.x * 256 + threadIdx.x;
    if (t >= O * J) return;
    int o = t / J, j = t % J;
    float s = 0.0f;
    for (int d = 0; d < Id; d++) s += A[o * Id + d] * Bm[d * J + j];
    if (tr) Cc[j * O + o] = s; else Cc[o * J + j] = s;
}
__global__ void bias1_kernel(const float* __restrict__ w1, const float* __restrict__ bq,
                             const float* __restrict__ bk, const float* __restrict__ pb2,
                             const float* __restrict__ ab1, float* __restrict__ out) {
    int o = blockIdx.x * 256 + threadIdx.x;
    if (o >= AH_) return;
    float s = ab1[o];
    for (int d = 0; d < DIM_; d++) s += w1[o * DIM_ + d] * (bq[d] - bk[d] + pb2[d]);
    out[o] = s;
}

// ---------------- att_w2 -> pre-swizzled fp16 image --------------------------
__global__ void prep_w2_kernel(const float* __restrict__ w2, unsigned int* __restrict__ img) {
    int t = blockIdx.x * 256 + threadIdx.x;
    if (t >= 256 * 256) return;
    int c = t >> 8, k4 = t & 255;
    int k = k4 * 4;
    int q = k >> 6, kl = k & 63;
    const float* src = w2 + (size_t)c * AH_ + k;
    uint32_t off = SWZ128((uint32_t)((c >> 3) * 1024 + (c & 7) * 128 + kl * 2));
    char* base = (char*)img + (size_t)q * 32768;
    *(uint2*)(base + off) = make_uint2(pack_h2(src[0], src[1]), pack_h2(src[2], src[3]));
}

// ---------------- Wmid -> pre-swizzled fp16 image ----------------------------
__global__ void prep_wmid_kernel(const float* __restrict__ att_w1,
                                 const float* __restrict__ pos_w2,
                                 unsigned int* __restrict__ img) {
    int t = blockIdx.x * 256 + threadIdx.x;
    if (t >= 1280 * 16) return;
    int c = t >> 4, k4 = t & 15;
    float f[4];
    if (c < AH_) {
#pragma unroll 4
        for (int kk = 0; kk < 4; kk++) {
            float s = 0.0f;
            for (int d = 0; d < DIM_; d++)
                s += att_w1[(size_t)c * DIM_ + d] * pos_w2[d * PH_ + k4 * 4 + kk];
            f[kk] = s;
        }
    } else {
#pragma unroll
        for (int kk = 0; kk < 4; kk++) f[kk] = pos_w2[(c - AH_) * PH_ + k4 * 4 + kk];
    }
    int ct = c >> 7, cl = c & 127;
    uint32_t off = (uint32_t)((cl >> 3) * 1024 + (cl & 7) * 128 +
                              ((k4 * 8) ^ ((cl & 7) << 4)));
    char* base = (char*)img + (size_t)ct * 16384;
    *(uint2*)(base + off) = make_uint2(pack_h2(f[0], f[1]), pack_h2(f[2], f[3]));
}

// ---------------- Wuq/Wvk [AH][C=128] -> fp16 image: 8 c-chunks x 32KB --------
__global__ void prep_wuv_kernel(const float* __restrict__ W, unsigned int* __restrict__ img) {
    int t = blockIdx.x * 256 + threadIdx.x;
    if (t >= AH_ * 32) return;
    int c = t >> 5, k4 = t & 31;
    int k = k4 * 4;
    int kc = k >> 6, kl = k & 63;
    const float* src = W + (size_t)c * C_ + k;
    int ct = c >> 7, cl = c & 127;
    uint32_t off = (uint32_t)((cl >> 3) * 1024 + (cl & 7) * 128 +
                              ((kl * 2) ^ ((cl & 7) << 4)));
    char* base = (char*)img + (size_t)ct * 32768 + (size_t)kc * 16384;
    *(uint2*)(base + off) = make_uint2(pack_h2(src[0], src[1]), pack_h2(src[2], src[3]));
}

// ---------------- generic fp32 SGEMM (small GEMMs) --------------------------
template <int FLAGS>
__global__ void sgemm_kernel(const float* __restrict__ W, const float* __restrict__ Xg,
                             const float* __restrict__ bias, float* __restrict__ outg,
                             const float* __restrict__ resg, int O, int I, int M) {
    const int b = blockIdx.z;
    const float* X = Xg + (size_t)b * I * M;
    float* out = outg + (size_t)b * O * M;
    const float* res = (FLAGS & 4) ? (resg + (size_t)b * O * M) : nullptr;
    __shared__ float Ws[8][132];
    __shared__ float Xs[8][128];
    const int tid = threadIdx.x;
    const int tx = tid & 15, ty = tid >> 4;
    const int o0 = blockIdx.y * 128, m0 = blockIdx.x * 128;
    const int wr = tid >> 1, wc = (tid & 1) * 4;
    const int xr = tid >> 5, xc = (tid & 31) * 4;
    float acc[8][8];
#pragma unroll
    for (int i = 0; i < 8; i++)
#pragma unroll
        for (int j = 0; j < 8; j++) acc[i][j] = 0.0f;
    for (int kt = 0; kt < I; kt += 8) {
        float4 wv = *(const float4*)&W[(size_t)(o0 + wr) * I + kt + wc];
        float4 xv = *(const float4*)&X[(size_t)(kt + xr) * M + m0 + xc];
        __syncthreads();
        Ws[wc + 0][wr] = wv.x; Ws[wc + 1][wr] = wv.y;
        Ws[wc + 2][wr] = wv.z; Ws[wc + 3][wr] = wv.w;
        *(float4*)&Xs[xr][xc] = xv;
        __syncthreads();
#pragma unroll
        for (int k = 0; k < 8; k++) {
            float a[8], bb[8];
            *(float4*)&a[0]  = *(const float4*)&Ws[k][ty * 8];
            *(float4*)&a[4]  = *(const float4*)&Ws[k][ty * 8 + 4];
            *(float4*)&bb[0] = *(const float4*)&Xs[k][tx * 8];
            *(float4*)&bb[4] = *(const float4*)&Xs[k][tx * 8 + 4];
#pragma unroll
            for (int i = 0; i < 8; i++)
#pragma unroll
                for (int j = 0; j < 8; j++) acc[i][j] += a[i] * bb[j];
        }
    }
#pragma unroll
    for (int i = 0; i < 8; i++) {
        const int o = o0 + ty * 8 + i;
        const float bv = bias[o];
        float* orow = out + (size_t)o * M + m0 + tx * 8;
        const float* rrow = (FLAGS & 4) ? (res + (size_t)o * M + m0 + tx * 8) : nullptr;
#pragma unroll
        for (int jj = 0; jj < 8; jj += 4) {
            float4 v;
            v.x = acc[i][jj + 0] + bv; v.y = acc[i][jj + 1] + bv;
            v.z = acc[i][jj + 2] + bv; v.w = acc[i][jj + 3] + bv;
            if (FLAGS & 1) { v.x = fmaxf(v.x, 0.f); v.y = fmaxf(v.y, 0.f);
                             v.z = fmaxf(v.z, 0.f); v.w = fmaxf(v.w, 0.f); }
            if (FLAGS & 2) { float4 old = *(float4*)&orow[jj];
                             v.x += old.x; v.y += old.y; v.z += old.z; v.w += old.w; }
            if (FLAGS & 4) { float4 r = *(const float4*)&rrow[jj];
                             v.x += r.x; v.y += r.y; v.z += r.z; v.w += r.w; }
            *(float4*)&orow[jj] = v;
        }
    }
}

// ---------------- pos_rel conv1 + BN partial stats ---------------------------
__global__ void posrel_kernel(const float* __restrict__ pos, const int* __restrict__ idx,
                              const float* __restrict__ w, const float* __restrict__ bias,
                              float* __restrict__ t1, float* __restrict__ part) {
    size_t i = (size_t)blockIdx.x * 256 + threadIdx.x;
    int k = (int)(i & 15);
    int n = (int)((i >> 4) & (N_ - 1));
    int c = (int)((i >> 16) & (PH_ - 1));
    int b = (int)(i >> 22);
    int m = idx[(((size_t)b * N_ + n) << 4) + k];
    const float* p = pos + (size_t)b * 3 * N_;
    float rx = p[n] - p[m];
    float ry = p[N_ + n] - p[N_ + m];
    float rz = p[2 * N_ + n] - p[2 * N_ + m];
    float val = w[c * 3] * rx + w[c * 3 + 1] * ry + w[c * 3 + 2] * rz + bias[c];
    t1[i] = val;
    __shared__ float ssum[256], ssq[256];
    ssum[threadIdx.x] = val; ssq[threadIdx.x] = val * val;
    __syncthreads();
    for (int st = 128; st > 0; st >>= 1) {
        if ((int)threadIdx.x < st) {
            ssum[threadIdx.x] += ssum[threadIdx.x + st];
            ssq[threadIdx.x]  += ssq[threadIdx.x + st];
        }
        __syncthreads();
    }
    if (threadIdx.x == 0) {
        int cb = (blockIdx.x >> 8) & (PH_ - 1);
        int bb = blockIdx.x >> 14;
        int sblk = blockIdx.x & 255;
        size_t o = ((size_t)cb * 512 + bb * 256 + sblk) * 2;
        part[o] = ssum[0]; part[o + 1] = ssq[0];
    }
}

// ---------------- BN finalize ------------------------------------------------
__global__ void finalize_stats(const float* __restrict__ part, int P, int ps, int cs,
                               const float* __restrict__ g, const float* __restrict__ be,
                               float* __restrict__ sc, float* __restrict__ sh, float cnt) {
    int c = blockIdx.x;
    double s = 0.0, q = 0.0;
    for (int p = threadIdx.x; p < P; p += blockDim.x) {
        size_t o = ((size_t)p * ps + (size_t)c * cs) * 2;
        s += (double)part[o]; q += (double)part[o + 1];
    }
    __shared__ double S[256], Q[256];
    S[threadIdx.x] = s; Q[threadIdx.x] = q;
    __syncthreads();
    for (int st = 128; st > 0; st >>= 1) {
        if ((int)threadIdx.x < st) {
            S[threadIdx.x] += S[threadIdx.x + st];
            Q[threadIdx.x] += Q[threadIdx.x + st];
        }
        __syncthreads();
    }
    if (threadIdx.x == 0) {
        double mean = S[0] / (double)cnt;
        double var  = Q[0] / (double)cnt - mean * mean;
        float scv = g[c] * (float)(1.0 / sqrt(var + 1e-5));
        sc[c] = scv;
        sh[c] = be[c] - (float)mean * scv;
    }
}

// ---------------- u/v GEMM on fp16 HMMA (v written transposed fp16) ----------
#define UV_X     0
#define UV_W(s)  (32768 + (s) * 32768)
#define UV_TR    98304
#define UV_SMEM  133120

__global__ __launch_bounds__(256) void uv_hmma(
    const float* __restrict__ query, const float* __restrict__ key,
    const unsigned int* __restrict__ wuqimg, const unsigned int* __restrict__ wvkimg,
    float* __restrict__ ug, __half* __restrict__ vt) {
    extern __shared__ char smc[];
    const uint32_t sb = smem_u32(smc);
    const int tid = threadIdx.x, lane = tid & 31, wid = tid >> 5;
    const int z = blockIdx.y;
    const int b = z & 1, which = z >> 1;
    const int n0 = blockIdx.x * 128;
    const float* X = (which == 0 ? query : key) + (size_t)b * C_ * N_;
    const unsigned int* wimg = (which == 0 ? wuqimg : wvkimg);
    float* uout = ug + (size_t)b * AH_ * N_;
    const int warp_cg = wid >> 1;
    const int warp_mg = wid & 1;

    {
        const uint4* src = (const uint4*)wimg;
        uint32_t dst = sb + UV_W(0);
#pragma unroll
        for (int it = 0; it < 8; it++)
            cp_async16(dst + (it * 256 + tid) * 16, src + it * 256 + tid);
        CP_COMMIT();
    }
    {
        char* xbase = smc + UV_X;
        int m = tid & 127, khalf = tid >> 7;
#pragma unroll
        for (int k2 = 0; k2 < 32; k2++) {
            int k = khalf * 64 + k2 * 2;
            int kl = k & 63;
            float x0 = X[(size_t)k * N_ + n0 + m];
            float x1 = X[(size_t)(k + 1) * N_ + n0 + m];
            uint32_t off = (uint32_t)((m >> 3) * 1024 + (m & 7) * 128 +
                                      ((kl * 2) ^ ((m & 7) << 4)));
            char* dst = xbase + khalf * 16384;
            *(uint32_t*)(dst + off) = pack_h2(x0, x1);
        }
    }
    CP_WAIT0();
    __syncthreads();

    const int g = lane >> 3, lr = lane & 7;
    const int wrow = warp_cg * 32 + (g & 1) * 8 + lr;
    const int xrow = warp_mg * 64 + (g >> 1) * 8 + lr;
    const int wkb0 = (g >> 1) * 16;
    const int xkb0 = (g & 1) * 16;
    const uint32_t sX = sb + UV_X;

    for (int ct = 0; ct < 8; ct++) {
        const int s = ct & 1;
        if (ct + 1 < 8) {
            const uint4* src = (const uint4*)wimg + (ct + 1) * 2048;
            uint32_t dst = sb + UV_W(s ^ 1);
#pragma unroll
            for (int it = 0; it < 8; it++)
                cp_async16(dst + (it * 256 + tid) * 16, src + it * 256 + tid);
            CP_COMMIT();
        }
        const uint32_t sW = sb + UV_W(s);
        float acc[2][8][4];
#pragma unroll
        for (int a = 0; a < 2; a++)
#pragma unroll
            for (int q = 0; q < 8; q++)
#pragma unroll
                for (int j = 0; j < 4; j++) acc[a][q][j] = 0.0f;
#pragma unroll
        for (int kc = 0; kc < 2; kc++) {
#pragma unroll
            for (int ks = 0; ks < 4; ks++) {
                uint32_t Wf[2][4], Xf[4][4];
#pragma unroll
                for (int ct2 = 0; ct2 < 2; ct2++) {
                    int cr = wrow + ct2 * 16;
                    uint32_t ro = (uint32_t)((cr >> 3) * 1024 + (cr & 7) * 128);
                    uint32_t kb = (uint32_t)((ks * 32 + wkb0) ^ ((cr & 7) << 4));
                    ldm_x4(Wf[ct2], sW + kc * 16384 + ro + kb);
                }
#pragma unroll
                for (int np = 0; np < 4; np++) {
                    int mr = xrow + np * 16;
                    uint32_t ro = (uint32_t)((mr >> 3) * 1024 + (mr & 7) * 128);
                    uint32_t kb = (uint32_t)((ks * 32 + xkb0) ^ ((mr & 7) << 4));
                    ldm_x4(Xf[np], sX + kc * 16384 + ro + kb);
                }
#pragma unroll
                for (int ct2 = 0; ct2 < 2; ct2++)
#pragma unroll
                    for (int np = 0; np < 4; np++) {
                        mma16816h(acc[ct2][np * 2],     Wf[ct2], &Xf[np][0]);
                        mma16816h(acc[ct2][np * 2 + 1], Wf[ct2], &Xf[np][2]);
                    }
            }
        }
        if (which == 0) {
#pragma unroll
            for (int ct2 = 0; ct2 < 2; ct2++) {
#pragma unroll
                for (int j = 0; j < 4; j++) {
                    int c_g = ct * 128 + warp_cg * 32 + ct2 * 16 + (lane >> 2) + (j >> 1) * 8;
                    float* orow = uout + (size_t)c_g * N_ + n0;
#pragma unroll
                    for (int q = 0; q < 8; q++) {
                        int m_loc = warp_mg * 64 + q * 8 + (lane & 3) * 2 + (j & 1);
                        orow[m_loc] = acc[ct2][q][j];
                    }
                }
            }
        } else {
            __half* trs = (__half*)(smc + UV_TR);
#pragma unroll
            for (int ct2 = 0; ct2 < 2; ct2++)
#pragma unroll
                for (int j = 0; j < 4; j++) {
                    int c_loc = warp_cg * 32 + ct2 * 16 + (lane >> 2) + (j >> 1) * 8;
#pragma unroll
                    for (int q = 0; q < 8; q++) {
                        int m_loc = warp_mg * 64 + q * 8 + (lane & 3) * 2 + (j & 1);
                        trs[m_loc * 136 + c_loc] = __float2half(acc[ct2][q][j]);
                    }
                }
            __syncthreads();
            __half* dvt = vt + ((size_t)b * N_ + n0) * AH_ + ct * 128;
#pragma unroll
            for (int it = 0; it < 8; it++) {
                int e = it * 256 + tid;
                int row = e >> 4, col = e & 15;
                *(uint4*)(dvt + (size_t)row * AH_ + col * 8) =
                    *(uint4*)&trs[row * 136 + col * 8];
            }
        }
        CP_WAIT0();
        __syncthreads();
    }
}

// ---------------- fused mid on fp16 HMMA (h only) ----------------------------
#define FM_X     0
#define FM_W(s)  (16384 + (s) * 16384)
#define FM_VG    49152
#define FM_U     82944
#define FM_RED   87552
#define FM_SIDX  89600
#define FM_SMEM  90112

__global__ __launch_bounds__(256, 2) void fused_mid_hmma(
    const float* __restrict__ t1, const float* __restrict__ psc,
    const float* __restrict__ psh, const unsigned int* __restrict__ wimg,
    const float* __restrict__ bias1, const float* __restrict__ u,
    const __half* __restrict__ vt, const int* __restrict__ idx,
    __half* __restrict__ h, float* __restrict__ part) {
    extern __shared__ char smc[];
    const uint32_t sb = smem_u32(smc);
    const int tid = threadIdx.x, lane = tid & 31, wid = tid >> 5;
    const int b = blockIdx.y, m0 = blockIdx.x * 128;
    const int warp_cg = wid >> 1;
    const int warp_mg = wid & 1;

    int* sidx = (int*)(smc + FM_SIDX);
    __half* vgsh = (__half*)(smc + FM_VG);
    float* us  = (float*)(smc + FM_U);
    float* redS = (float*)(smc + FM_RED);
    float* redQ = redS + 256;

    if (tid < 128) sidx[tid] = idx[((size_t)b * N_ + (m0 >> 4)) * K_ + tid];

    {
        const uint4* src = (const uint4*)wimg;
        uint32_t dst = sb + FM_W(0);
#pragma unroll
        for (int it = 0; it < 4; it++)
            cp_async16(dst + (it * 256 + tid) * 16, src + it * 256 + tid);
        CP_COMMIT();
    }
    {
        const float* tb = t1 + (size_t)b * PH_ * M_ + m0;
        char* xd = smc + FM_X;
        int m = tid & 127, khalf = tid >> 7;
#pragma unroll
        for (int k2 = 0; k2 < 16; k2++) {
            int k = khalf * 32 + k2 * 2;
            float x0 = tb[(size_t)k * M_ + m];
            float x1 = tb[(size_t)(k + 1) * M_ + m];
            x0 = fmaxf(x0 * psc[k] + psh[k], 0.f);
            x1 = fmaxf(x1 * psc[k + 1] + psh[k + 1], 0.f);
            uint32_t off = (uint32_t)((m >> 3) * 1024 + (m & 7) * 128 +
                                      ((k * 2) ^ ((m & 7) << 4)));
            *(uint32_t*)(xd + off) = pack_h2(x0, x1);
        }
    }
    CP_WAIT0();
    __syncthreads();

    const int g = lane >> 3, lr = lane & 7;
    const int wrow = warp_cg * 32 + (g & 1) * 8 + lr;
    const int xrow = warp_mg * 64 + (g >> 1) * 8 + lr;
    const int wkb0 = (g >> 1) * 16;
    const int xkb0 = (g & 1) * 16;
    const uint32_t sX = sb + FM_X;
    const __half* vtb = vt + (size_t)b * N_ * AH_;
    const int n0 = m0 >> 4;

    for (int ct = 0; ct < 8; ct++) {
        const int s = ct & 1;
        if (ct + 1 < 8) {
            const uint4* src = (const uint4*)wimg + (ct + 1) * 1024;
            uint32_t dst = sb + FM_W(s ^ 1);
#pragma unroll
            for (int it = 0; it < 4; it++)
                cp_async16(dst + (it * 256 + tid) * 16, src + it * 256 + tid);
            CP_COMMIT();
        }
        {
#pragma unroll
            for (int jj = 0; jj < 16; jj++) {
                int j = wid * 16 + jj;
                const __half* row = vtb + (size_t)sidx[j] * AH_ + ct * 128;
#pragma unroll
                for (int cc = 0; cc < 2; cc++) {
                    int c = cc * 64 + lane * 2;
                    __half2 hv = *(const __half2*)(row + c);
                    vgsh[c * 132 + j] = hv.x;
                    vgsh[(c + 1) * 132 + j] = hv.y;
                }
            }
#pragma unroll
            for (int it = 0; it < 4; it++) {
                int e = it * 256 + tid;
                int c = e >> 3, nn = e & 7;
                us[c * 9 + nn] = u[((size_t)b * AH_ + ct * 128 + c) * N_ + n0 + nn]
                               + bias1[ct * 128 + c];
            }
        }
        const uint32_t sW = sb + FM_W(s);
        float acc[2][8][4];
#pragma unroll
        for (int a = 0; a < 2; a++)
#pragma unroll
            for (int q = 0; q < 8; q++)
#pragma unroll
                for (int j = 0; j < 4; j++) acc[a][q][j] = 0.0f;
#pragma unroll
        for (int ks = 0; ks < 4; ks++) {
            uint32_t Wf[2][4], Xf[4][4];
#pragma unroll
            for (int ct2 = 0; ct2 < 2; ct2++) {
                int cr = wrow + ct2 * 16;
                uint32_t ro = (uint32_t)((cr >> 3) * 1024 + (cr & 7) * 128);
                uint32_t kb = (uint32_t)((ks * 32 + wkb0) ^ ((cr & 7) << 4));
                ldm_x4(Wf[ct2], sW + ro + kb);
            }
#pragma unroll
            for (int np = 0; np < 4; np++) {
                int mr = xrow + np * 16;
                uint32_t ro = (uint32_t)((mr >> 3) * 1024 + (mr & 7) * 128);
                uint32_t kb = (uint32_t)((ks * 32 + xkb0) ^ ((mr & 7) << 4));
                ldm_x4(Xf[np], sX + ro + kb);
            }
#pragma unroll
            for (int ct2 = 0; ct2 < 2; ct2++)
#pragma unroll
                for (int np = 0; np < 4; np++) {
                    mma16816h(acc[ct2][np * 2],     Wf[ct2], &Xf[np][0]);
                    mma16816h(acc[ct2][np * 2 + 1], Wf[ct2], &Xf[np][2]);
                }
        }
        __syncthreads();
        {
            float sS[2][2], sQ[2][2];
#pragma unroll
            for (int a = 0; a < 2; a++) { sS[a][0] = sS[a][1] = 0.f; sQ[a][0] = sQ[a][1] = 0.f; }
#pragma unroll
            for (int ct2 = 0; ct2 < 2; ct2++) {
#pragma unroll
                for (int rh = 0; rh < 2; rh++) {
                    int c_loc = warp_cg * 32 + ct2 * 16 + (lane >> 2) + rh * 8;
                    int c_g = ct * 128 + c_loc;
                    __half* hrow = h + ((size_t)b * AH_ + c_g) * M_ + m0;
#pragma unroll
                    for (int q = 0; q < 8; q++) {
                        int m_loc = warp_mg * 64 + q * 8 + (lane & 3) * 2;
                        float base = us[c_loc * 9 + (m_loc >> 4)];
                        float v0 = acc[ct2][q][rh * 2]     + base
                                 - __half2float(vgsh[c_loc * 132 + m_loc]);
                        float v1 = acc[ct2][q][rh * 2 + 1] + base
                                 - __half2float(vgsh[c_loc * 132 + m_loc + 1]);
                        *(__half2*)(hrow + m_loc) = __floats2half2_rn(v0, v1);
                        sS[ct2][rh] += v0 + v1;
                        sQ[ct2][rh] += v0 * v0 + v1 * v1;
                    }
                }
            }
#pragma unroll
            for (int ct2 = 0; ct2 < 2; ct2++)
#pragma unroll
                for (int rh = 0; rh < 2; rh++) {
                    float s1 = sS[ct2][rh], q1 = sQ[ct2][rh];
                    s1 += __shfl_xor_sync(0xffffffffu, s1, 1);
                    s1 += __shfl_xor_sync(0xffffffffu, s1, 2);
                    q1 += __shfl_xor_sync(0xffffffffu, q1, 1);
                    q1 += __shfl_xor_sync(0xffffffffu, q1, 2);
                    if ((lane & 3) == 0) {
                        int c_loc = warp_cg * 32 + ct2 * 16 + (lane >> 2) + rh * 8;
                        redS[c_loc * 2 + warp_mg] = s1;
                        redQ[c_loc * 2 + warp_mg] = q1;
                    }
                }
            __syncthreads();
            if (tid < 128) {
                float ss = redS[tid * 2] + redS[tid * 2 + 1];
                float qq = redQ[tid * 2] + redQ[tid * 2 + 1];
                size_t po = (((size_t)b * 512 + blockIdx.x) * AH_ + ct * 128 + tid) * 2;
                part[po] = ss; part[po + 1] = qq;
            }
        }
        CP_WAIT0();
        __syncthreads();
    }
}

// ---------------- attn GEMM2 (fp16 HMMA; c-halved for 2 blocks/SM) -----------
// smem: A 16K @0 | B 2x16K @16K | h stg 16K @48K | pes half 33.8K @64K = 97K
#define A2_A      0
#define A2_B(s)   (16384 + (s) * 16384)
#define A2_STG    49152
#define A2_PES    65536
#define SMEM_ATT2 99328

__device__ __forceinline__ void attn2_cpasync(uint32_t sb, int s, int cq, int ch,
                                              const __half* hbase, const uint4* w2img,
                                              int tid) {
    const uint4* src = w2img + (size_t)cq * 2048 + ch * 1024;
    uint32_t bdst = sb + A2_B(s);
#pragma unroll
    for (int it = 0; it < 4; it++) {
        int i = it * 256 + tid;
        cp_async16(bdst + i * 16, src + i);
    }
#pragma unroll
    for (int it = 0; it < 4; it++) {
        int ch2 = it * 256 + tid;
        int krow = ch2 >> 4, off = ch2 & 15;
        const __half* srcr = hbase + (size_t)(cq * 64 + krow) * M_ + off * 8;
        cp_async16(sb + A2_STG + krow * 256 + off * 16, srcr);
    }
}

__device__ __forceinline__ void attn2_convert(char* smc, int cq,
                                              const float* __restrict__ scale,
                                              const float* __restrict__ shift,
                                              int wid, int lane) {
    const __half* stg = (const __half*)(smc + A2_STG);
    char* dst = smc + A2_A;
#pragma unroll
    for (int g2 = 0; g2 < 2; g2++) {
        int base_k = wid * 8 + g2 * 4;
        float X[4][4];
#pragma unroll
        for (int r = 0; r < 4; r++) {
            uint2 raw = *(const uint2*)&stg[(base_k + r) * 128 + lane * 4];
            float2 f01 = __half22float2(*(__half2*)&raw.x);
            float2 f23 = __half22float2(*(__half2*)&raw.y);
            float sc = scale[cq * 64 + base_k + r];
            float sh = shift[cq * 64 + base_k + r];
            X[0][r] = fmaxf(f01.x * sc + sh, 0.f);
            X[1][r] = fmaxf(f01.y * sc + sh, 0.f);
            X[2][r] = fmaxf(f23.x * sc + sh, 0.f);
            X[3][r] = fmaxf(f23.y * sc + sh, 0.f);
        }
#pragma unroll
        for (int mm = 0; mm < 4; mm++) {
            int m = lane * 4 + mm;
            uint32_t off = (uint32_t)((m >> 3) * 1024 + (m & 7) * 128 +
                                      ((base_k * 2) ^ ((m & 7) << 4)));
            *(uint2*)(dst + off) = make_uint2(pack_h2(X[mm][0], X[mm][1]),
                                              pack_h2(X[mm][2], X[mm][3]));
        }
    }
}

__global__ __launch_bounds__(256, 2) void attn2_hmma_kernel(
    const uint4* __restrict__ w2img, const __half* __restrict__ h,
    const float* __restrict__ scale, const float* __restrict__ shift,
    const float* __restrict__ t1, const float* __restrict__ psc,
    const float* __restrict__ psh, const uint4* __restrict__ wmid89,
    const float* __restrict__ pos_b2, const float* __restrict__ vf,
    float* __restrict__ agg) {
    extern __shared__ char smc[];
    const uint32_t sb = smem_u32(smc);
    const int tid = threadIdx.x, lane = tid & 31, wid = tid >> 5;
    const int b = blockIdx.y >> 1, ch = blockIdx.y & 1;
    const int m0 = blockIdx.x * 128;
    const int warp_m = wid >> 2, warp_c = wid & 3;

    const __half* hbase = h + (size_t)b * AH_ * M_ + m0;

    const int g = lane >> 3, lr = lane & 7;
    const int amr  = warp_m * 64 + (g & 1) * 8 + lr;
    const int bcr  = warp_c * 32 + (g >> 1) * 8 + lr;
    const int akb0 = (g >> 1) * 16;
    const int bkb0 = (g & 1) * 16;

    float acc[4][4][4];

    // ---- phase 1: compute pe tile (this c-half) into pes smem ----
    {
        {
            const uint4* src = wmid89 + ch * 1024;
            uint32_t dst = sb + A2_B(0);
#pragma unroll
            for (int it = 0; it < 4; it++)
                cp_async16(dst + (it * 256 + tid) * 16, src + it * 256 + tid);
            CP_COMMIT();
        }
        {
            const float* tb = t1 + (size_t)b * PH_ * M_ + m0;
            char* xd = smc + A2_A;
            int m = tid & 127, khalf = tid >> 7;
#pragma unroll
            for (int k2 = 0; k2 < 16; k2++) {
                int k = khalf * 32 + k2 * 2;
                float x0 = tb[(size_t)k * M_ + m];
                float x1 = tb[(size_t)(k + 1) * M_ + m];
                x0 = fmaxf(x0 * psc[k] + psh[k], 0.f);
                x1 = fmaxf(x1 * psc[k + 1] + psh[k + 1], 0.f);
                uint32_t off = (uint32_t)((m >> 3) * 1024 + (m & 7) * 128 +
                                          ((k * 2) ^ ((m & 7) << 4)));
                *(uint32_t*)(xd + off) = pack_h2(x0, x1);
            }
        }
        CP_WAIT0();
        __syncthreads();
#pragma unroll
        for (int mt = 0; mt < 4; mt++)
#pragma unroll
            for (int nt = 0; nt < 4; nt++)
#pragma unroll
                for (int j = 0; j < 4; j++) acc[mt][nt][j] = 0.0f;
        const uint32_t sA = sb + A2_A;
        const uint32_t sB = sb + A2_B(0);
#pragma unroll
        for (int ks = 0; ks < 4; ks++) {
            uint32_t Af[4][4], Bf[2][4];
#pragma unroll
            for (int mt = 0; mt < 4; mt++) {
                int m = amr + mt * 16;
                uint32_t ro = (uint32_t)((m >> 3) * 1024 + (m & 7) * 128);
                uint32_t kb = (uint32_t)((ks * 32 + akb0) ^ ((m & 7) << 4));
                ldm_x4(Af[mt], sA + ro + kb);
            }
#pragma unroll
            for (int np = 0; np < 2; np++) {
                int c = bcr + np * 16;
                uint32_t ro = (uint32_t)((c >> 3) * 1024 + (c & 7) * 128);
                uint32_t kb = (uint32_t)((ks * 32 + bkb0) ^ ((c & 7) << 4));
                ldm_x4(Bf[np], sB + ro + kb);
            }
#pragma unroll
            for (int mt = 0; mt < 4; mt++)
#pragma unroll
                for (int np = 0; np < 2; np++) {
                    mma16816h(acc[mt][np * 2],     Af[mt], &Bf[np][0]);
                    mma16816h(acc[mt][np * 2 + 1], Af[mt], &Bf[np][2]);
                }
        }
        __half* pesh = (__half*)(smc + A2_PES);
        const int r = lane >> 2;
#pragma unroll
        for (int mt = 0; mt < 4; mt++) {
            int mbase = warp_m * 64 + mt * 16;
#pragma unroll
            for (int nt = 0; nt < 4; nt++)
#pragma unroll
                for (int j = 0; j < 2; j++) {
                    int c = warp_c * 32 + nt * 8 + (lane & 3) * 2 + j;
                    float bv = pos_b2[ch * 128 + c];
                    pesh[c * 132 + mbase + r]     = __float2half(acc[mt][nt][j] + bv);
                    pesh[c * 132 + mbase + r + 8] = __float2half(acc[mt][nt][2 + j] + bv);
                }
        }
        __syncthreads();
    }

    // ---- main loop: logits GEMM (this c-half) ----
#pragma unroll
    for (int mt = 0; mt < 4; mt++)
#pragma unroll
        for (int nt = 0; nt < 4; nt++)
#pragma unroll
            for (int j = 0; j < 4; j++) acc[mt][nt][j] = 0.0f;

    attn2_cpasync(sb, 0, 0, ch, hbase, w2img, tid);
    CP_COMMIT();
    CP_WAIT0();
    __syncthreads();
    attn2_convert(smc, 0, scale, shift, wid, lane);
    __syncthreads();

    for (int cq = 0; cq < 16; cq++) {
        const int s = cq & 1;
        if (cq + 1 < 16) {
            attn2_cpasync(sb, s ^ 1, cq + 1, ch, hbase, w2img, tid);
            CP_COMMIT();
        }
        const uint32_t sA = sb + A2_A;
        const uint32_t sB = sb + A2_B(s);
#pragma unroll
        for (int ks = 0; ks < 4; ks++) {
            uint32_t Af[4][4], Bf[2][4];
#pragma unroll
            for (int mt = 0; mt < 4; mt++) {
                int m = amr + mt * 16;
                uint32_t ro = (uint32_t)((m >> 3) * 1024 + (m & 7) * 128);
                uint32_t kb = (uint32_t)((ks * 32 + akb0) ^ ((m & 7) << 4));
                ldm_x4(Af[mt], sA + ro + kb);
            }
#pragma unroll
            for (int np = 0; np < 2; np++) {
                int c = bcr + np * 16;
                uint32_t ro = (uint32_t)((c >> 3) * 1024 + (c & 7) * 128);
                uint32_t kb = (uint32_t)((ks * 32 + bkb0) ^ ((c & 7) << 4));
                ldm_x4(Bf[np], sB + ro + kb);
            }
#pragma unroll
            for (int mt = 0; mt < 4; mt++)
#pragma unroll
                for (int np = 0; np < 2; np++) {
                    mma16816h(acc[mt][np * 2],     Af[mt], &Bf[np][0]);
                    mma16816h(acc[mt][np * 2 + 1], Af[mt], &Bf[np][2]);
                }
        }
        if (cq + 1 < 16) {
            CP_WAIT0();
            __syncthreads();
            attn2_convert(smc, cq + 1, scale, shift, wid, lane);
            __syncthreads();
        }
    }
    __syncthreads();

    // ---- epilogue: softmax + aggregation ----
    const __half* pesh = (const __half*)(smc + A2_PES);
#pragma unroll
    for (int mt = 0; mt < 4; mt++) {
        const int mbase = warp_m * 64 + mt * 16;
        const int n = (m0 + mbase) >> 4;
        const int r = lane >> 2;
#pragma unroll
        for (int nt = 0; nt < 4; nt++) {
#pragma unroll
            for (int j = 0; j < 2; j++) {
                int c = warp_c * 32 + nt * 8 + (lane & 3) * 2 + j;
                float v0 = acc[mt][nt][j], v1 = acc[mt][nt][2 + j];
                float mx = fmaxf(v0, v1);
                mx = fmaxf(mx, __shfl_xor_sync(0xffffffffu, mx, 4));
                mx = fmaxf(mx, __shfl_xor_sync(0xffffffffu, mx, 8));
                mx = fmaxf(mx, __shfl_xor_sync(0xffffffffu, mx, 16));
                float e0 = __expf(v0 - mx), e1 = __expf(v1 - mx);
                float se = e0 + e1;
                se += __shfl_xor_sync(0xffffffffu, se, 4);
                se += __shfl_xor_sync(0xffffffffu, se, 8);
                se += __shfl_xor_sync(0xffffffffu, se, 16);
                float p0 = __half2float(pesh[c * 132 + mbase + r]);
                float p1 = __half2float(pesh[c * 132 + mbase + r + 8]);
                float t = e0 * p0 + e1 * p1;
                t += __shfl_xor_sync(0xffffffffu, t, 4);
                t += __shfl_xor_sync(0xffffffffu, t, 8);
                t += __shfl_xor_sync(0xffffffffu, t, 16);
                if (r == 0) {
                    size_t o = ((size_t)(b * DIM_ + ch * 128 + c)) * N_ + n;
                    agg[o] = vf[o] + t / se;
                }
            }
        }
    }
}

// ---------------- launch ----------------------------------------------------
extern "C" void kernel_launch(void* const* d_in, const int* in_sizes, int n_in,
                              void* d_out, int out_size) {
    const float* pos     = (const float*)d_in[0];
    const float* key     = (const float*)d_in[1];
    const float* query   = (const float*)d_in[2];
    const float* mlpv_w1 = (const float*)d_in[3];
    const float* mlpv_b1 = (const float*)d_in[4];
    const float* mlpv_w2 = (const float*)d_in[5];
    const float* mlpv_b2 = (const float*)d_in[6];
    const float* mlpv_ws = (const float*)d_in[7];
    const float* mlpv_bs = (const float*)d_in[8];
    const float* wk      = (const float*)d_in[9];
    const float* bk      = (const float*)d_in[10];
    const float* wq      = (const float*)d_in[11];
    const float* bq      = (const float*)d_in[12];
    const float* wv      = (const float*)d_in[13];
    const float* bv      = (const float*)d_in[14];
    const float* pos_w1  = (const float*)d_in[15];
    const float* pos_b1  = (const float*)d_in[16];
    const float* pos_g1  = (const float*)d_in[17];
    const float* pos_be1 = (const float*)d_in[18];
    const float* pos_w2  = (const float*)d_in[19];
    const float* pos_b2  = (const float*)d_in[20];
    const float* att_w1  = (const float*)d_in[21];
    const float* att_b1  = (const float*)d_in[22];
    const float* att_g1  = (const float*)d_in[23];
    const float* att_be1 = (const float*)d_in[24];
    const float* att_w2  = (const float*)d_in[25];
    const float* we      = (const float*)d_in[27];
    const float* be      = (const float*)d_in[28];
    float* out = (float*)d_out;

    void* p;
#define GETP(sym, var) cudaGetSymbolAddress(&p, sym); float* var = (float*)p;
    GETP(g_x, x_)       GETP(g_t, t_)       GETP(g_value, val)
    GETP(g_vf, vf_)     GETP(g_u, u_)
    GETP(g_t1, t1_)
    GETP(g_agg, agg)    GETP(g_part, part)  GETP(g_partp, partp)
    GETP(g_Wuq, Wuq)    GETP(g_Wvk, Wvk)    GETP(g_bias1, bias1)
    GETP(g_scp, scp)    GETP(g_shp, shp)    GETP(g_sca, sca)
    GETP(g_sha, sha)
#undef GETP
    cudaGetSymbolAddress(&p, g_idx);      int* idx = (int*)p;
    cudaGetSymbolAddress(&p, g_vt);       __half* vt_ = (__half*)p;
    cudaGetSymbolAddress(&p, g_h);        __half* h_ = (__half*)p;
    cudaGetSymbolAddress(&p, g_w2img);    unsigned int* w2img = (unsigned int*)p;
    cudaGetSymbolAddress(&p, g_wmidimg);  unsigned int* wmidimg = (unsigned int*)p;
    cudaGetSymbolAddress(&p, g_wuqimg);   unsigned int* wuqimg = (unsigned int*)p;
    cudaGetSymbolAddress(&p, g_wvkimg);   unsigned int* wvkimg = (unsigned int*)p;

    // --- precompute folded weights + weight images ---
    smallmm_kernel<<<(AH_ * C_ + 255) / 256, 256>>>(att_w1, wq, Wuq, AH_, DIM_, C_, 0);
    smallmm_kernel<<<(AH_ * C_ + 255) / 256, 256>>>(att_w1, wk, Wvk, AH_, DIM_, C_, 0);
    bias1_kernel<<<(AH_ + 255) / 256, 256>>>(att_w1, bq, bk, pos_b2, att_b1, bias1);
    prep_w2_kernel<<<(256 * 256) / 256, 256>>>(att_w2, w2img);
    prep_wmid_kernel<<<(1280 * 16 + 255) / 256, 256>>>(att_w1, pos_w2, wmidimg);
    prep_wuv_kernel<<<(AH_ * 32 + 255) / 256, 256>>>(Wuq, wuqimg);
    prep_wuv_kernel<<<(AH_ * 32 + 255) / 256, 256>>>(Wvk, wvkimg);

    // --- front end ---
    concat_kernel<<<(unsigned)(((size_t)B_ * 2 * C_ * N_ + 255) / 256), 256>>>(key, query, x_);
    knn_kernel<<<dim3(N_ / 256, B_), 256>>>(pos, idx);
    sgemm_kernel<1><<<dim3(N_ / 128, C_ / 128, B_), 256>>>(mlpv_w1, x_, mlpv_b1, t_, nullptr, C_, 2 * C_, N_);
    sgemm_kernel<0><<<dim3(N_ / 128, C_ / 128, B_), 256>>>(mlpv_w2, t_, mlpv_b2, val, nullptr, C_, C_, N_);
    sgemm_kernel<2><<<dim3(N_ / 128, C_ / 128, B_), 256>>>(mlpv_ws, x_, mlpv_bs, val, nullptr, C_, 2 * C_, N_);
    sgemm_kernel<0><<<dim3(N_ / 128, DIM_ / 128, B_), 256>>>(wv, val, bv, vf_, nullptr, DIM_, C_, N_);

    // --- u/v on fp16 HMMA (v written transposed) ---
    cudaFuncSetAttribute(uv_hmma, cudaFuncAttributeMaxDynamicSharedMemorySize, UV_SMEM);
    uv_hmma<<<dim3(N_ / 128, 4), 256, UV_SMEM>>>(query, key, wuqimg, wvkimg, u_, vt_);

    // --- pos_rel conv1 + pos BN ---
    posrel_kernel<<<(unsigned)(((size_t)B_ * PH_ * M_) / 256), 256>>>(pos, idx, pos_w1, pos_b1, t1_, partp);
    finalize_stats<<<PH_, 256>>>(partp, 512, 1, 512, pos_g1, pos_be1, scp, shp, (float)((size_t)B_ * M_));

    // --- fused mid on fp16 HMMA (h only, 2 blocks/SM) ---
    cudaFuncSetAttribute(fused_mid_hmma, cudaFuncAttributeMaxDynamicSharedMemorySize, FM_SMEM);
    fused_mid_hmma<<<dim3(M_ / 128, B_), 256, FM_SMEM>>>(
        t1_, scp, shp, wmidimg, bias1, u_, vt_, idx, h_, part);
    finalize_stats<<<AH_, 256>>>(part, B_ * 512, AH_, 1, att_g1, att_be1, sca, sha, (float)((size_t)B_ * M_));

    // --- big GEMM2: c-halved fp16 HMMA, 2 blocks/SM ---
    cudaFuncSetAttribute(attn2_hmma_kernel, cudaFuncAttributeMaxDynamicSharedMemorySize, SMEM_ATT2);
    attn2_hmma_kernel<<<dim3(M_ / 128, B_ * 2), 256, SMEM_ATT2>>>(
        (const uint4*)w2img, h_, sca, sha, t1_, scp, shp,
        (const uint4*)wmidimg + 8 * 1024, pos_b2, vf_, agg);

    // --- final projection + residual ---
    sgemm_kernel<4><<<dim3(N_ / 128, C_ / 128, B_), 256>>>(we, agg, be, out, val, C_, DIM_, N_);
}

// round 16
// speedup vs baseline: 1.3785x; 1.0193x over previous
#include <cuda_runtime.h>
#include <cuda_bf16.h>
#include <cuda_fp16.h>
#include <math.h>
#include <stdint.h>

#define B_   2
#define C_   128
#define N_   4096
#define K_   16
#define DIM_ 256
#define PH_  64
#define AH_  1024
#define M_   (N_ * K_)          // 65536 columns per batch in (n,k) space

// ---------------- scratch ---------------------------------------------------
__device__ float g_x    [(size_t)B_ * 2 * C_ * N_];
__device__ float g_t    [(size_t)B_ * C_ * N_];
__device__ float g_value[(size_t)B_ * C_ * N_];
__device__ float g_vf   [(size_t)B_ * DIM_ * N_];
__device__ float g_u    [(size_t)B_ * AH_ * N_];
__device__ __half g_vt  [(size_t)B_ * N_ * AH_];       // v transposed (fp16)
__device__ int   g_idx  [(size_t)B_ * N_ * K_];
__device__ __half g_t1  [(size_t)B_ * PH_ * M_];       // pos conv1 out (fp16)
__device__ __half g_h   [(size_t)B_ * AH_ * M_];       // h (fp16, c-major)
__device__ float g_agg  [(size_t)B_ * DIM_ * N_];
__device__ float g_part [(size_t)B_ * 512 * AH_ * 2];
__device__ float g_partp[(size_t)PH_ * 512 * 2];
__device__ float g_Wuq  [AH_ * C_];
__device__ float g_Wvk  [AH_ * C_];
__device__ float g_bias1[AH_];
__device__ float g_scp  [PH_];
__device__ float g_shp  [PH_];
__device__ float g_sca  [AH_];
__device__ float g_sha  [AH_];
// fp16 image of att_w2: 16 K-chunks x 32KB = 512KB
__device__ unsigned int g_w2img[16 * 32768 / 4];
// fp16 image of Wmid = concat(att_w1@pos_w2, pos_w2): 10 chunks x 16KB
__device__ unsigned int g_wmidimg[10 * 16384 / 4];
// fp16 images of Wuq/Wvk: 8 c-chunks x 32KB (2 kc x 16KB)
__device__ unsigned int g_wuqimg[8 * 32768 / 4];
__device__ unsigned int g_wvkimg[8 * 32768 / 4];

// ---------------- helpers ---------------------------------------------------
__device__ __forceinline__ uint32_t smem_u32(const void* p) {
    uint32_t a;
    asm("{ .reg .u64 t; cvta.to.shared.u64 t, %1; cvt.u32.u64 %0, t; }" : "=r"(a) : "l"(p));
    return a;
}
#define SWZ128(b) ((b) ^ (((b) >> 3) & 0x70))
__device__ __forceinline__ uint32_t pack_h2(float a, float b) {
    __half2 t = __floats2half2_rn(a, b);
    return *reinterpret_cast<uint32_t*>(&t);
}
__device__ __forceinline__ void ldm_x4(uint32_t* r, uint32_t addr) {
    asm volatile("ldmatrix.sync.aligned.m8n8.x4.shared.b16 {%0,%1,%2,%3}, [%4];"
        : "=r"(r[0]), "=r"(r[1]), "=r"(r[2]), "=r"(r[3]) : "r"(addr));
}
__device__ __forceinline__ void mma16816h(float* d, const uint32_t* a, const uint32_t* b) {
    asm volatile(
        "mma.sync.aligned.m16n8k16.row.col.f32.f16.f16.f32 "
        "{%0,%1,%2,%3}, {%4,%5,%6,%7}, {%8,%9}, {%0,%1,%2,%3};"
        : "+f"(d[0]), "+f"(d[1]), "+f"(d[2]), "+f"(d[3])
        : "r"(a[0]), "r"(a[1]), "r"(a[2]), "r"(a[3]), "r"(b[0]), "r"(b[1]));
}
__device__ __forceinline__ void cp_async16(uint32_t dst, const void* src) {
    asm volatile("cp.async.cg.shared.global [%0], [%1], 16;" :: "r"(dst), "l"(src));
}
#define CP_COMMIT() asm volatile("cp.async.commit_group;" ::: "memory")
#define CP_WAIT0()  asm volatile("cp.async.wait_group 0;" ::: "memory")

// ---------------- concat ----------------------------------------------------
__global__ void concat_kernel(const float* __restrict__ key,
                              const float* __restrict__ query,
                              float* __restrict__ x) {
    size_t i = (size_t)blockIdx.x * blockDim.x + threadIdx.x;
    if (i >= (size_t)B_ * 2 * C_ * N_) return;
    int n = (int)(i % N_);
    int c = (int)((i / N_) % (2 * C_));
    int b = (int)(i / ((size_t)N_ * 2 * C_));
    float v;
    if (c < C_) v = key  [((size_t)b * C_ + c) * N_ + n];
    else        v = query[((size_t)b * C_ + (c - C_)) * N_ + n];
    x[i] = v;
}

// ---------------- KNN -------------------------------------------------------
__global__ void knn_kernel(const float* __restrict__ pos, int* __restrict__ idx) {
    const int b = blockIdx.y;
    const int n = blockIdx.x * blockDim.x + threadIdx.x;
    const float* p = pos + (size_t)b * 3 * N_;
    const float qx = p[n], qy = p[N_ + n], qz = p[2 * N_ + n];
    const float qs = qx * qx + qy * qy + qz * qz;
    float bd[K_]; int bi[K_];
#pragma unroll
    for (int j = 0; j < K_; j++) { bd[j] = 3.4e38f; bi[j] = 0; }
    __shared__ float sx[512], sy[512], sz[512], ss[512];
    for (int t0 = 0; t0 < N_; t0 += 512) {
        __syncthreads();
        for (int i = threadIdx.x; i < 512; i += blockDim.x) {
            float x = p[t0 + i], y = p[N_ + t0 + i], z = p[2 * N_ + t0 + i];
            sx[i] = x; sy[i] = y; sz[i] = z; ss[i] = x * x + y * y + z * z;
        }
        __syncthreads();
        for (int i = 0; i < 512; i++) {
            float d = qs + ss[i] - 2.0f * (qx * sx[i] + qy * sy[i] + qz * sz[i]);
            if (d < bd[K_ - 1]) {
                int j = K_ - 1;
                while (j > 0 && d < bd[j - 1]) { bd[j] = bd[j - 1]; bi[j] = bi[j - 1]; j--; }
                bd[j] = d; bi[j] = t0 + i;
            }
        }
    }
    int* op = idx + ((size_t)b * N_ + n) * K_;
#pragma unroll
    for (int j = 0; j < K_; j++) op[j] = bi[j];
}

// ---------------- precompute small products ---------------------------------
__global__ void smallmm_kernel(const float* __restrict__ A, const float* __restrict__ Bm,
                               float* __restrict__ Cc, int O, int Id, int J, int tr) {
    int t = blockIdx.x * 256 + threadIdx.x;
    if (t >= O * J) return;
    int o = t / J, j = t % J;
    float s = 0.0f;
    for (int d = 0; d < Id; d++) s += A[o * Id + d] * Bm[d * J + j];
    if (tr) Cc[j * O + o] = s; else Cc[o * J + j] = s;
}
__global__ void bias1_kernel(const float* __restrict__ w1, const float* __restrict__ bq,
                             const float* __restrict__ bk, const float* __restrict__ pb2,
                             const float* __restrict__ ab1, float* __restrict__ out) {
    int o = blockIdx.x * 256 + threadIdx.x;
    if (o >= AH_) return;
    float s = ab1[o];
    for (int d = 0; d < DIM_; d++) s += w1[o * DIM_ + d] * (bq[d] - bk[d] + pb2[d]);
    out[o] = s;
}

// ---------------- att_w2 -> pre-swizzled fp16 image --------------------------
__global__ void prep_w2_kernel(const float* __restrict__ w2, unsigned int* __restrict__ img) {
    int t = blockIdx.x * 256 + threadIdx.x;
    if (t >= 256 * 256) return;
    int c = t >> 8, k4 = t & 255;
    int k = k4 * 4;
    int q = k >> 6, kl = k & 63;
    const float* src = w2 + (size_t)c * AH_ + k;
    uint32_t off = SWZ128((uint32_t)((c >> 3) * 1024 + (c & 7) * 128 + kl * 2));
    char* base = (char*)img + (size_t)q * 32768;
    *(uint2*)(base + off) = make_uint2(pack_h2(src[0], src[1]), pack_h2(src[2], src[3]));
}

// ---------------- Wmid -> pre-swizzled fp16 image ----------------------------
__global__ void prep_wmid_kernel(const float* __restrict__ att_w1,
                                 const float* __restrict__ pos_w2,
                                 unsigned int* __restrict__ img) {
    int t = blockIdx.x * 256 + threadIdx.x;
    if (t >= 1280 * 16) return;
    int c = t >> 4, k4 = t & 15;
    float f[4];
    if (c < AH_) {
#pragma unroll 4
        for (int kk = 0; kk < 4; kk++) {
            float s = 0.0f;
            for (int d = 0; d < DIM_; d++)
                s += att_w1[(size_t)c * DIM_ + d] * pos_w2[d * PH_ + k4 * 4 + kk];
            f[kk] = s;
        }
    } else {
#pragma unroll
        for (int kk = 0; kk < 4; kk++) f[kk] = pos_w2[(c - AH_) * PH_ + k4 * 4 + kk];
    }
    int ct = c >> 7, cl = c & 127;
    uint32_t off = (uint32_t)((cl >> 3) * 1024 + (cl & 7) * 128 +
                              ((k4 * 8) ^ ((cl & 7) << 4)));
    char* base = (char*)img + (size_t)ct * 16384;
    *(uint2*)(base + off) = make_uint2(pack_h2(f[0], f[1]), pack_h2(f[2], f[3]));
}

// ---------------- Wuq/Wvk [AH][C=128] -> fp16 image: 8 c-chunks x 32KB --------
__global__ void prep_wuv_kernel(const float* __restrict__ W, unsigned int* __restrict__ img) {
    int t = blockIdx.x * 256 + threadIdx.x;
    if (t >= AH_ * 32) return;
    int c = t >> 5, k4 = t & 31;
    int k = k4 * 4;
    int kc = k >> 6, kl = k & 63;
    const float* src = W + (size_t)c * C_ + k;
    int ct = c >> 7, cl = c & 127;
    uint32_t off = (uint32_t)((cl >> 3) * 1024 + (cl & 7) * 128 +
                              ((kl * 2) ^ ((cl & 7) << 4)));
    char* base = (char*)img + (size_t)ct * 32768 + (size_t)kc * 16384;
    *(uint2*)(base + off) = make_uint2(pack_h2(src[0], src[1]), pack_h2(src[2], src[3]));
}

// ---------------- generic fp32 SGEMM (small GEMMs) --------------------------
template <int FLAGS>
__global__ void sgemm_kernel(const float* __restrict__ W, const float* __restrict__ Xg,
                             const float* __restrict__ bias, float* __restrict__ outg,
                             const float* __restrict__ resg, int O, int I, int M) {
    const int b = blockIdx.z;
    const float* X = Xg + (size_t)b * I * M;
    float* out = outg + (size_t)b * O * M;
    const float* res = (FLAGS & 4) ? (resg + (size_t)b * O * M) : nullptr;
    __shared__ float Ws[8][132];
    __shared__ float Xs[8][128];
    const int tid = threadIdx.x;
    const int tx = tid & 15, ty = tid >> 4;
    const int o0 = blockIdx.y * 128, m0 = blockIdx.x * 128;
    const int wr = tid >> 1, wc = (tid & 1) * 4;
    const int xr = tid >> 5, xc = (tid & 31) * 4;
    float acc[8][8];
#pragma unroll
    for (int i = 0; i < 8; i++)
#pragma unroll
        for (int j = 0; j < 8; j++) acc[i][j] = 0.0f;
    for (int kt = 0; kt < I; kt += 8) {
        float4 wv = *(const float4*)&W[(size_t)(o0 + wr) * I + kt + wc];
        float4 xv = *(const float4*)&X[(size_t)(kt + xr) * M + m0 + xc];
        __syncthreads();
        Ws[wc + 0][wr] = wv.x; Ws[wc + 1][wr] = wv.y;
        Ws[wc + 2][wr] = wv.z; Ws[wc + 3][wr] = wv.w;
        *(float4*)&Xs[xr][xc] = xv;
        __syncthreads();
#pragma unroll
        for (int k = 0; k < 8; k++) {
            float a[8], bb[8];
            *(float4*)&a[0]  = *(const float4*)&Ws[k][ty * 8];
            *(float4*)&a[4]  = *(const float4*)&Ws[k][ty * 8 + 4];
            *(float4*)&bb[0] = *(const float4*)&Xs[k][tx * 8];
            *(float4*)&bb[4] = *(const float4*)&Xs[k][tx * 8 + 4];
#pragma unroll
            for (int i = 0; i < 8; i++)
#pragma unroll
                for (int j = 0; j < 8; j++) acc[i][j] += a[i] * bb[j];
        }
    }
#pragma unroll
    for (int i = 0; i < 8; i++) {
        const int o = o0 + ty * 8 + i;
        const float bv = bias[o];
        float* orow = out + (size_t)o * M + m0 + tx * 8;
        const float* rrow = (FLAGS & 4) ? (res + (size_t)o * M + m0 + tx * 8) : nullptr;
#pragma unroll
        for (int jj = 0; jj < 8; jj += 4) {
            float4 v;
            v.x = acc[i][jj + 0] + bv; v.y = acc[i][jj + 1] + bv;
            v.z = acc[i][jj + 2] + bv; v.w = acc[i][jj + 3] + bv;
            if (FLAGS & 1) { v.x = fmaxf(v.x, 0.f); v.y = fmaxf(v.y, 0.f);
                             v.z = fmaxf(v.z, 0.f); v.w = fmaxf(v.w, 0.f); }
            if (FLAGS & 2) { float4 old = *(float4*)&orow[jj];
                             v.x += old.x; v.y += old.y; v.z += old.z; v.w += old.w; }
            if (FLAGS & 4) { float4 r = *(const float4*)&rrow[jj];
                             v.x += r.x; v.y += r.y; v.z += r.z; v.w += r.w; }
            *(float4*)&orow[jj] = v;
        }
    }
}

// ---------------- pos_rel conv1 + BN partial stats (fp16 t1 out) -------------
__global__ void posrel_kernel(const float* __restrict__ pos, const int* __restrict__ idx,
                              const float* __restrict__ w, const float* __restrict__ bias,
                              __half* __restrict__ t1, float* __restrict__ part) {
    size_t i = (size_t)blockIdx.x * 256 + threadIdx.x;
    int k = (int)(i & 15);
    int n = (int)((i >> 4) & (N_ - 1));
    int c = (int)((i >> 16) & (PH_ - 1));
    int b = (int)(i >> 22);
    int m = idx[(((size_t)b * N_ + n) << 4) + k];
    const float* p = pos + (size_t)b * 3 * N_;
    float rx = p[n] - p[m];
    float ry = p[N_ + n] - p[N_ + m];
    float rz = p[2 * N_ + n] - p[2 * N_ + m];
    float val = w[c * 3] * rx + w[c * 3 + 1] * ry + w[c * 3 + 2] * rz + bias[c];
    t1[i] = __float2half(val);
    __shared__ float ssum[256], ssq[256];
    ssum[threadIdx.x] = val; ssq[threadIdx.x] = val * val;
    __syncthreads();
    for (int st = 128; st > 0; st >>= 1) {
        if ((int)threadIdx.x < st) {
            ssum[threadIdx.x] += ssum[threadIdx.x + st];
            ssq[threadIdx.x]  += ssq[threadIdx.x + st];
        }
        __syncthreads();
    }
    if (threadIdx.x == 0) {
        int cb = (blockIdx.x >> 8) & (PH_ - 1);
        int bb = blockIdx.x >> 14;
        int sblk = blockIdx.x & 255;
        size_t o = ((size_t)cb * 512 + bb * 256 + sblk) * 2;
        part[o] = ssum[0]; part[o + 1] = ssq[0];
    }
}

// ---------------- BN finalize ------------------------------------------------
__global__ void finalize_stats(const float* __restrict__ part, int P, int ps, int cs,
                               const float* __restrict__ g, const float* __restrict__ be,
                               float* __restrict__ sc, float* __restrict__ sh, float cnt) {
    int c = blockIdx.x;
    double s = 0.0, q = 0.0;
    for (int p = threadIdx.x; p < P; p += blockDim.x) {
        size_t o = ((size_t)p * ps + (size_t)c * cs) * 2;
        s += (double)part[o]; q += (double)part[o + 1];
    }
    __shared__ double S[256], Q[256];
    S[threadIdx.x] = s; Q[threadIdx.x] = q;
    __syncthreads();
    for (int st = 128; st > 0; st >>= 1) {
        if ((int)threadIdx.x < st) {
            S[threadIdx.x] += S[threadIdx.x + st];
            Q[threadIdx.x] += Q[threadIdx.x + st];
        }
        __syncthreads();
    }
    if (threadIdx.x == 0) {
        double mean = S[0] / (double)cnt;
        double var  = Q[0] / (double)cnt - mean * mean;
        float scv = g[c] * (float)(1.0 / sqrt(var + 1e-5));
        sc[c] = scv;
        sh[c] = be[c] - (float)mean * scv;
    }
}

// ---------------- u/v GEMM on fp16 HMMA (single W buf, 2 blocks/SM) ----------
#define UV_X     0
#define UV_W     32768
#define UV_TR    65536
#define UV_SMEM  100352

__global__ __launch_bounds__(256, 2) void uv_hmma(
    const float* __restrict__ query, const float* __restrict__ key,
    const unsigned int* __restrict__ wuqimg, const unsigned int* __restrict__ wvkimg,
    float* __restrict__ ug, __half* __restrict__ vt) {
    extern __shared__ char smc[];
    const uint32_t sb = smem_u32(smc);
    const int tid = threadIdx.x, lane = tid & 31, wid = tid >> 5;
    const int z = blockIdx.y;
    const int b = z & 1, which = z >> 1;
    const int n0 = blockIdx.x * 128;
    const float* X = (which == 0 ? query : key) + (size_t)b * C_ * N_;
    const unsigned int* wimg = (which == 0 ? wuqimg : wvkimg);
    float* uout = ug + (size_t)b * AH_ * N_;
    const int warp_cg = wid >> 1;
    const int warp_mg = wid & 1;

    {
        const uint4* src = (const uint4*)wimg;
        uint32_t dst = sb + UV_W;
#pragma unroll
        for (int it = 0; it < 8; it++)
            cp_async16(dst + (it * 256 + tid) * 16, src + it * 256 + tid);
        CP_COMMIT();
    }
    {
        char* xbase = smc + UV_X;
        int m = tid & 127, khalf = tid >> 7;
#pragma unroll
        for (int k2 = 0; k2 < 32; k2++) {
            int k = khalf * 64 + k2 * 2;
            int kl = k & 63;
            float x0 = X[(size_t)k * N_ + n0 + m];
            float x1 = X[(size_t)(k + 1) * N_ + n0 + m];
            uint32_t off = (uint32_t)((m >> 3) * 1024 + (m & 7) * 128 +
                                      ((kl * 2) ^ ((m & 7) << 4)));
            char* dst = xbase + khalf * 16384;
            *(uint32_t*)(dst + off) = pack_h2(x0, x1);
        }
    }
    CP_WAIT0();
    __syncthreads();

    const int g = lane >> 3, lr = lane & 7;
    const int wrow = warp_cg * 32 + (g & 1) * 8 + lr;
    const int xrow = warp_mg * 64 + (g >> 1) * 8 + lr;
    const int wkb0 = (g >> 1) * 16;
    const int xkb0 = (g & 1) * 16;
    const uint32_t sX = sb + UV_X;
    const uint32_t sW = sb + UV_W;

    for (int ct = 0; ct < 8; ct++) {
        float acc[2][8][4];
#pragma unroll
        for (int a = 0; a < 2; a++)
#pragma unroll
            for (int q = 0; q < 8; q++)
#pragma unroll
                for (int j = 0; j < 4; j++) acc[a][q][j] = 0.0f;
#pragma unroll
        for (int kc = 0; kc < 2; kc++) {
#pragma unroll
            for (int ks = 0; ks < 4; ks++) {
                uint32_t Wf[2][4], Xf[4][4];
#pragma unroll
                for (int ct2 = 0; ct2 < 2; ct2++) {
                    int cr = wrow + ct2 * 16;
                    uint32_t ro = (uint32_t)((cr >> 3) * 1024 + (cr & 7) * 128);
                    uint32_t kb = (uint32_t)((ks * 32 + wkb0) ^ ((cr & 7) << 4));
                    ldm_x4(Wf[ct2], sW + kc * 16384 + ro + kb);
                }
#pragma unroll
                for (int np = 0; np < 4; np++) {
                    int mr = xrow + np * 16;
                    uint32_t ro = (uint32_t)((mr >> 3) * 1024 + (mr & 7) * 128);
                    uint32_t kb = (uint32_t)((ks * 32 + xkb0) ^ ((mr & 7) << 4));
                    ldm_x4(Xf[np], sX + kc * 16384 + ro + kb);
                }
#pragma unroll
                for (int ct2 = 0; ct2 < 2; ct2++)
#pragma unroll
                    for (int np = 0; np < 4; np++) {
                        mma16816h(acc[ct2][np * 2],     Wf[ct2], &Xf[np][0]);
                        mma16816h(acc[ct2][np * 2 + 1], Wf[ct2], &Xf[np][2]);
                    }
            }
        }
        if (which == 0) {
#pragma unroll
            for (int ct2 = 0; ct2 < 2; ct2++) {
#pragma unroll
                for (int j = 0; j < 4; j++) {
                    int c_g = ct * 128 + warp_cg * 32 + ct2 * 16 + (lane >> 2) + (j >> 1) * 8;
                    float* orow = uout + (size_t)c_g * N_ + n0;
#pragma unroll
                    for (int q = 0; q < 8; q++) {
                        int m_loc = warp_mg * 64 + q * 8 + (lane & 3) * 2 + (j & 1);
                        orow[m_loc] = acc[ct2][q][j];
                    }
                }
            }
        } else {
            __half* trs = (__half*)(smc + UV_TR);
#pragma unroll
            for (int ct2 = 0; ct2 < 2; ct2++)
#pragma unroll
                for (int j = 0; j < 4; j++) {
                    int c_loc = warp_cg * 32 + ct2 * 16 + (lane >> 2) + (j >> 1) * 8;
#pragma unroll
                    for (int q = 0; q < 8; q++) {
                        int m_loc = warp_mg * 64 + q * 8 + (lane & 3) * 2 + (j & 1);
                        trs[m_loc * 136 + c_loc] = __float2half(acc[ct2][q][j]);
                    }
                }
            __syncthreads();
            __half* dvt = vt + ((size_t)b * N_ + n0) * AH_ + ct * 128;
#pragma unroll
            for (int it = 0; it < 8; it++) {
                int e = it * 256 + tid;
                int row = e >> 4, col = e & 15;
                *(uint4*)(dvt + (size_t)row * AH_ + col * 8) =
                    *(uint4*)&trs[row * 136 + col * 8];
            }
        }
        if (ct + 1 < 8) {
            __syncthreads();   // all reads of W done before overwrite
            const uint4* src = (const uint4*)wimg + (ct + 1) * 2048;
            uint32_t dst = sb + UV_W;
#pragma unroll
            for (int it = 0; it < 8; it++)
                cp_async16(dst + (it * 256 + tid) * 16, src + it * 256 + tid);
            CP_COMMIT();
            CP_WAIT0();
            __syncthreads();
        }
    }
}

// ---------------- fused mid on fp16 HMMA (h only) ----------------------------
#define FM_X     0
#define FM_W(s)  (16384 + (s) * 16384)
#define FM_VG    49152
#define FM_U     82944
#define FM_RED   87552
#define FM_SIDX  89600
#define FM_SMEM  90112

__global__ __launch_bounds__(256, 2) void fused_mid_hmma(
    const __half* __restrict__ t1, const float* __restrict__ psc,
    const float* __restrict__ psh, const unsigned int* __restrict__ wimg,
    const float* __restrict__ bias1, const float* __restrict__ u,
    const __half* __restrict__ vt, const int* __restrict__ idx,
    __half* __restrict__ h, float* __restrict__ part) {
    extern __shared__ char smc[];
    const uint32_t sb = smem_u32(smc);
    const int tid = threadIdx.x, lane = tid & 31, wid = tid >> 5;
    const int b = blockIdx.y, m0 = blockIdx.x * 128;
    const int warp_cg = wid >> 1;
    const int warp_mg = wid & 1;

    int* sidx = (int*)(smc + FM_SIDX);
    __half* vgsh = (__half*)(smc + FM_VG);
    float* us  = (float*)(smc + FM_U);
    float* redS = (float*)(smc + FM_RED);
    float* redQ = redS + 256;

    if (tid < 128) sidx[tid] = idx[((size_t)b * N_ + (m0 >> 4)) * K_ + tid];

    {
        const uint4* src = (const uint4*)wimg;
        uint32_t dst = sb + FM_W(0);
#pragma unroll
        for (int it = 0; it < 4; it++)
            cp_async16(dst + (it * 256 + tid) * 16, src + it * 256 + tid);
        CP_COMMIT();
    }
    {
        const __half* tb = t1 + (size_t)b * PH_ * M_ + m0;
        char* xd = smc + FM_X;
        int m = tid & 127, khalf = tid >> 7;
#pragma unroll
        for (int k2 = 0; k2 < 16; k2++) {
            int k = khalf * 32 + k2 * 2;
            float x0 = __half2float(tb[(size_t)k * M_ + m]);
            float x1 = __half2float(tb[(size_t)(k + 1) * M_ + m]);
            x0 = fmaxf(x0 * psc[k] + psh[k], 0.f);
            x1 = fmaxf(x1 * psc[k + 1] + psh[k + 1], 0.f);
            uint32_t off = (uint32_t)((m >> 3) * 1024 + (m & 7) * 128 +
                                      ((k * 2) ^ ((m & 7) << 4)));
            *(uint32_t*)(xd + off) = pack_h2(x0, x1);
        }
    }
    CP_WAIT0();
    __syncthreads();

    const int g = lane >> 3, lr = lane & 7;
    const int wrow = warp_cg * 32 + (g & 1) * 8 + lr;
    const int xrow = warp_mg * 64 + (g >> 1) * 8 + lr;
    const int wkb0 = (g >> 1) * 16;
    const int xkb0 = (g & 1) * 16;
    const uint32_t sX = sb + FM_X;
    const __half* vtb = vt + (size_t)b * N_ * AH_;
    const int n0 = m0 >> 4;

    for (int ct = 0; ct < 8; ct++) {
        const int s = ct & 1;
        if (ct + 1 < 8) {
            const uint4* src = (const uint4*)wimg + (ct + 1) * 1024;
            uint32_t dst = sb + FM_W(s ^ 1);
#pragma unroll
            for (int it = 0; it < 4; it++)
                cp_async16(dst + (it * 256 + tid) * 16, src + it * 256 + tid);
            CP_COMMIT();
        }
        {
#pragma unroll
            for (int jj = 0; jj < 16; jj++) {
                int j = wid * 16 + jj;
                const __half* row = vtb + (size_t)sidx[j] * AH_ + ct * 128;
#pragma unroll
                for (int cc = 0; cc < 2; cc++) {
                    int c = cc * 64 + lane * 2;
                    __half2 hv = *(const __half2*)(row + c);
                    vgsh[c * 132 + j] = hv.x;
                    vgsh[(c + 1) * 132 + j] = hv.y;
                }
            }
#pragma unroll
            for (int it = 0; it < 4; it++) {
                int e = it * 256 + tid;
                int c = e >> 3, nn = e & 7;
                us[c * 9 + nn] = u[((size_t)b * AH_ + ct * 128 + c) * N_ + n0 + nn]
                               + bias1[ct * 128 + c];
            }
        }
        const uint32_t sW = sb + FM_W(s);
        float acc[2][8][4];
#pragma unroll
        for (int a = 0; a < 2; a++)
#pragma unroll
            for (int q = 0; q < 8; q++)
#pragma unroll
                for (int j = 0; j < 4; j++) acc[a][q][j] = 0.0f;
#pragma unroll
        for (int ks = 0; ks < 4; ks++) {
            uint32_t Wf[2][4], Xf[4][4];
#pragma unroll
            for (int ct2 = 0; ct2 < 2; ct2++) {
                int cr = wrow + ct2 * 16;
                uint32_t ro = (uint32_t)((cr >> 3) * 1024 + (cr & 7) * 128);
                uint32_t kb = (uint32_t)((ks * 32 + wkb0) ^ ((cr & 7) << 4));
                ldm_x4(Wf[ct2], sW + ro + kb);
            }
#pragma unroll
            for (int np = 0; np < 4; np++) {
                int mr = xrow + np * 16;
                uint32_t ro = (uint32_t)((mr >> 3) * 1024 + (mr & 7) * 128);
                uint32_t kb = (uint32_t)((ks * 32 + xkb0) ^ ((mr & 7) << 4));
                ldm_x4(Xf[np], sX + ro + kb);
            }
#pragma unroll
            for (int ct2 = 0; ct2 < 2; ct2++)
#pragma unroll
                for (int np = 0; np < 4; np++) {
                    mma16816h(acc[ct2][np * 2],     Wf[ct2], &Xf[np][0]);
                    mma16816h(acc[ct2][np * 2 + 1], Wf[ct2], &Xf[np][2]);
                }
        }
        __syncthreads();
        {
            float sS[2][2], sQ[2][2];
#pragma unroll
            for (int a = 0; a < 2; a++) { sS[a][0] = sS[a][1] = 0.f; sQ[a][0] = sQ[a][1] = 0.f; }
#pragma unroll
            for (int ct2 = 0; ct2 < 2; ct2++) {
#pragma unroll
                for (int rh = 0; rh < 2; rh++) {
                    int c_loc = warp_cg * 32 + ct2 * 16 + (lane >> 2) + rh * 8;
                    int c_g = ct * 128 + c_loc;
                    __half* hrow = h + ((size_t)b * AH_ + c_g) * M_ + m0;
#pragma unroll
                    for (int q = 0; q < 8; q++) {
                        int m_loc = warp_mg * 64 + q * 8 + (lane & 3) * 2;
                        float base = us[c_loc * 9 + (m_loc >> 4)];
                        float v0 = acc[ct2][q][rh * 2]     + base
                                 - __half2float(vgsh[c_loc * 132 + m_loc]);
                        float v1 = acc[ct2][q][rh * 2 + 1] + base
                                 - __half2float(vgsh[c_loc * 132 + m_loc + 1]);
                        *(__half2*)(hrow + m_loc) = __floats2half2_rn(v0, v1);
                        sS[ct2][rh] += v0 + v1;
                        sQ[ct2][rh] += v0 * v0 + v1 * v1;
                    }
                }
            }
#pragma unroll
            for (int ct2 = 0; ct2 < 2; ct2++)
#pragma unroll
                for (int rh = 0; rh < 2; rh++) {
                    float s1 = sS[ct2][rh], q1 = sQ[ct2][rh];
                    s1 += __shfl_xor_sync(0xffffffffu, s1, 1);
                    s1 += __shfl_xor_sync(0xffffffffu, s1, 2);
                    q1 += __shfl_xor_sync(0xffffffffu, q1, 1);
                    q1 += __shfl_xor_sync(0xffffffffu, q1, 2);
                    if ((lane & 3) == 0) {
                        int c_loc = warp_cg * 32 + ct2 * 16 + (lane >> 2) + rh * 8;
                        redS[c_loc * 2 + warp_mg] = s1;
                        redQ[c_loc * 2 + warp_mg] = q1;
                    }
                }
            __syncthreads();
            if (tid < 128) {
                float ss = redS[tid * 2] + redS[tid * 2 + 1];
                float qq = redQ[tid * 2] + redQ[tid * 2 + 1];
                size_t po = (((size_t)b * 512 + blockIdx.x) * AH_ + ct * 128 + tid) * 2;
                part[po] = ss; part[po + 1] = qq;
            }
        }
        CP_WAIT0();
        __syncthreads();
    }
}

// ---------------- attn GEMM2 (fp16 HMMA; c-halved, 2 blocks/SM) --------------
#define A2_A      0
#define A2_B(s)   (16384 + (s) * 16384)
#define A2_STG    49152
#define A2_PES    65536
#define SMEM_ATT2 99328

__device__ __forceinline__ void attn2_cpasync(uint32_t sb, int s, int cq, int ch,
                                              const __half* hbase, const uint4* w2img,
                                              int tid) {
    const uint4* src = w2img + (size_t)cq * 2048 + ch * 1024;
    uint32_t bdst = sb + A2_B(s);
#pragma unroll
    for (int it = 0; it < 4; it++) {
        int i = it * 256 + tid;
        cp_async16(bdst + i * 16, src + i);
    }
#pragma unroll
    for (int it = 0; it < 4; it++) {
        int ch2 = it * 256 + tid;
        int krow = ch2 >> 4, off = ch2 & 15;
        const __half* srcr = hbase + (size_t)(cq * 64 + krow) * M_ + off * 8;
        cp_async16(sb + A2_STG + krow * 256 + off * 16, srcr);
    }
}

__device__ __forceinline__ void attn2_convert(char* smc, int cq,
                                              const float* __restrict__ scale,
                                              const float* __restrict__ shift,
                                              int wid, int lane) {
    const __half* stg = (const __half*)(smc + A2_STG);
    char* dst = smc + A2_A;
#pragma unroll
    for (int g2 = 0; g2 < 2; g2++) {
        int base_k = wid * 8 + g2 * 4;
        float X[4][4];
#pragma unroll
        for (int r = 0; r < 4; r++) {
            uint2 raw = *(const uint2*)&stg[(base_k + r) * 128 + lane * 4];
            float2 f01 = __half22float2(*(__half2*)&raw.x);
            float2 f23 = __half22float2(*(__half2*)&raw.y);
            float sc = scale[cq * 64 + base_k + r];
            float sh = shift[cq * 64 + base_k + r];
            X[0][r] = fmaxf(f01.x * sc + sh, 0.f);
            X[1][r] = fmaxf(f01.y * sc + sh, 0.f);
            X[2][r] = fmaxf(f23.x * sc + sh, 0.f);
            X[3][r] = fmaxf(f23.y * sc + sh, 0.f);
        }
#pragma unroll
        for (int mm = 0; mm < 4; mm++) {
            int m = lane * 4 + mm;
            uint32_t off = (uint32_t)((m >> 3) * 1024 + (m & 7) * 128 +
                                      ((base_k * 2) ^ ((m & 7) << 4)));
            *(uint2*)(dst + off) = make_uint2(pack_h2(X[mm][0], X[mm][1]),
                                              pack_h2(X[mm][2], X[mm][3]));
        }
    }
}

__global__ __launch_bounds__(256, 2) void attn2_hmma_kernel(
    const uint4* __restrict__ w2img, const __half* __restrict__ h,
    const float* __restrict__ scale, const float* __restrict__ shift,
    const __half* __restrict__ t1, const float* __restrict__ psc,
    const float* __restrict__ psh, const uint4* __restrict__ wmid89,
    const float* __restrict__ pos_b2, const float* __restrict__ vf,
    float* __restrict__ agg) {
    extern __shared__ char smc[];
    const uint32_t sb = smem_u32(smc);
    const int tid = threadIdx.x, lane = tid & 31, wid = tid >> 5;
    const int b = blockIdx.y >> 1, ch = blockIdx.y & 1;
    const int m0 = blockIdx.x * 128;
    const int warp_m = wid >> 2, warp_c = wid & 3;

    const __half* hbase = h + (size_t)b * AH_ * M_ + m0;

    const int g = lane >> 3, lr = lane & 7;
    const int amr  = warp_m * 64 + (g & 1) * 8 + lr;
    const int bcr  = warp_c * 32 + (g >> 1) * 8 + lr;
    const int akb0 = (g >> 1) * 16;
    const int bkb0 = (g & 1) * 16;

    float acc[4][4][4];

    // ---- phase 1: compute pe tile (this c-half) into pes smem ----
    {
        {
            const uint4* src = wmid89 + ch * 1024;
            uint32_t dst = sb + A2_B(0);
#pragma unroll
            for (int it = 0; it < 4; it++)
                cp_async16(dst + (it * 256 + tid) * 16, src + it * 256 + tid);
            CP_COMMIT();
        }
        {
            const __half* tb = t1 + (size_t)b * PH_ * M_ + m0;
            char* xd = smc + A2_A;
            int m = tid & 127, khalf = tid >> 7;
#pragma unroll
            for (int k2 = 0; k2 < 16; k2++) {
                int k = khalf * 32 + k2 * 2;
                float x0 = __half2float(tb[(size_t)k * M_ + m]);
                float x1 = __half2float(tb[(size_t)(k + 1) * M_ + m]);
                x0 = fmaxf(x0 * psc[k] + psh[k], 0.f);
                x1 = fmaxf(x1 * psc[k + 1] + psh[k + 1], 0.f);
                uint32_t off = (uint32_t)((m >> 3) * 1024 + (m & 7) * 128 +
                                          ((k * 2) ^ ((m & 7) << 4)));
                *(uint32_t*)(xd + off) = pack_h2(x0, x1);
            }
        }
        CP_WAIT0();
        __syncthreads();
#pragma unroll
        for (int mt = 0; mt < 4; mt++)
#pragma unroll
            for (int nt = 0; nt < 4; nt++)
#pragma unroll
                for (int j = 0; j < 4; j++) acc[mt][nt][j] = 0.0f;
        const uint32_t sA = sb + A2_A;
        const uint32_t sB = sb + A2_B(0);
#pragma unroll
        for (int ks = 0; ks < 4; ks++) {
            uint32_t Af[4][4], Bf[2][4];
#pragma unroll
            for (int mt = 0; mt < 4; mt++) {
                int m = amr + mt * 16;
                uint32_t ro = (uint32_t)((m >> 3) * 1024 + (m & 7) * 128);
                uint32_t kb = (uint32_t)((ks * 32 + akb0) ^ ((m & 7) << 4));
                ldm_x4(Af[mt], sA + ro + kb);
            }
#pragma unroll
            for (int np = 0; np < 2; np++) {
                int c = bcr + np * 16;
                uint32_t ro = (uint32_t)((c >> 3) * 1024 + (c & 7) * 128);
                uint32_t kb = (uint32_t)((ks * 32 + bkb0) ^ ((c & 7) << 4));
                ldm_x4(Bf[np], sB + ro + kb);
            }
#pragma unroll
            for (int mt = 0; mt < 4; mt++)
#pragma unroll
                for (int np = 0; np < 2; np++) {
                    mma16816h(acc[mt][np * 2],     Af[mt], &Bf[np][0]);
                    mma16816h(acc[mt][np * 2 + 1], Af[mt], &Bf[np][2]);
                }
        }
        __half* pesh = (__half*)(smc + A2_PES);
        const int r = lane >> 2;
#pragma unroll
        for (int mt = 0; mt < 4; mt++) {
            int mbase = warp_m * 64 + mt * 16;
#pragma unroll
            for (int nt = 0; nt < 4; nt++)
#pragma unroll
                for (int j = 0; j < 2; j++) {
                    int c = warp_c * 32 + nt * 8 + (lane & 3) * 2 + j;
                    float bv = pos_b2[ch * 128 + c];
                    pesh[c * 132 + mbase + r]     = __float2half(acc[mt][nt][j] + bv);
                    pesh[c * 132 + mbase + r + 8] = __float2half(acc[mt][nt][2 + j] + bv);
                }
        }
        __syncthreads();
    }

    // ---- main loop: logits GEMM (this c-half) ----
#pragma unroll
    for (int mt = 0; mt < 4; mt++)
#pragma unroll
        for (int nt = 0; nt < 4; nt++)
#pragma unroll
            for (int j = 0; j < 4; j++) acc[mt][nt][j] = 0.0f;

    attn2_cpasync(sb, 0, 0, ch, hbase, w2img, tid);
    CP_COMMIT();
    CP_WAIT0();
    __syncthreads();
    attn2_convert(smc, 0, scale, shift, wid, lane);
    __syncthreads();

    for (int cq = 0; cq < 16; cq++) {
        const int s = cq & 1;
        if (cq + 1 < 16) {
            attn2_cpasync(sb, s ^ 1, cq + 1, ch, hbase, w2img, tid);
            CP_COMMIT();
        }
        const uint32_t sA = sb + A2_A;
        const uint32_t sB = sb + A2_B(s);
#pragma unroll
        for (int ks = 0; ks < 4; ks++) {
            uint32_t Af[4][4], Bf[2][4];
#pragma unroll
            for (int mt = 0; mt < 4; mt++) {
                int m = amr + mt * 16;
                uint32_t ro = (uint32_t)((m >> 3) * 1024 + (m & 7) * 128);
                uint32_t kb = (uint32_t)((ks * 32 + akb0) ^ ((m & 7) << 4));
                ldm_x4(Af[mt], sA + ro + kb);
            }
#pragma unroll
            for (int np = 0; np < 2; np++) {
                int c = bcr + np * 16;
                uint32_t ro = (uint32_t)((c >> 3) * 1024 + (c & 7) * 128);
                uint32_t kb = (uint32_t)((ks * 32 + bkb0) ^ ((c & 7) << 4));
                ldm_x4(Bf[np], sB + ro + kb);
            }
#pragma unroll
            for (int mt = 0; mt < 4; mt++)
#pragma unroll
                for (int np = 0; np < 2; np++) {
                    mma16816h(acc[mt][np * 2],     Af[mt], &Bf[np][0]);
                    mma16816h(acc[mt][np * 2 + 1], Af[mt], &Bf[np][2]);
                }
        }
        if (cq + 1 < 16) {
            CP_WAIT0();
            __syncthreads();
            attn2_convert(smc, cq + 1, scale, shift, wid, lane);
            __syncthreads();
        }
    }
    __syncthreads();

    // ---- epilogue: softmax + aggregation ----
    const __half* pesh = (const __half*)(smc + A2_PES);
#pragma unroll
    for (int mt = 0; mt < 4; mt++) {
        const int mbase = warp_m * 64 + mt * 16;
        const int n = (m0 + mbase) >> 4;
        const int r = lane >> 2;
#pragma unroll
        for (int nt = 0; nt < 4; nt++) {
#pragma unroll
            for (int j = 0; j < 2; j++) {
                int c = warp_c * 32 + nt * 8 + (lane & 3) * 2 + j;
                float v0 = acc[mt][nt][j], v1 = acc[mt][nt][2 + j];
                float mx = fmaxf(v0, v1);
                mx = fmaxf(mx, __shfl_xor_sync(0xffffffffu, mx, 4));
                mx = fmaxf(mx, __shfl_xor_sync(0xffffffffu, mx, 8));
                mx = fmaxf(mx, __shfl_xor_sync(0xffffffffu, mx, 16));
                float e0 = __expf(v0 - mx), e1 = __expf(v1 - mx);
                float se = e0 + e1;
                se += __shfl_xor_sync(0xffffffffu, se, 4);
                se += __shfl_xor_sync(0xffffffffu, se, 8);
                se += __shfl_xor_sync(0xffffffffu, se, 16);
                float p0 = __half2float(pesh[c * 132 + mbase + r]);
                float p1 = __half2float(pesh[c * 132 + mbase + r + 8]);
                float t = e0 * p0 + e1 * p1;
                t += __shfl_xor_sync(0xffffffffu, t, 4);
                t += __shfl_xor_sync(0xffffffffu, t, 8);
                t += __shfl_xor_sync(0xffffffffu, t, 16);
                if (r == 0) {
                    size_t o = ((size_t)(b * DIM_ + ch * 128 + c)) * N_ + n;
                    agg[o] = vf[o] + t / se;
                }
            }
        }
    }
}

// ---------------- launch ----------------------------------------------------
extern "C" void kernel_launch(void* const* d_in, const int* in_sizes, int n_in,
                              void* d_out, int out_size) {
    const float* pos     = (const float*)d_in[0];
    const float* key     = (const float*)d_in[1];
    const float* query   = (const float*)d_in[2];
    const float* mlpv_w1 = (const float*)d_in[3];
    const float* mlpv_b1 = (const float*)d_in[4];
    const float* mlpv_w2 = (const float*)d_in[5];
    const float* mlpv_b2 = (const float*)d_in[6];
    const float* mlpv_ws = (const float*)d_in[7];
    const float* mlpv_bs = (const float*)d_in[8];
    const float* wk      = (const float*)d_in[9];
    const float* bk      = (const float*)d_in[10];
    const float* wq      = (const float*)d_in[11];
    const float* bq      = (const float*)d_in[12];
    const float* wv      = (const float*)d_in[13];
    const float* bv      = (const float*)d_in[14];
    const float* pos_w1  = (const float*)d_in[15];
    const float* pos_b1  = (const float*)d_in[16];
    const float* pos_g1  = (const float*)d_in[17];
    const float* pos_be1 = (const float*)d_in[18];
    const float* pos_w2  = (const float*)d_in[19];
    const float* pos_b2  = (const float*)d_in[20];
    const float* att_w1  = (const float*)d_in[21];
    const float* att_b1  = (const float*)d_in[22];
    const float* att_g1  = (const float*)d_in[23];
    const float* att_be1 = (const float*)d_in[24];
    const float* att_w2  = (const float*)d_in[25];
    const float* we      = (const float*)d_in[27];
    const float* be      = (const float*)d_in[28];
    float* out = (float*)d_out;

    void* p;
#define GETP(sym, var) cudaGetSymbolAddress(&p, sym); float* var = (float*)p;
    GETP(g_x, x_)       GETP(g_t, t_)       GETP(g_value, val)
    GETP(g_vf, vf_)     GETP(g_u, u_)
    GETP(g_agg, agg)    GETP(g_part, part)  GETP(g_partp, partp)
    GETP(g_Wuq, Wuq)    GETP(g_Wvk, Wvk)    GETP(g_bias1, bias1)
    GETP(g_scp, scp)    GETP(g_shp, shp)    GETP(g_sca, sca)
    GETP(g_sha, sha)
#undef GETP
    cudaGetSymbolAddress(&p, g_idx);      int* idx = (int*)p;
    cudaGetSymbolAddress(&p, g_vt);       __half* vt_ = (__half*)p;
    cudaGetSymbolAddress(&p, g_t1);       __half* t1_ = (__half*)p;
    cudaGetSymbolAddress(&p, g_h);        __half* h_ = (__half*)p;
    cudaGetSymbolAddress(&p, g_w2img);    unsigned int* w2img = (unsigned int*)p;
    cudaGetSymbolAddress(&p, g_wmidimg);  unsigned int* wmidimg = (unsigned int*)p;
    cudaGetSymbolAddress(&p, g_wuqimg);   unsigned int* wuqimg = (unsigned int*)p;
    cudaGetSymbolAddress(&p, g_wvkimg);   unsigned int* wvkimg = (unsigned int*)p;

    // --- precompute folded weights + weight images ---
    smallmm_kernel<<<(AH_ * C_ + 255) / 256, 256>>>(att_w1, wq, Wuq, AH_, DIM_, C_, 0);
    smallmm_kernel<<<(AH_ * C_ + 255) / 256, 256>>>(att_w1, wk, Wvk, AH_, DIM_, C_, 0);
    bias1_kernel<<<(AH_ + 255) / 256, 256>>>(att_w1, bq, bk, pos_b2, att_b1, bias1);
    prep_w2_kernel<<<(256 * 256) / 256, 256>>>(att_w2, w2img);
    prep_wmid_kernel<<<(1280 * 16 + 255) / 256, 256>>>(att_w1, pos_w2, wmidimg);
    prep_wuv_kernel<<<(AH_ * 32 + 255) / 256, 256>>>(Wuq, wuqimg);
    prep_wuv_kernel<<<(AH_ * 32 + 255) / 256, 256>>>(Wvk, wvkimg);

    // --- front end ---
    concat_kernel<<<(unsigned)(((size_t)B_ * 2 * C_ * N_ + 255) / 256), 256>>>(key, query, x_);
    knn_kernel<<<dim3(N_ / 256, B_), 256>>>(pos, idx);
    sgemm_kernel<1><<<dim3(N_ / 128, C_ / 128, B_), 256>>>(mlpv_w1, x_, mlpv_b1, t_, nullptr, C_, 2 * C_, N_);
    sgemm_kernel<0><<<dim3(N_ / 128, C_ / 128, B_), 256>>>(mlpv_w2, t_, mlpv_b2, val, nullptr, C_, C_, N_);
    sgemm_kernel<2><<<dim3(N_ / 128, C_ / 128, B_), 256>>>(mlpv_ws, x_, mlpv_bs, val, nullptr, C_, 2 * C_, N_);
    sgemm_kernel<0><<<dim3(N_ / 128, DIM_ / 128, B_), 256>>>(wv, val, bv, vf_, nullptr, DIM_, C_, N_);

    // --- u/v on fp16 HMMA (2 blocks/SM) ---
    cudaFuncSetAttribute(uv_hmma, cudaFuncAttributeMaxDynamicSharedMemorySize, UV_SMEM);
    uv_hmma<<<dim3(N_ / 128, 4), 256, UV_SMEM>>>(query, key, wuqimg, wvkimg, u_, vt_);

    // --- pos_rel conv1 + pos BN (fp16 t1) ---
    posrel_kernel<<<(unsigned)(((size_t)B_ * PH_ * M_) / 256), 256>>>(pos, idx, pos_w1, pos_b1, t1_, partp);
    finalize_stats<<<PH_, 256>>>(partp, 512, 1, 512, pos_g1, pos_be1, scp, shp, (float)((size_t)B_ * M_));

    // --- fused mid on fp16 HMMA (h only, 2 blocks/SM) ---
    cudaFuncSetAttribute(fused_mid_hmma, cudaFuncAttributeMaxDynamicSharedMemorySize, FM_SMEM);
    fused_mid_hmma<<<dim3(M_ / 128, B_), 256, FM_SMEM>>>(
        t1_, scp, shp, wmidimg, bias1, u_, vt_, idx, h_, part);
    finalize_stats<<<AH_, 256>>>(part, B_ * 512, AH_, 1, att_g1, att_be1, sca, sha, (float)((size_t)B_ * M_));

    // --- big GEMM2: c-halved fp16 HMMA, 2 blocks/SM ---
    cudaFuncSetAttribute(attn2_hmma_kernel, cudaFuncAttributeMaxDynamicSharedMemorySize, SMEM_ATT2);
    attn2_hmma_kernel<<<dim3(M_ / 128, B_ * 2), 256, SMEM_ATT2>>>(
        (const uint4*)w2img, h_, sca, sha, t1_, scp, shp,
        (const uint4*)wmidimg + 8 * 1024, pos_b2, vf_, agg);

    // --- final projection + residual ---
    sgemm_kernel<4><<<dim3(N_ / 128, C_ / 128, B_), 256>>>(we, agg, be, out, val, C_, DIM_, N_);
}